// round 9
// baseline (speedup 1.0000x reference)
#include <cuda_runtime.h>
#include <cuda_bf16.h>
#include <math.h>
#include <stdint.h>

// ------------ problem constants ------------
#define NFRM   256                  // B*T
#define ECOLS  147456               // NFRM * 576 edge columns
#define NCOLS  6144                 // NFRM * 24 node columns

// ------------ device scratch ------------
__device__ float g_epre  [128 * ECOLS];   // msg_We @ edge + msg_b (loop-invariant)
__device__ float g_gate  [ECOLS];
__device__ float g_node0 [128 * NCOLS];   // transposed node_resnet
__device__ float g_hnode [128 * NCOLS];
__device__ float g_nh    [128 * NCOLS];   // msg_Wh @ h_node
__device__ float g_mv    [128 * NCOLS];
__device__ float g_gi    [384 * NCOLS];
__device__ float g_gh    [384 * NCOLS];
__device__ float g_xg    [512 * NCOLS];   // lstm_Wih @ h_node + bih + bhh
__device__ float g_h     [2 * 128 * 192]; // double-buffered LSTM hidden
__device__ float g_hist  [128 * 6144];    // h history [j][t*192 + b*24 + n]
__device__ unsigned g_cnt2[8];
__device__ unsigned g_sense2[8];
// HMMA A fragments: per m16 block 768 uint4 (24 kk * 32 lanes)
// offsets (uint4): link_W1=0, msg_We=6144, msg_Wh=12288, gru_Wih=18432,
//                  gru_Whh=36864, lstm_Wih=55296  (total 79872)
__device__ uint4 g_wA4[79872];

__device__ __forceinline__ float sigm(float x) { return 1.f / (1.f + expf(-x)); }

__device__ __forceinline__ void ffma2(unsigned long long& acc,
                                      unsigned long long a, unsigned long long b) {
    asm("fma.rn.f32x2 %0, %1, %2, %0;" : "+l"(acc) : "l"(a), "l"(b));
}
__device__ __forceinline__ unsigned long long pack2(float x, float y) {
    unsigned long long r;
    asm("mov.b64 %0, {%1, %2};" : "=l"(r) : "f"(x), "f"(y));
    return r;
}
__device__ __forceinline__ float2 unpack2(unsigned long long v) {
    float2 f;
    asm("mov.b64 {%0, %1}, %2;" : "=f"(f.x), "=f"(f.y) : "l"(v));
    return f;
}
__device__ __forceinline__ void split_bf(float x, __nv_bfloat16& h, __nv_bfloat16& l) {
    h = __float2bfloat16(x);
    l = __float2bfloat16(x - __bfloat162float(h));
}
__device__ __forceinline__ void split_pair(float x0, float x1, unsigned& hw, unsigned& lw) {
    __nv_bfloat16 h0, l0, h1, l1;
    split_bf(x0, h0, l0); split_bf(x1, h1, l1);
    hw = (unsigned)__bfloat16_as_ushort(h0) | ((unsigned)__bfloat16_as_ushort(h1) << 16);
    lw = (unsigned)__bfloat16_as_ushort(l0) | ((unsigned)__bfloat16_as_ushort(l1) << 16);
}
__device__ __forceinline__ uint32_t smem_to_u32(const void* p) {
    uint32_t a;
    asm("{ .reg .u64 t; cvta.to.shared.u64 t, %1; cvt.u32.u64 %0, t; }" : "=r"(a) : "l"(p));
    return a;
}

// ---- HMMA m16n8k16 bf16 ----
__device__ __forceinline__ void mma_bf16(float* c, uint32_t a0, uint32_t a1,
                                         uint32_t a2, uint32_t a3,
                                         uint32_t b0, uint32_t b1) {
    asm volatile(
        "mma.sync.aligned.m16n8k16.row.col.f32.bf16.bf16.f32 "
        "{%0,%1,%2,%3}, {%4,%5,%6,%7}, {%8,%9}, {%0,%1,%2,%3};"
        : "+f"(c[0]), "+f"(c[1]), "+f"(c[2]), "+f"(c[3])
        : "r"(a0), "r"(a1), "r"(a2), "r"(a3), "r"(b0), "r"(b1));
}

// B tile: bf16 [96 rows(n)][264 cols(k: 0-127 hi, 128-255 lo, 8 pad)]
// row pitch 528 B = 132 words; 132 mod 32 = 4 -> ldmatrix conflict-free.
#define BPITCH_W  132       // words per B row
#define BPITCH_B  528
#define SNH_OFF   50688     // float[128*24]
#define SG_OFF    62976     // float[96]
#define SRED_OFF  63360     // float[8][52]
#define SM_EDGE   66688
#define SM_HG     50688

// ------------ prep: pack split-bf16 W (K-stacked [Whi|Whi|Wlo]) into HMMA A-frag layout ------------
__device__ __forceinline__ void prep_one(const float* __restrict__ W, uint4* __restrict__ out,
                                         int gidx)
{
    int mblk = gidx / 768;
    int rem  = gidx - mblk * 768;
    int kk   = rem >> 5;
    int lane = rem & 31;
    int g = lane >> 2, t = lane & 3;
    unsigned regs[4];
#pragma unroll
    for (int r = 0; r < 4; r++) {
        int row = mblk * 16 + g + ((r & 1) ? 8 : 0);
        int k0  = kk * 16 + t * 2 + ((r & 2) ? 8 : 0);
        unsigned pk = 0;
#pragma unroll
        for (int e = 0; e < 2; e++) {
            int ks = k0 + e;
            int region = ks >> 7;
            int kloc = ks & 127;
            float w = W[row * 128 + kloc];
            __nv_bfloat16 h, l; split_bf(w, h, l);
            __nv_bfloat16 b = (region < 2) ? h : l;
            pk |= (unsigned)__bfloat16_as_ushort(b) << (e * 16);
        }
        regs[r] = pk;
    }
    out[gidx] = make_uint4(regs[0], regs[1], regs[2], regs[3]);
}

__global__ void __launch_bounds__(256) prep_a_k(const float* __restrict__ w1,
                                                const float* __restrict__ we,
                                                const float* __restrict__ wh,
                                                uint4* __restrict__ out)
{
    int b = blockIdx.x;
    if (b < 24)      prep_one(w1, out,          b * 256 + threadIdx.x);
    else if (b < 48) prep_one(we, out + 6144,  (b - 24) * 256 + threadIdx.x);
    else             prep_one(wh, out + 12288, (b - 48) * 256 + threadIdx.x);
}
__global__ void __launch_bounds__(256) prep_b_k(const float* __restrict__ wih,
                                                const float* __restrict__ whh,
                                                const float* __restrict__ lih,
                                                uint4* __restrict__ out)
{
    int b = blockIdx.x;
    if (b < 72)       prep_one(wih, out + 18432,  b * 256 + threadIdx.x);
    else if (b < 144) prep_one(whh, out + 36864, (b - 72) * 256 + threadIdx.x);
    else              prep_one(lih, out + 55296, (b - 144) * 256 + threadIdx.x);
}

// ------------ warp GEMM m32 x n48, software-pipelined ------------
// A prefetched one k-step ahead; 3 LDSM batched before the 12 MMAs of each step.
__device__ __forceinline__ void gemm_m32(float c[2][6][4], const uint4* __restrict__ A4,
                                         uint32_t sbAddr, int lane, int nh)
{
    int midx = lane >> 3, row = lane & 7;
    uint32_t base0 = sbAddr +
        (uint32_t)((nh * 48 + ((midx >> 1) << 3) + row) * BPITCH_B + (midx & 1) * 16);
#pragma unroll
    for (int mb = 0; mb < 2; mb++)
#pragma unroll
        for (int nt = 0; nt < 6; nt++)
#pragma unroll
            for (int r = 0; r < 4; r++) c[mb][nt][r] = 0.f;

    uint4 a0 = A4[lane];
    uint4 a1 = A4[768 + lane];
#pragma unroll
    for (int kk = 0; kk < 24; kk++) {
        uint32_t kb = (uint32_t)((kk < 16 ? kk : kk - 16) * 32);
        uint32_t r[12];
#pragma unroll
        for (int j2 = 0; j2 < 3; j2++) {
            asm volatile("ldmatrix.sync.aligned.m8n8.x4.shared.b16 {%0,%1,%2,%3}, [%4];"
                         : "=r"(r[4 * j2]), "=r"(r[4 * j2 + 1]),
                           "=r"(r[4 * j2 + 2]), "=r"(r[4 * j2 + 3])
                         : "r"(base0 + (uint32_t)(j2 * 16 * BPITCH_B) + kb));
        }
        int nk = (kk + 1 < 24) ? kk + 1 : 23;
        uint4 na0 = A4[nk * 32 + lane];
        uint4 na1 = A4[768 + nk * 32 + lane];
#pragma unroll
        for (int j2 = 0; j2 < 3; j2++) {
            mma_bf16(c[0][2 * j2],     a0.x, a0.y, a0.z, a0.w, r[4 * j2],     r[4 * j2 + 1]);
            mma_bf16(c[0][2 * j2 + 1], a0.x, a0.y, a0.z, a0.w, r[4 * j2 + 2], r[4 * j2 + 3]);
            mma_bf16(c[1][2 * j2],     a1.x, a1.y, a1.z, a1.w, r[4 * j2],     r[4 * j2 + 1]);
            mma_bf16(c[1][2 * j2 + 1], a1.x, a1.y, a1.z, a1.w, r[4 * j2 + 2], r[4 * j2 + 3]);
        }
        a0 = na0; a1 = na1;
    }
}

// ------------ gate epilogue (m32 x n48 tiling) ------------
__device__ __forceinline__ void gate_epi32(float c[2][6][4], char* smem,
                                           const float* __restrict__ lb1,
                                           const float* __restrict__ W2,
                                           const float* __restrict__ b2p,
                                           const int* __restrict__ nnum,
                                           int c0, int f, int off)
{
    int tid = threadIdx.x;
    int w = tid >> 5, lane = tid & 31;
    int mp = w & 3;
    int g = lane >> 2, t = lane & 3;
    float* sRed = (float*)(smem + SRED_OFF);   // [8][52]

    float p0[6], p1[6];
#pragma unroll
    for (int j = 0; j < 6; j++) { p0[j] = 0.f; p1[j] = 0.f; }
#pragma unroll
    for (int mb = 0; mb < 2; mb++) {
        int r0 = mp * 32 + mb * 16 + g;
        float bb0 = lb1[r0], bb8 = lb1[r0 + 8];
        float w0 = W2[r0], w8 = W2[r0 + 8];
#pragma unroll
        for (int j = 0; j < 6; j++) {
            p0[j] += fmaxf(c[mb][j][0] + bb0, 0.f) * w0 + fmaxf(c[mb][j][2] + bb8, 0.f) * w8;
            p1[j] += fmaxf(c[mb][j][1] + bb0, 0.f) * w0 + fmaxf(c[mb][j][3] + bb8, 0.f) * w8;
        }
    }
#pragma unroll
    for (int j = 0; j < 6; j++) {
#pragma unroll
        for (int m = 4; m <= 16; m <<= 1) {
            p0[j] += __shfl_xor_sync(0xffffffffu, p0[j], m);
            p1[j] += __shfl_xor_sync(0xffffffffu, p1[j], m);
        }
    }
    if (g == 0) {
#pragma unroll
        for (int j = 0; j < 6; j++) {
            sRed[w * 52 + j * 8 + t * 2]     = p0[j];
            sRed[w * 52 + j * 8 + t * 2 + 1] = p1[j];
        }
    }
    __syncthreads();
    if (tid < 96) {
        int nh2 = tid / 48, nn = tid - nh2 * 48;
        float s = sRed[(nh2 * 4 + 0) * 52 + nn] + sRed[(nh2 * 4 + 1) * 52 + nn]
                + sRed[(nh2 * 4 + 2) * 52 + nn] + sRed[(nh2 * 4 + 3) * 52 + nn];
        int v = (off + tid) / 24, ww = (off + tid) - v * 24;
        int cnt = nnum[f];
        g_gate[c0 + tid] = (v < cnt && ww < cnt) ? sigm(s + b2p[0]) : 0.f;
    }
}

// ------------ edge0_k: layer-0 gate + epre (two GEMM passes share one B tile) ------------
__global__ void __launch_bounds__(256, 3) edge0_k(const float* __restrict__ edge,
                                                  const float* __restrict__ lb1,
                                                  const float* __restrict__ W2,
                                                  const float* __restrict__ b2p,
                                                  const float* __restrict__ msg_b,
                                                  const int* __restrict__ nnum)
{
    extern __shared__ char smem[];
    uint32_t sbAddr = smem_to_u32(smem);
    unsigned* sBw = (unsigned*)smem;
    int tid = threadIdx.x;
    int c0 = blockIdx.x * 96;
    int f = c0 / 576;
    int off = c0 - f * 576;

    // B conversion, d-pair packed: q = n-quarter, dp = d-pair
    {
        int q = tid >> 6, dp = tid & 63;
        const float* s0 = edge + (size_t)f * 73728 + (2 * dp) * 576 + off + q * 24;
        const float* s1 = s0 + 576;
        for (int i = 0; i < 24; i += 4) {
            float4 x0 = *(const float4*)(s0 + i);
            float4 x1 = *(const float4*)(s1 + i);
            float a0[4] = {x0.x, x0.y, x0.z, x0.w};
            float a1[4] = {x1.x, x1.y, x1.z, x1.w};
#pragma unroll
            for (int j = 0; j < 4; j++) {
                int n = q * 24 + i + j;
                unsigned hw, lw; split_pair(a0[j], a1[j], hw, lw);
                sBw[n * BPITCH_W + dp]      = hw;
                sBw[n * BPITCH_W + 64 + dp] = lw;
            }
        }
    }
    __syncthreads();

    int w = tid >> 5, lane = tid & 31;
    int mp = w & 3, nh = w >> 2;
    int g = lane >> 2, t = lane & 3;
    float c[2][6][4];

    // pass 1: link_W1 -> gate0
    gemm_m32(c, g_wA4 + (2 * mp) * 768, sbAddr, lane, nh);
    gate_epi32(c, smem, lb1, W2, b2p, nnum, c0, f, off);
    __syncthreads();

    // pass 2: msg_We -> epre
    gemm_m32(c, g_wA4 + 6144 + (2 * mp) * 768, sbAddr, lane, nh);
#pragma unroll
    for (int mb = 0; mb < 2; mb++) {
        int r0 = mp * 32 + mb * 16 + g;
        float mb0 = msg_b[r0], mb8 = msg_b[r0 + 8];
#pragma unroll
        for (int j = 0; j < 6; j++) {
            int col = c0 + nh * 48 + j * 8 + t * 2;
            *(float2*)(g_epre + (size_t)r0 * ECOLS + col) =
                make_float2(c[mb][j][0] + mb0, c[mb][j][1] + mb0);
            *(float2*)(g_epre + (size_t)(r0 + 8) * ECOLS + col) =
                make_float2(c[mb][j][2] + mb8, c[mb][j][3] + mb8);
        }
    }
}

// ------------ recon_k: layer p>=1 gate + m_v of layer p-1 (byproduct) ------------
__global__ void __launch_bounds__(256, 3) recon_k(const float* __restrict__ lb1,
                                                  const float* __restrict__ W2,
                                                  const float* __restrict__ b2p,
                                                  const int* __restrict__ nnum)
{
    extern __shared__ char smem[];
    uint32_t sbAddr = smem_to_u32(smem);
    unsigned* sBw = (unsigned*)smem;
    float* snh = (float*)(smem + SNH_OFF);   // [128][24]
    float* sg  = (float*)(smem + SG_OFF);    // [96]
    int tid = threadIdx.x;
    int c0 = blockIdx.x * 96;
    int f = c0 / 576;
    int off = c0 - f * 576;

    for (int i = tid; i < 3072; i += 256) {
        int d = i / 24, w = i - d * 24;
        snh[d * 24 + w] = g_nh[d * NCOLS + f * 24 + w];
    }
    if (tid < 96) sg[tid] = g_gate[c0 + tid];
    __syncthreads();

    // B conversion from reconstruction h_edge = gate * relu(nh + epre); m_v byproduct
    {
        int q = tid >> 6, dp = tid & 63;
        int d0 = 2 * dp, d1 = d0 + 1;
        const float* s0 = g_epre + (size_t)d0 * ECOLS + c0 + q * 24;
        const float* s1 = s0 + ECOLS;
        float sum0 = 0.f, sum1 = 0.f;
        for (int i = 0; i < 24; i += 4) {
            float4 x0 = *(const float4*)(s0 + i);
            float4 x1 = *(const float4*)(s1 + i);
            float a0[4] = {x0.x, x0.y, x0.z, x0.w};
            float a1[4] = {x1.x, x1.y, x1.z, x1.w};
#pragma unroll
            for (int j = 0; j < 4; j++) {
                int w = i + j;
                int n = q * 24 + w;
                float gv = sg[n];
                float v0 = gv * fmaxf(snh[d0 * 24 + w] + a0[j], 0.f);
                float v1 = gv * fmaxf(snh[d1 * 24 + w] + a1[j], 0.f);
                sum0 += v0; sum1 += v1;
                unsigned hw, lw; split_pair(v0, v1, hw, lw);
                sBw[n * BPITCH_W + dp]      = hw;
                sBw[n * BPITCH_W + 64 + dp] = lw;
            }
        }
        int v = off / 24 + q;
        g_mv[d0 * NCOLS + f * 24 + v] = sum0;
        g_mv[d1 * NCOLS + f * 24 + v] = sum1;
    }
    __syncthreads();

    int w = tid >> 5, lane = tid & 31;
    int mp = w & 3, nh = w >> 2;
    float c[2][6][4];
    gemm_m32(c, g_wA4 + (2 * mp) * 768, sbAddr, lane, nh);
    gate_epi32(c, smem, lb1, W2, b2p, nnum, c0, f, off);
}

// ------------ shared hgemm body (m32 x n48 tiling) ------------
__device__ __forceinline__ void hgemm_body(const uint4* __restrict__ Afrag, int mrowblk,
                                           const float* __restrict__ X,
                                           const float* __restrict__ bias,
                                           const float* __restrict__ bias2,
                                           float* __restrict__ Y, int cols, int c0,
                                           char* smem, uint32_t sbAddr)
{
    unsigned* sBw = (unsigned*)smem;
    int tid = threadIdx.x;
    {
        int q = tid >> 6, dp = tid & 63;
        const float* s0 = X + (size_t)(2 * dp) * cols + c0 + q * 24;
        const float* s1 = s0 + cols;
        for (int i = 0; i < 24; i += 4) {
            float4 x0 = *(const float4*)(s0 + i);
            float4 x1 = *(const float4*)(s1 + i);
            float a0[4] = {x0.x, x0.y, x0.z, x0.w};
            float a1[4] = {x1.x, x1.y, x1.z, x1.w};
#pragma unroll
            for (int j = 0; j < 4; j++) {
                int n = q * 24 + i + j;
                unsigned hw, lw; split_pair(a0[j], a1[j], hw, lw);
                sBw[n * BPITCH_W + dp]      = hw;
                sBw[n * BPITCH_W + 64 + dp] = lw;
            }
        }
    }
    __syncthreads();

    int w = tid >> 5, lane = tid & 31;
    int mp = w & 3, nh = w >> 2;
    int g = lane >> 2, t = lane & 3;
    float c[2][6][4];
    gemm_m32(c, Afrag + (mrowblk * 8 + 2 * mp) * 768, sbAddr, lane, nh);

#pragma unroll
    for (int mb = 0; mb < 2; mb++) {
        int r0 = mrowblk * 128 + mp * 32 + mb * 16 + g;
        float b0v = (bias ? bias[r0] : 0.f) + (bias2 ? bias2[r0] : 0.f);
        float b8v = (bias ? bias[r0 + 8] : 0.f) + (bias2 ? bias2[r0 + 8] : 0.f);
#pragma unroll
        for (int j = 0; j < 6; j++) {
            int col = c0 + nh * 48 + j * 8 + t * 2;
            *(float2*)(Y + (size_t)r0 * cols + col) =
                make_float2(c[mb][j][0] + b0v, c[mb][j][1] + b0v);
            *(float2*)(Y + (size_t)(r0 + 8) * cols + col) =
                make_float2(c[mb][j][2] + b8v, c[mb][j][3] + b8v);
        }
    }
}

__global__ void __launch_bounds__(256, 3) hgemm_k(const uint4* __restrict__ Afrag,
                                                  const float* __restrict__ X,
                                                  const float* __restrict__ bias,
                                                  const float* __restrict__ bias2,
                                                  float* __restrict__ Y, int cols)
{
    extern __shared__ char smem[];
    hgemm_body(Afrag, blockIdx.y, X, bias, bias2, Y, cols, blockIdx.x * 96,
               smem, smem_to_u32(smem));
}

// gi and gh in one launch: y<3 -> gi, y>=3 -> gh
__global__ void __launch_bounds__(256, 3) gigh_k(const uint4* __restrict__ wA)
{
    extern __shared__ char smem[];
    int by = blockIdx.y;
    if (by < 3)
        hgemm_body(wA + 18432, by, g_mv, nullptr, nullptr, g_gi, NCOLS,
                   blockIdx.x * 96, smem, smem_to_u32(smem));
    else
        hgemm_body(wA + 36864, by - 3, g_hnode, nullptr, nullptr, g_gh, NCOLS,
                   blockIdx.x * 96, smem, smem_to_u32(smem));
}

// ------------ node transpose ------------
__global__ void __launch_bounds__(256) tr_node_k(const float* __restrict__ in)
{
    int o4 = blockIdx.x * 256 + threadIdx.x;         // < 128*NCOLS/4
    int d = o4 / 1536; int c4 = o4 - d * 1536;
    int f = c4 / 6;    int n4 = c4 - f * 6;
    float4 v = *(const float4*)(in + f * 3072 + d * 24 + n4 * 4);
    int dst = d * NCOLS + f * 24 + n4 * 4;
    *(float4*)(g_node0 + dst) = v;
    *(float4*)(g_hnode + dst) = v;
}

// ------------ last-layer message aggregation ------------
__global__ void __launch_bounds__(256) msg3_k()
{
    __shared__ float snh[32][24];
    __shared__ float sg[576];
    int f = blockIdx.x >> 2, dg = blockIdx.x & 3;
    int tid = threadIdx.x;
    for (int i = tid; i < 768; i += 256) {
        int d = i / 24, w = i - d * 24;
        snh[d][w] = g_nh[(dg * 32 + d) * NCOLS + f * 24 + w];
    }
    for (int i = tid; i < 576; i += 256) sg[i] = g_gate[f * 576 + i];
    __syncthreads();

    int wl = tid & 31, wp = tid >> 5;
    bool ok = wl < 24;
    for (int p = wp; p < 768; p += 8) {
        int dl = p / 24, v = p - dl * 24;
        int d = dg * 32 + dl;
        float s = 0.f;
        if (ok) s = sg[v * 24 + wl] * fmaxf(snh[dl][wl] + g_epre[(size_t)d * ECOLS + f * 576 + v * 24 + wl], 0.f);
#pragma unroll
        for (int o = 16; o; o >>= 1) s += __shfl_xor_sync(0xffffffffu, s, o);
        if (wl == 0) g_mv[d * NCOLS + f * 24 + v] = s;
    }
}

// ------------ GRU elementwise ------------
__global__ void __launch_bounds__(256) gru_k(const int* __restrict__ nnum,
                                             const float* __restrict__ bih,
                                             const float* __restrict__ bhh)
{
    int idx = blockIdx.x * 256 + threadIdx.x;        // < 128*NCOLS
    int j = idx / NCOLS; int col = idx - j * NCOLS;
    float gir = g_gi[j * NCOLS + col]         + bih[j];
    float giz = g_gi[(128 + j) * NCOLS + col] + bih[128 + j];
    float gin = g_gi[(256 + j) * NCOLS + col] + bih[256 + j];
    float ghr = g_gh[j * NCOLS + col]         + bhh[j];
    float ghz = g_gh[(128 + j) * NCOLS + col] + bhh[128 + j];
    float ghn = g_gh[(256 + j) * NCOLS + col] + bhh[256 + j];
    float r = sigm(gir + ghr);
    float z = sigm(giz + ghz);
    float n2 = tanhf(gin + r * ghn);
    float h = g_hnode[idx];
    float hn = (1.f - z) * n2 + z * h;
    int f = col / 24; int n = col - f * 24;
    g_hnode[idx] = (n < nnum[f]) ? hn : g_node0[idx];
}

// ------------ persistent LSTM ------------
__device__ __forceinline__ void group_barrier(int b, unsigned want)
{
    __threadfence();
    __syncthreads();
    if (threadIdx.x == 0) {
        unsigned tk = atomicAdd(&g_cnt2[b], 1u);
        if (tk == 15u) {
            g_cnt2[b] = 0;
            __threadfence();
            atomicExch(&g_sense2[b], want);
        } else {
            unsigned v;
            do {
                asm volatile("ld.acquire.gpu.u32 %0, [%1];" : "=r"(v) : "l"(&g_sense2[b]));
            } while (v != want);
        }
    }
    __syncthreads();
}

__global__ void __launch_bounds__(192) lstm_all_k(const float* __restrict__ Whh)
{
    __shared__ __align__(16) float sWt[128][36];
    __shared__ float sH[128][25];
    __shared__ float sG[32][25];
    int tid = threadIdx.x;
    int rg = blockIdx.x & 15, b = blockIdx.x >> 4;

    for (int i = tid; i < 4096; i += 192) {
        int r = i >> 7, k = i & 127;
        int jg = (r >> 3) * 128 + rg * 8 + (r & 7);
        sWt[k][r] = Whh[jg * 128 + k];
    }
    int tr = tid & 7, tc = tid >> 3;
    int hh = tid / 24, nn = tid - hh * 24;
    int jrow = rg * 8 + hh;
    int scol = b * 24 + nn;
    float creg = 0.f;
    unsigned phase = 0;

    for (int t = 0; t < 32; t++) {
        if (t == 0) {
            for (int i = tid; i < 3200; i += 192) (&sH[0][0])[i] = 0.f;
            __syncthreads();
        } else {
            phase++;
            group_barrier(b, phase & 1u);
            const float* hb = g_h + ((t + 1) & 1) * 24576;
            for (int i = tid; i < 3072; i += 192) {
                int j = i / 24, n2 = i - j * 24;
                sH[j][n2] = __ldcg(hb + j * 192 + b * 24 + n2);
            }
            __syncthreads();
        }

        unsigned long long acc0 = 0ull, acc1 = 0ull;
#pragma unroll 8
        for (int k = 0; k < 128; k++) {
            ulonglong2 av = *(const ulonglong2*)&sWt[k][tr * 4];
            float bv = sH[k][tc];
            unsigned long long bs = pack2(bv, bv);
            ffma2(acc0, av.x, bs);
            ffma2(acc1, av.y, bs);
        }
        float2 u0 = unpack2(acc0), u1 = unpack2(acc1);
        sG[tr * 4 + 0][tc] = u0.x; sG[tr * 4 + 1][tc] = u0.y;
        sG[tr * 4 + 2][tc] = u1.x; sG[tr * 4 + 3][tc] = u1.y;
        __syncthreads();

        int colx = (b * 32 + t) * 24 + nn;
        float ig = sG[hh][nn]      + g_xg[(      jrow) * NCOLS + colx];
        float fg = sG[8 + hh][nn]  + g_xg[(128 + jrow) * NCOLS + colx];
        float gg = sG[16 + hh][nn] + g_xg[(256 + jrow) * NCOLS + colx];
        float og = sG[24 + hh][nn] + g_xg[(384 + jrow) * NCOLS + colx];
        creg = sigm(fg) * creg + sigm(ig) * tanhf(gg);
        float hnew = sigm(og) * tanhf(creg);
        __stcg(g_h + (t & 1) * 24576 + jrow * 192 + scol, hnew);
        g_hist[jrow * 6144 + t * 192 + scol] = hnew;
        __syncthreads();
    }
    phase++;
    group_barrier(b, phase & 1u);
}

// ------------ readout ------------
__global__ void __launch_bounds__(256) readout_k(const float* __restrict__ roW,
                                                 const float* __restrict__ rob,
                                                 const int* __restrict__ nnum,
                                                 float* __restrict__ out)
{
    __shared__ float sH[128][65];
    __shared__ float sRo[6][128];
    __shared__ float sRob[6];
    int tid = threadIdx.x;
    int c0 = blockIdx.x * 64;
    for (int i = tid; i < 8192; i += 256) {
        int j = i >> 6, cc = i & 63;
        sH[j][cc] = g_hist[j * 6144 + c0 + cc];
    }
    for (int i = tid; i < 768; i += 256) sRo[i >> 7][i & 127] = roW[i];
    if (tid < 6) sRob[tid] = rob[tid];
    __syncthreads();
    for (int e = tid; e < 384; e += 256) {
        int cc = e / 6, c = e - cc * 6;
        float s = 0.f;
#pragma unroll 8
        for (int j = 0; j < 128; j++) s += sRo[c][j] * sH[j][cc];
        int ct = c0 + cc;
        int t = ct / 192; int srem = ct - t * 192;
        int b = srem / 24; int n = srem - b * 24;
        int f = b * 32 + t;
        out[(f * 24 + n) * 6 + c] = (n < nnum[f]) ? (s + sRob[c]) : 0.f;
    }
}

// ------------ host launcher ------------
extern "C" void kernel_launch(void* const* d_in, const int* in_sizes, int n_in,
                              void* d_out, int out_size)
{
    const float* node     = (const float*)d_in[0];
    const float* edge     = (const float*)d_in[1];
    const float* link_W1  = (const float*)d_in[2];
    const float* link_b1  = (const float*)d_in[3];
    const float* link_W2  = (const float*)d_in[4];
    const float* link_b2  = (const float*)d_in[5];
    const float* msg_Wh   = (const float*)d_in[6];
    const float* msg_We   = (const float*)d_in[7];
    const float* msg_b    = (const float*)d_in[8];
    const float* gru_Wih  = (const float*)d_in[9];
    const float* gru_Whh  = (const float*)d_in[10];
    const float* gru_bih  = (const float*)d_in[11];
    const float* gru_bhh  = (const float*)d_in[12];
    const float* lstm_Wih = (const float*)d_in[13];
    const float* lstm_Whh = (const float*)d_in[14];
    const float* lstm_bih = (const float*)d_in[15];
    const float* lstm_bhh = (const float*)d_in[16];
    const float* ro_W     = (const float*)d_in[17];
    const float* ro_b     = (const float*)d_in[18];
    const int*   nnum     = (const int*)d_in[19];
    float* out = (float*)d_out;

    float* hnode; cudaGetSymbolAddress((void**)&hnode, g_hnode);
    float* nh;    cudaGetSymbolAddress((void**)&nh,    g_nh);
    float* xg;    cudaGetSymbolAddress((void**)&xg,    g_xg);
    uint4* wA;    cudaGetSymbolAddress((void**)&wA,    g_wA4);

    static int smem_set = 0;
    if (!smem_set) {
        cudaFuncSetAttribute(edge0_k, cudaFuncAttributeMaxDynamicSharedMemorySize, SM_EDGE);
        cudaFuncSetAttribute(recon_k, cudaFuncAttributeMaxDynamicSharedMemorySize, SM_EDGE);
        cudaFuncSetAttribute(hgemm_k, cudaFuncAttributeMaxDynamicSharedMemorySize, SM_HG);
        cudaFuncSetAttribute(gigh_k,  cudaFuncAttributeMaxDynamicSharedMemorySize, SM_HG);
        smem_set = 1;
    }

    const int NTILE = ECOLS / 96;   // 1536
    const int NCT   = NCOLS / 96;   // 64

    // launch order puts recon_k at position 6 (ncu captures launch #6)
    tr_node_k<<<(128 * NCOLS / 4) / 256, 256>>>(node);                       // 1
    prep_a_k<<<72, 256>>>(link_W1, msg_We, msg_Wh, wA);                      // 2
    prep_b_k<<<240, 256>>>(gru_Wih, gru_Whh, lstm_Wih, wA);                  // 3
    edge0_k<<<NTILE, 256, SM_EDGE>>>(edge, link_b1, link_W2, link_b2, msg_b, nnum);  // 4

    for (int p = 0; p < 3; p++) {
        hgemm_k<<<dim3(NCT, 1), 256, SM_HG>>>(wA + 12288, hnode, nullptr, nullptr, nh, NCOLS); // 5
        if (p < 2) {
            recon_k<<<NTILE, 256, SM_EDGE>>>(link_b1, link_W2, link_b2, nnum);                 // 6
        } else {
            msg3_k<<<1024, 256>>>();
        }
        gigh_k<<<dim3(NCT, 6), 256, SM_HG>>>(wA);
        gru_k<<<(128 * NCOLS) / 256, 256>>>(nnum, gru_bih, gru_bhh);
    }

    hgemm_k<<<dim3(NCT, 4), 256, SM_HG>>>(wA + 55296, hnode, lstm_bih, lstm_bhh, xg, NCOLS);
    lstm_all_k<<<128, 192>>>(lstm_Whh);
    readout_k<<<96, 256>>>(ro_W, ro_b, nnum, out);
    (void)in_sizes; (void)n_in; (void)out_size;
}

// round 10
// speedup vs baseline: 1.5480x; 1.5480x over previous
#include <cuda_runtime.h>
#include <cuda_bf16.h>
#include <math.h>
#include <stdint.h>

// ------------ problem constants ------------
#define NFRM   256                  // B*T
#define ECOLS  147456               // NFRM * 576 edge columns
#define NCOLS  6144                 // NFRM * 24 node columns

// ------------ device scratch ------------
__device__ float g_epre  [128 * ECOLS];   // msg_We @ edge + msg_b (loop-invariant)
__device__ float g_gate  [ECOLS];
__device__ float g_node0 [128 * NCOLS];   // transposed node_resnet
__device__ float g_hnode [128 * NCOLS];
__device__ float g_nh    [128 * NCOLS];   // msg_Wh @ h_node
__device__ float g_mv    [128 * NCOLS];
__device__ float g_gi    [384 * NCOLS];
__device__ float g_gh    [384 * NCOLS];
__device__ float g_xg    [512 * NCOLS];   // lstm_Wih @ h_node + bih + bhh
__device__ float g_h     [2 * 128 * 192]; // double-buffered LSTM hidden
__device__ float g_hist  [128 * 6144];    // h history [j][t*192 + b*24 + n]
__device__ unsigned g_cnt2[8];
__device__ unsigned g_sense2[8];
// HMMA A fragments: per m16 block 768 uint4 (24 kk * 32 lanes)
// offsets (uint4): link_W1=0, msg_We=6144, msg_Wh=12288, gru_Wih=18432,
//                  gru_Whh=36864, lstm_Wih=55296  (total 79872)
__device__ uint4 g_wA4[79872];

__device__ __forceinline__ float sigm(float x) { return 1.f / (1.f + expf(-x)); }

__device__ __forceinline__ void ffma2(unsigned long long& acc,
                                      unsigned long long a, unsigned long long b) {
    asm("fma.rn.f32x2 %0, %1, %2, %0;" : "+l"(acc) : "l"(a), "l"(b));
}
__device__ __forceinline__ unsigned long long pack2(float x, float y) {
    unsigned long long r;
    asm("mov.b64 %0, {%1, %2};" : "=l"(r) : "f"(x), "f"(y));
    return r;
}
__device__ __forceinline__ float2 unpack2(unsigned long long v) {
    float2 f;
    asm("mov.b64 {%0, %1}, %2;" : "=f"(f.x), "=f"(f.y) : "l"(v));
    return f;
}
__device__ __forceinline__ void split_bf(float x, __nv_bfloat16& h, __nv_bfloat16& l) {
    h = __float2bfloat16(x);
    l = __float2bfloat16(x - __bfloat162float(h));
}
__device__ __forceinline__ void split_pair(float x0, float x1, unsigned& hw, unsigned& lw) {
    __nv_bfloat16 h0, l0, h1, l1;
    split_bf(x0, h0, l0); split_bf(x1, h1, l1);
    hw = (unsigned)__bfloat16_as_ushort(h0) | ((unsigned)__bfloat16_as_ushort(h1) << 16);
    lw = (unsigned)__bfloat16_as_ushort(l0) | ((unsigned)__bfloat16_as_ushort(l1) << 16);
}
__device__ __forceinline__ uint32_t smem_to_u32(const void* p) {
    uint32_t a;
    asm("{ .reg .u64 t; cvta.to.shared.u64 t, %1; cvt.u32.u64 %0, t; }" : "=r"(a) : "l"(p));
    return a;
}

// ---- HMMA m16n8k16 bf16 ----
__device__ __forceinline__ void mma_bf16(float* c, uint32_t a0, uint32_t a1,
                                         uint32_t a2, uint32_t a3,
                                         uint32_t b0, uint32_t b1) {
    asm volatile(
        "mma.sync.aligned.m16n8k16.row.col.f32.bf16.bf16.f32 "
        "{%0,%1,%2,%3}, {%4,%5,%6,%7}, {%8,%9}, {%0,%1,%2,%3};"
        : "+f"(c[0]), "+f"(c[1]), "+f"(c[2]), "+f"(c[3])
        : "r"(a0), "r"(a1), "r"(a2), "r"(a3), "r"(b0), "r"(b1));
}

// B tile: bf16 [96 rows(n)][264 cols(k: 0-127 hi, 128-255 lo, 8 pad)]
// row pitch 528 B = 132 words; 132 mod 32 = 4 -> ldmatrix conflict-free.
#define BPITCH_W  132       // words per B row
#define BPITCH_B  528
#define SNH_OFF   50688     // float[128*24]
#define SG_OFF    62976     // float[96]
#define SRED_OFF  63360     // float[8][52]
#define SM_EDGE   66688
#define SM_HG     50688

// ------------ prep: pack split-bf16 W (K-stacked [Whi|Whi|Wlo]) into HMMA A-frag layout ------------
__device__ __forceinline__ void prep_one(const float* __restrict__ W, uint4* __restrict__ out,
                                         int gidx)
{
    int mblk = gidx / 768;
    int rem  = gidx - mblk * 768;
    int kk   = rem >> 5;
    int lane = rem & 31;
    int g = lane >> 2, t = lane & 3;
    unsigned regs[4];
#pragma unroll
    for (int r = 0; r < 4; r++) {
        int row = mblk * 16 + g + ((r & 1) ? 8 : 0);
        int k0  = kk * 16 + t * 2 + ((r & 2) ? 8 : 0);
        unsigned pk = 0;
#pragma unroll
        for (int e = 0; e < 2; e++) {
            int ks = k0 + e;
            int region = ks >> 7;
            int kloc = ks & 127;
            float w = W[row * 128 + kloc];
            __nv_bfloat16 h, l; split_bf(w, h, l);
            __nv_bfloat16 b = (region < 2) ? h : l;
            pk |= (unsigned)__bfloat16_as_ushort(b) << (e * 16);
        }
        regs[r] = pk;
    }
    out[gidx] = make_uint4(regs[0], regs[1], regs[2], regs[3]);
}

__global__ void __launch_bounds__(256) prep_a_k(const float* __restrict__ w1,
                                                const float* __restrict__ we,
                                                const float* __restrict__ wh,
                                                uint4* __restrict__ out)
{
    int b = blockIdx.x;
    if (b < 24)      prep_one(w1, out,          b * 256 + threadIdx.x);
    else if (b < 48) prep_one(we, out + 6144,  (b - 24) * 256 + threadIdx.x);
    else             prep_one(wh, out + 12288, (b - 48) * 256 + threadIdx.x);
}
__global__ void __launch_bounds__(256) prep_b_k(const float* __restrict__ wih,
                                                const float* __restrict__ whh,
                                                const float* __restrict__ lih,
                                                uint4* __restrict__ out)
{
    int b = blockIdx.x;
    if (b < 72)       prep_one(wih, out + 18432,  b * 256 + threadIdx.x);
    else if (b < 144) prep_one(whh, out + 36864, (b - 72) * 256 + threadIdx.x);
    else              prep_one(lih, out + 55296, (b - 144) * 256 + threadIdx.x);
}

// ------------ warp GEMM m32 x n48, A-hi dedup (two-phase) ------------
// Phase 1: A-hi (kk 0-7) x B-hi then B-lo -> one A load pair per 24 MMAs.
// Phase 2: A-lo (kk 16-23) x B-hi.  Bit-identical to the 24-step version.
__device__ __forceinline__ void gemm_m32(float c[2][6][4], const uint4* __restrict__ A4,
                                         uint32_t sbAddr, int lane, int nh)
{
    int midx = lane >> 3, row = lane & 7;
    uint32_t base0 = sbAddr +
        (uint32_t)((nh * 48 + ((midx >> 1) << 3) + row) * BPITCH_B + (midx & 1) * 16);
#pragma unroll
    for (int mb = 0; mb < 2; mb++)
#pragma unroll
        for (int nt = 0; nt < 6; nt++)
#pragma unroll
            for (int r = 0; r < 4; r++) c[mb][nt][r] = 0.f;

    // phase 1: A-hi shared by B-hi and B-lo k-chunks
#pragma unroll 2
    for (int kk2 = 0; kk2 < 8; kk2++) {
        uint4 a0 = A4[kk2 * 32 + lane];
        uint4 a1 = A4[768 + kk2 * 32 + lane];
        uint32_t r[12];
        // B-hi chunk (bytes kk2*32)
#pragma unroll
        for (int j2 = 0; j2 < 3; j2++) {
            asm volatile("ldmatrix.sync.aligned.m8n8.x4.shared.b16 {%0,%1,%2,%3}, [%4];"
                         : "=r"(r[4 * j2]), "=r"(r[4 * j2 + 1]),
                           "=r"(r[4 * j2 + 2]), "=r"(r[4 * j2 + 3])
                         : "r"(base0 + (uint32_t)(j2 * 16 * BPITCH_B + kk2 * 32)));
        }
#pragma unroll
        for (int j2 = 0; j2 < 3; j2++) {
            mma_bf16(c[0][2 * j2],     a0.x, a0.y, a0.z, a0.w, r[4 * j2],     r[4 * j2 + 1]);
            mma_bf16(c[0][2 * j2 + 1], a0.x, a0.y, a0.z, a0.w, r[4 * j2 + 2], r[4 * j2 + 3]);
            mma_bf16(c[1][2 * j2],     a1.x, a1.y, a1.z, a1.w, r[4 * j2],     r[4 * j2 + 1]);
            mma_bf16(c[1][2 * j2 + 1], a1.x, a1.y, a1.z, a1.w, r[4 * j2 + 2], r[4 * j2 + 3]);
        }
        // B-lo chunk (bytes (kk2+8)*32) with the SAME A-hi fragments
#pragma unroll
        for (int j2 = 0; j2 < 3; j2++) {
            asm volatile("ldmatrix.sync.aligned.m8n8.x4.shared.b16 {%0,%1,%2,%3}, [%4];"
                         : "=r"(r[4 * j2]), "=r"(r[4 * j2 + 1]),
                           "=r"(r[4 * j2 + 2]), "=r"(r[4 * j2 + 3])
                         : "r"(base0 + (uint32_t)(j2 * 16 * BPITCH_B + (kk2 + 8) * 32)));
        }
#pragma unroll
        for (int j2 = 0; j2 < 3; j2++) {
            mma_bf16(c[0][2 * j2],     a0.x, a0.y, a0.z, a0.w, r[4 * j2],     r[4 * j2 + 1]);
            mma_bf16(c[0][2 * j2 + 1], a0.x, a0.y, a0.z, a0.w, r[4 * j2 + 2], r[4 * j2 + 3]);
            mma_bf16(c[1][2 * j2],     a1.x, a1.y, a1.z, a1.w, r[4 * j2],     r[4 * j2 + 1]);
            mma_bf16(c[1][2 * j2 + 1], a1.x, a1.y, a1.z, a1.w, r[4 * j2 + 2], r[4 * j2 + 3]);
        }
    }
    // phase 2: A-lo x B-hi
#pragma unroll 2
    for (int kk2 = 0; kk2 < 8; kk2++) {
        uint4 a0 = A4[(16 + kk2) * 32 + lane];
        uint4 a1 = A4[768 + (16 + kk2) * 32 + lane];
        uint32_t r[12];
#pragma unroll
        for (int j2 = 0; j2 < 3; j2++) {
            asm volatile("ldmatrix.sync.aligned.m8n8.x4.shared.b16 {%0,%1,%2,%3}, [%4];"
                         : "=r"(r[4 * j2]), "=r"(r[4 * j2 + 1]),
                           "=r"(r[4 * j2 + 2]), "=r"(r[4 * j2 + 3])
                         : "r"(base0 + (uint32_t)(j2 * 16 * BPITCH_B + kk2 * 32)));
        }
#pragma unroll
        for (int j2 = 0; j2 < 3; j2++) {
            mma_bf16(c[0][2 * j2],     a0.x, a0.y, a0.z, a0.w, r[4 * j2],     r[4 * j2 + 1]);
            mma_bf16(c[0][2 * j2 + 1], a0.x, a0.y, a0.z, a0.w, r[4 * j2 + 2], r[4 * j2 + 3]);
            mma_bf16(c[1][2 * j2],     a1.x, a1.y, a1.z, a1.w, r[4 * j2],     r[4 * j2 + 1]);
            mma_bf16(c[1][2 * j2 + 1], a1.x, a1.y, a1.z, a1.w, r[4 * j2 + 2], r[4 * j2 + 3]);
        }
    }
}

// ------------ gate epilogue (m32 x n48 tiling) ------------
__device__ __forceinline__ void gate_epi32(float c[2][6][4], char* smem,
                                           const float* __restrict__ lb1,
                                           const float* __restrict__ W2,
                                           const float* __restrict__ b2p,
                                           const int* __restrict__ nnum,
                                           int c0, int f, int off)
{
    int tid = threadIdx.x;
    int w = tid >> 5, lane = tid & 31;
    int mp = w & 3;
    int g = lane >> 2, t = lane & 3;
    float* sRed = (float*)(smem + SRED_OFF);   // [8][52]

    float p0[6], p1[6];
#pragma unroll
    for (int j = 0; j < 6; j++) { p0[j] = 0.f; p1[j] = 0.f; }
#pragma unroll
    for (int mb = 0; mb < 2; mb++) {
        int r0 = mp * 32 + mb * 16 + g;
        float bb0 = lb1[r0], bb8 = lb1[r0 + 8];
        float w0 = W2[r0], w8 = W2[r0 + 8];
#pragma unroll
        for (int j = 0; j < 6; j++) {
            p0[j] += fmaxf(c[mb][j][0] + bb0, 0.f) * w0 + fmaxf(c[mb][j][2] + bb8, 0.f) * w8;
            p1[j] += fmaxf(c[mb][j][1] + bb0, 0.f) * w0 + fmaxf(c[mb][j][3] + bb8, 0.f) * w8;
        }
    }
#pragma unroll
    for (int j = 0; j < 6; j++) {
#pragma unroll
        for (int m = 4; m <= 16; m <<= 1) {
            p0[j] += __shfl_xor_sync(0xffffffffu, p0[j], m);
            p1[j] += __shfl_xor_sync(0xffffffffu, p1[j], m);
        }
    }
    if (g == 0) {
#pragma unroll
        for (int j = 0; j < 6; j++) {
            sRed[w * 52 + j * 8 + t * 2]     = p0[j];
            sRed[w * 52 + j * 8 + t * 2 + 1] = p1[j];
        }
    }
    __syncthreads();
    if (tid < 96) {
        int nh2 = tid / 48, nn = tid - nh2 * 48;
        float s = sRed[(nh2 * 4 + 0) * 52 + nn] + sRed[(nh2 * 4 + 1) * 52 + nn]
                + sRed[(nh2 * 4 + 2) * 52 + nn] + sRed[(nh2 * 4 + 3) * 52 + nn];
        int v = (off + tid) / 24, ww = (off + tid) - v * 24;
        int cnt = nnum[f];
        g_gate[c0 + tid] = (v < cnt && ww < cnt) ? sigm(s + b2p[0]) : 0.f;
    }
}

// ------------ edge0_k: layer-0 gate + epre (two GEMM passes share one B tile) ------------
__global__ void __launch_bounds__(256, 3) edge0_k(const float* __restrict__ edge,
                                                  const float* __restrict__ lb1,
                                                  const float* __restrict__ W2,
                                                  const float* __restrict__ b2p,
                                                  const float* __restrict__ msg_b,
                                                  const int* __restrict__ nnum)
{
    extern __shared__ char smem[];
    uint32_t sbAddr = smem_to_u32(smem);
    unsigned* sBw = (unsigned*)smem;
    int tid = threadIdx.x;
    int c0 = blockIdx.x * 96;
    int f = c0 / 576;
    int off = c0 - f * 576;

    // B conversion, d-pair packed: q = n-quarter, dp = d-pair
    {
        int q = tid >> 6, dp = tid & 63;
        const float* s0 = edge + (size_t)f * 73728 + (2 * dp) * 576 + off + q * 24;
        const float* s1 = s0 + 576;
        for (int i = 0; i < 24; i += 4) {
            float4 x0 = *(const float4*)(s0 + i);
            float4 x1 = *(const float4*)(s1 + i);
            float a0[4] = {x0.x, x0.y, x0.z, x0.w};
            float a1[4] = {x1.x, x1.y, x1.z, x1.w};
#pragma unroll
            for (int j = 0; j < 4; j++) {
                int n = q * 24 + i + j;
                unsigned hw, lw; split_pair(a0[j], a1[j], hw, lw);
                sBw[n * BPITCH_W + dp]      = hw;
                sBw[n * BPITCH_W + 64 + dp] = lw;
            }
        }
    }
    __syncthreads();

    int w = tid >> 5, lane = tid & 31;
    int mp = w & 3, nh = w >> 2;
    int g = lane >> 2, t = lane & 3;
    float c[2][6][4];

    // pass 1: link_W1 -> gate0
    gemm_m32(c, g_wA4 + (2 * mp) * 768, sbAddr, lane, nh);
    gate_epi32(c, smem, lb1, W2, b2p, nnum, c0, f, off);
    __syncthreads();

    // pass 2: msg_We -> epre
    gemm_m32(c, g_wA4 + 6144 + (2 * mp) * 768, sbAddr, lane, nh);
#pragma unroll
    for (int mb = 0; mb < 2; mb++) {
        int r0 = mp * 32 + mb * 16 + g;
        float mb0 = msg_b[r0], mb8 = msg_b[r0 + 8];
#pragma unroll
        for (int j = 0; j < 6; j++) {
            int col = c0 + nh * 48 + j * 8 + t * 2;
            *(float2*)(g_epre + (size_t)r0 * ECOLS + col) =
                make_float2(c[mb][j][0] + mb0, c[mb][j][1] + mb0);
            *(float2*)(g_epre + (size_t)(r0 + 8) * ECOLS + col) =
                make_float2(c[mb][j][2] + mb8, c[mb][j][3] + mb8);
        }
    }
}

// ------------ recon_k: layer p>=1 gate + m_v of layer p-1 (byproduct) ------------
__global__ void __launch_bounds__(256, 3) recon_k(const float* __restrict__ lb1,
                                                  const float* __restrict__ W2,
                                                  const float* __restrict__ b2p,
                                                  const int* __restrict__ nnum)
{
    extern __shared__ char smem[];
    uint32_t sbAddr = smem_to_u32(smem);
    unsigned* sBw = (unsigned*)smem;
    float* snh = (float*)(smem + SNH_OFF);   // [128][24]
    float* sg  = (float*)(smem + SG_OFF);    // [96]
    int tid = threadIdx.x;
    int c0 = blockIdx.x * 96;
    int f = c0 / 576;
    int off = c0 - f * 576;

    for (int i = tid; i < 3072; i += 256) {
        int d = i / 24, w = i - d * 24;
        snh[d * 24 + w] = g_nh[d * NCOLS + f * 24 + w];
    }
    if (tid < 96) sg[tid] = g_gate[c0 + tid];
    __syncthreads();

    // B conversion from reconstruction h_edge = gate * relu(nh + epre); m_v byproduct
    {
        int q = tid >> 6, dp = tid & 63;
        int d0 = 2 * dp, d1 = d0 + 1;
        const float* s0 = g_epre + (size_t)d0 * ECOLS + c0 + q * 24;
        const float* s1 = s0 + ECOLS;
        float sum0 = 0.f, sum1 = 0.f;
        for (int i = 0; i < 24; i += 4) {
            float4 x0 = *(const float4*)(s0 + i);
            float4 x1 = *(const float4*)(s1 + i);
            float a0[4] = {x0.x, x0.y, x0.z, x0.w};
            float a1[4] = {x1.x, x1.y, x1.z, x1.w};
#pragma unroll
            for (int j = 0; j < 4; j++) {
                int w = i + j;
                int n = q * 24 + w;
                float gv = sg[n];
                float v0 = gv * fmaxf(snh[d0 * 24 + w] + a0[j], 0.f);
                float v1 = gv * fmaxf(snh[d1 * 24 + w] + a1[j], 0.f);
                sum0 += v0; sum1 += v1;
                unsigned hw, lw; split_pair(v0, v1, hw, lw);
                sBw[n * BPITCH_W + dp]      = hw;
                sBw[n * BPITCH_W + 64 + dp] = lw;
            }
        }
        int v = off / 24 + q;
        g_mv[d0 * NCOLS + f * 24 + v] = sum0;
        g_mv[d1 * NCOLS + f * 24 + v] = sum1;
    }
    __syncthreads();

    int w = tid >> 5, lane = tid & 31;
    int mp = w & 3, nh = w >> 2;
    float c[2][6][4];
    gemm_m32(c, g_wA4 + (2 * mp) * 768, sbAddr, lane, nh);
    gate_epi32(c, smem, lb1, W2, b2p, nnum, c0, f, off);
}

// ------------ shared hgemm body (m32 x n48 tiling) ------------
__device__ __forceinline__ void hgemm_body(const uint4* __restrict__ Afrag, int mrowblk,
                                           const float* __restrict__ X,
                                           const float* __restrict__ bias,
                                           const float* __restrict__ bias2,
                                           float* __restrict__ Y, int cols, int c0,
                                           char* smem, uint32_t sbAddr)
{
    unsigned* sBw = (unsigned*)smem;
    int tid = threadIdx.x;
    {
        int q = tid >> 6, dp = tid & 63;
        const float* s0 = X + (size_t)(2 * dp) * cols + c0 + q * 24;
        const float* s1 = s0 + cols;
        for (int i = 0; i < 24; i += 4) {
            float4 x0 = *(const float4*)(s0 + i);
            float4 x1 = *(const float4*)(s1 + i);
            float a0[4] = {x0.x, x0.y, x0.z, x0.w};
            float a1[4] = {x1.x, x1.y, x1.z, x1.w};
#pragma unroll
            for (int j = 0; j < 4; j++) {
                int n = q * 24 + i + j;
                unsigned hw, lw; split_pair(a0[j], a1[j], hw, lw);
                sBw[n * BPITCH_W + dp]      = hw;
                sBw[n * BPITCH_W + 64 + dp] = lw;
            }
        }
    }
    __syncthreads();

    int w = tid >> 5, lane = tid & 31;
    int mp = w & 3, nh = w >> 2;
    int g = lane >> 2, t = lane & 3;
    float c[2][6][4];
    gemm_m32(c, Afrag + (mrowblk * 8 + 2 * mp) * 768, sbAddr, lane, nh);

#pragma unroll
    for (int mb = 0; mb < 2; mb++) {
        int r0 = mrowblk * 128 + mp * 32 + mb * 16 + g;
        float b0v = (bias ? bias[r0] : 0.f) + (bias2 ? bias2[r0] : 0.f);
        float b8v = (bias ? bias[r0 + 8] : 0.f) + (bias2 ? bias2[r0 + 8] : 0.f);
#pragma unroll
        for (int j = 0; j < 6; j++) {
            int col = c0 + nh * 48 + j * 8 + t * 2;
            *(float2*)(Y + (size_t)r0 * cols + col) =
                make_float2(c[mb][j][0] + b0v, c[mb][j][1] + b0v);
            *(float2*)(Y + (size_t)(r0 + 8) * cols + col) =
                make_float2(c[mb][j][2] + b8v, c[mb][j][3] + b8v);
        }
    }
}

__global__ void __launch_bounds__(256, 3) hgemm_k(const uint4* __restrict__ Afrag,
                                                  const float* __restrict__ X,
                                                  const float* __restrict__ bias,
                                                  const float* __restrict__ bias2,
                                                  float* __restrict__ Y, int cols)
{
    extern __shared__ char smem[];
    hgemm_body(Afrag, blockIdx.y, X, bias, bias2, Y, cols, blockIdx.x * 96,
               smem, smem_to_u32(smem));
}

// gi and gh in one launch: y<3 -> gi, y>=3 -> gh
__global__ void __launch_bounds__(256, 3) gigh_k(const uint4* __restrict__ wA)
{
    extern __shared__ char smem[];
    int by = blockIdx.y;
    if (by < 3)
        hgemm_body(wA + 18432, by, g_mv, nullptr, nullptr, g_gi, NCOLS,
                   blockIdx.x * 96, smem, smem_to_u32(smem));
    else
        hgemm_body(wA + 36864, by - 3, g_hnode, nullptr, nullptr, g_gh, NCOLS,
                   blockIdx.x * 96, smem, smem_to_u32(smem));
}

// ------------ node transpose ------------
__global__ void __launch_bounds__(256) tr_node_k(const float* __restrict__ in)
{
    int o4 = blockIdx.x * 256 + threadIdx.x;         // < 128*NCOLS/4
    int d = o4 / 1536; int c4 = o4 - d * 1536;
    int f = c4 / 6;    int n4 = c4 - f * 6;
    float4 v = *(const float4*)(in + f * 3072 + d * 24 + n4 * 4);
    int dst = d * NCOLS + f * 24 + n4 * 4;
    *(float4*)(g_node0 + dst) = v;
    *(float4*)(g_hnode + dst) = v;
}

// ------------ last-layer message aggregation ------------
__global__ void __launch_bounds__(256) msg3_k()
{
    __shared__ float snh[32][24];
    __shared__ float sg[576];
    int f = blockIdx.x >> 2, dg = blockIdx.x & 3;
    int tid = threadIdx.x;
    for (int i = tid; i < 768; i += 256) {
        int d = i / 24, w = i - d * 24;
        snh[d][w] = g_nh[(dg * 32 + d) * NCOLS + f * 24 + w];
    }
    for (int i = tid; i < 576; i += 256) sg[i] = g_gate[f * 576 + i];
    __syncthreads();

    int wl = tid & 31, wp = tid >> 5;
    bool ok = wl < 24;
    for (int p = wp; p < 768; p += 8) {
        int dl = p / 24, v = p - dl * 24;
        int d = dg * 32 + dl;
        float s = 0.f;
        if (ok) s = sg[v * 24 + wl] * fmaxf(snh[dl][wl] + g_epre[(size_t)d * ECOLS + f * 576 + v * 24 + wl], 0.f);
#pragma unroll
        for (int o = 16; o; o >>= 1) s += __shfl_xor_sync(0xffffffffu, s, o);
        if (wl == 0) g_mv[d * NCOLS + f * 24 + v] = s;
    }
}

// ------------ GRU elementwise ------------
__global__ void __launch_bounds__(256) gru_k(const int* __restrict__ nnum,
                                             const float* __restrict__ bih,
                                             const float* __restrict__ bhh)
{
    int idx = blockIdx.x * 256 + threadIdx.x;        // < 128*NCOLS
    int j = idx / NCOLS; int col = idx - j * NCOLS;
    float gir = g_gi[j * NCOLS + col]         + bih[j];
    float giz = g_gi[(128 + j) * NCOLS + col] + bih[128 + j];
    float gin = g_gi[(256 + j) * NCOLS + col] + bih[256 + j];
    float ghr = g_gh[j * NCOLS + col]         + bhh[j];
    float ghz = g_gh[(128 + j) * NCOLS + col] + bhh[128 + j];
    float ghn = g_gh[(256 + j) * NCOLS + col] + bhh[256 + j];
    float r = sigm(gir + ghr);
    float z = sigm(giz + ghz);
    float n2 = tanhf(gin + r * ghn);
    float h = g_hnode[idx];
    float hn = (1.f - z) * n2 + z * h;
    int f = col / 24; int n = col - f * 24;
    g_hnode[idx] = (n < nnum[f]) ? hn : g_node0[idx];
}

// ------------ persistent LSTM ------------
__device__ __forceinline__ void group_barrier(int b, unsigned want)
{
    __threadfence();
    __syncthreads();
    if (threadIdx.x == 0) {
        unsigned tk = atomicAdd(&g_cnt2[b], 1u);
        if (tk == 15u) {
            g_cnt2[b] = 0;
            __threadfence();
            atomicExch(&g_sense2[b], want);
        } else {
            unsigned v;
            do {
                asm volatile("ld.acquire.gpu.u32 %0, [%1];" : "=r"(v) : "l"(&g_sense2[b]));
            } while (v != want);
        }
    }
    __syncthreads();
}

__global__ void __launch_bounds__(192) lstm_all_k(const float* __restrict__ Whh)
{
    __shared__ __align__(16) float sWt[128][36];
    __shared__ float sH[128][25];
    __shared__ float sG[32][25];
    int tid = threadIdx.x;
    int rg = blockIdx.x & 15, b = blockIdx.x >> 4;

    for (int i = tid; i < 4096; i += 192) {
        int r = i >> 7, k = i & 127;
        int jg = (r >> 3) * 128 + rg * 8 + (r & 7);
        sWt[k][r] = Whh[jg * 128 + k];
    }
    int tr = tid & 7, tc = tid >> 3;
    int hh = tid / 24, nn = tid - hh * 24;
    int jrow = rg * 8 + hh;
    int scol = b * 24 + nn;
    float creg = 0.f;
    unsigned phase = 0;

    for (int t = 0; t < 32; t++) {
        if (t == 0) {
            for (int i = tid; i < 3200; i += 192) (&sH[0][0])[i] = 0.f;
            __syncthreads();
        } else {
            phase++;
            group_barrier(b, phase & 1u);
            const float* hb = g_h + ((t + 1) & 1) * 24576;
            for (int i = tid; i < 3072; i += 192) {
                int j = i / 24, n2 = i - j * 24;
                sH[j][n2] = __ldcg(hb + j * 192 + b * 24 + n2);
            }
            __syncthreads();
        }

        unsigned long long acc0 = 0ull, acc1 = 0ull;
#pragma unroll 8
        for (int k = 0; k < 128; k++) {
            ulonglong2 av = *(const ulonglong2*)&sWt[k][tr * 4];
            float bv = sH[k][tc];
            unsigned long long bs = pack2(bv, bv);
            ffma2(acc0, av.x, bs);
            ffma2(acc1, av.y, bs);
        }
        float2 u0 = unpack2(acc0), u1 = unpack2(acc1);
        sG[tr * 4 + 0][tc] = u0.x; sG[tr * 4 + 1][tc] = u0.y;
        sG[tr * 4 + 2][tc] = u1.x; sG[tr * 4 + 3][tc] = u1.y;
        __syncthreads();

        int colx = (b * 32 + t) * 24 + nn;
        float ig = sG[hh][nn]      + g_xg[(      jrow) * NCOLS + colx];
        float fg = sG[8 + hh][nn]  + g_xg[(128 + jrow) * NCOLS + colx];
        float gg = sG[16 + hh][nn] + g_xg[(256 + jrow) * NCOLS + colx];
        float og = sG[24 + hh][nn] + g_xg[(384 + jrow) * NCOLS + colx];
        creg = sigm(fg) * creg + sigm(ig) * tanhf(gg);
        float hnew = sigm(og) * tanhf(creg);
        __stcg(g_h + (t & 1) * 24576 + jrow * 192 + scol, hnew);
        g_hist[jrow * 6144 + t * 192 + scol] = hnew;
        __syncthreads();
    }
    phase++;
    group_barrier(b, phase & 1u);
}

// ------------ readout ------------
__global__ void __launch_bounds__(256) readout_k(const float* __restrict__ roW,
                                                 const float* __restrict__ rob,
                                                 const int* __restrict__ nnum,
                                                 float* __restrict__ out)
{
    __shared__ float sH[128][65];
    __shared__ float sRo[6][128];
    __shared__ float sRob[6];
    int tid = threadIdx.x;
    int c0 = blockIdx.x * 64;
    for (int i = tid; i < 8192; i += 256) {
        int j = i >> 6, cc = i & 63;
        sH[j][cc] = g_hist[j * 6144 + c0 + cc];
    }
    for (int i = tid; i < 768; i += 256) sRo[i >> 7][i & 127] = roW[i];
    if (tid < 6) sRob[tid] = rob[tid];
    __syncthreads();
    for (int e = tid; e < 384; e += 256) {
        int cc = e / 6, c = e - cc * 6;
        float s = 0.f;
#pragma unroll 8
        for (int j = 0; j < 128; j++) s += sRo[c][j] * sH[j][cc];
        int ct = c0 + cc;
        int t = ct / 192; int srem = ct - t * 192;
        int b = srem / 24; int n = srem - b * 24;
        int f = b * 32 + t;
        out[(f * 24 + n) * 6 + c] = (n < nnum[f]) ? (s + sRob[c]) : 0.f;
    }
}

// ------------ host launcher ------------
extern "C" void kernel_launch(void* const* d_in, const int* in_sizes, int n_in,
                              void* d_out, int out_size)
{
    const float* node     = (const float*)d_in[0];
    const float* edge     = (const float*)d_in[1];
    const float* link_W1  = (const float*)d_in[2];
    const float* link_b1  = (const float*)d_in[3];
    const float* link_W2  = (const float*)d_in[4];
    const float* link_b2  = (const float*)d_in[5];
    const float* msg_Wh   = (const float*)d_in[6];
    const float* msg_We   = (const float*)d_in[7];
    const float* msg_b    = (const float*)d_in[8];
    const float* gru_Wih  = (const float*)d_in[9];
    const float* gru_Whh  = (const float*)d_in[10];
    const float* gru_bih  = (const float*)d_in[11];
    const float* gru_bhh  = (const float*)d_in[12];
    const float* lstm_Wih = (const float*)d_in[13];
    const float* lstm_Whh = (const float*)d_in[14];
    const float* lstm_bih = (const float*)d_in[15];
    const float* lstm_bhh = (const float*)d_in[16];
    const float* ro_W     = (const float*)d_in[17];
    const float* ro_b     = (const float*)d_in[18];
    const int*   nnum     = (const int*)d_in[19];
    float* out = (float*)d_out;

    float* hnode; cudaGetSymbolAddress((void**)&hnode, g_hnode);
    float* nh;    cudaGetSymbolAddress((void**)&nh,    g_nh);
    float* xg;    cudaGetSymbolAddress((void**)&xg,    g_xg);
    uint4* wA;    cudaGetSymbolAddress((void**)&wA,    g_wA4);

    static int smem_set = 0;
    if (!smem_set) {
        cudaFuncSetAttribute(edge0_k, cudaFuncAttributeMaxDynamicSharedMemorySize, SM_EDGE);
        cudaFuncSetAttribute(recon_k, cudaFuncAttributeMaxDynamicSharedMemorySize, SM_EDGE);
        cudaFuncSetAttribute(hgemm_k, cudaFuncAttributeMaxDynamicSharedMemorySize, SM_HG);
        cudaFuncSetAttribute(gigh_k,  cudaFuncAttributeMaxDynamicSharedMemorySize, SM_HG);
        smem_set = 1;
    }

    const int NTILE = ECOLS / 96;   // 1536
    const int NCT   = NCOLS / 96;   // 64

    // launch order puts recon_k at position 6 (ncu captures launch #6)
    tr_node_k<<<(128 * NCOLS / 4) / 256, 256>>>(node);                       // 1
    prep_a_k<<<72, 256>>>(link_W1, msg_We, msg_Wh, wA);                      // 2
    prep_b_k<<<240, 256>>>(gru_Wih, gru_Whh, lstm_Wih, wA);                  // 3
    edge0_k<<<NTILE, 256, SM_EDGE>>>(edge, link_b1, link_W2, link_b2, msg_b, nnum);  // 4

    for (int p = 0; p < 3; p++) {
        hgemm_k<<<dim3(NCT, 1), 256, SM_HG>>>(wA + 12288, hnode, nullptr, nullptr, nh, NCOLS); // 5
        if (p < 2) {
            recon_k<<<NTILE, 256, SM_EDGE>>>(link_b1, link_W2, link_b2, nnum);                 // 6
        } else {
            msg3_k<<<1024, 256>>>();
        }
        gigh_k<<<dim3(NCT, 6), 256, SM_HG>>>(wA);
        gru_k<<<(128 * NCOLS) / 256, 256>>>(nnum, gru_bih, gru_bhh);
    }

    hgemm_k<<<dim3(NCT, 4), 256, SM_HG>>>(wA + 55296, hnode, lstm_bih, lstm_bhh, xg, NCOLS);
    lstm_all_k<<<128, 192>>>(lstm_Whh);
    readout_k<<<96, 256>>>(ro_W, ro_b, nnum, out);
    (void)in_sizes; (void)n_in; (void)out_size;
}

// round 11
// speedup vs baseline: 1.5577x; 1.0063x over previous
#include <cuda_runtime.h>
#include <cuda_bf16.h>
#include <math.h>
#include <stdint.h>

// ------------ problem constants ------------
#define NFRM   256                  // B*T
#define ECOLS  147456               // NFRM * 576 edge columns
#define NCOLS  6144                 // NFRM * 24 node columns

// ------------ device scratch ------------
__device__ float g_epre  [128 * ECOLS];   // msg_We @ edge + msg_b (loop-invariant)
__device__ float g_gate  [ECOLS];
__device__ float g_node0 [128 * NCOLS];   // transposed node_resnet
__device__ float g_hnode [128 * NCOLS];
__device__ float g_nh    [128 * NCOLS];   // msg_Wh @ h_node
__device__ float g_mv    [128 * NCOLS];
__device__ float g_gi    [384 * NCOLS];
__device__ float g_gh    [384 * NCOLS];
__device__ float g_xg    [512 * NCOLS];   // lstm_Wih @ h_node + bih + bhh
__device__ float g_h     [2 * 128 * 192]; // double-buffered LSTM hidden
__device__ float g_hist  [128 * 6144];    // h history [j][t*192 + b*24 + n]
__device__ unsigned g_cnt2[8];
__device__ unsigned g_sense2[8];
// HMMA A fragments: per m16 block 768 uint4 (24 kk * 32 lanes)
// offsets (uint4): link_W1=0, msg_We=6144, msg_Wh=12288, gru_Wih=18432,
//                  gru_Whh=36864, lstm_Wih=55296  (total 79872)
__device__ uint4 g_wA4[79872];

__device__ __forceinline__ float sigm(float x) { return 1.f / (1.f + expf(-x)); }

__device__ __forceinline__ void ffma2(unsigned long long& acc,
                                      unsigned long long a, unsigned long long b) {
    asm("fma.rn.f32x2 %0, %1, %2, %0;" : "+l"(acc) : "l"(a), "l"(b));
}
__device__ __forceinline__ unsigned long long pack2(float x, float y) {
    unsigned long long r;
    asm("mov.b64 %0, {%1, %2};" : "=l"(r) : "f"(x), "f"(y));
    return r;
}
__device__ __forceinline__ float2 unpack2(unsigned long long v) {
    float2 f;
    asm("mov.b64 {%0, %1}, %2;" : "=f"(f.x), "=f"(f.y) : "l"(v));
    return f;
}
__device__ __forceinline__ void split_bf(float x, __nv_bfloat16& h, __nv_bfloat16& l) {
    h = __float2bfloat16(x);
    l = __float2bfloat16(x - __bfloat162float(h));
}
__device__ __forceinline__ void split_pair(float x0, float x1, unsigned& hw, unsigned& lw) {
    __nv_bfloat16 h0, l0, h1, l1;
    split_bf(x0, h0, l0); split_bf(x1, h1, l1);
    hw = (unsigned)__bfloat16_as_ushort(h0) | ((unsigned)__bfloat16_as_ushort(h1) << 16);
    lw = (unsigned)__bfloat16_as_ushort(l0) | ((unsigned)__bfloat16_as_ushort(l1) << 16);
}
__device__ __forceinline__ uint32_t smem_to_u32(const void* p) {
    uint32_t a;
    asm("{ .reg .u64 t; cvta.to.shared.u64 t, %1; cvt.u32.u64 %0, t; }" : "=r"(a) : "l"(p));
    return a;
}

// ---- HMMA m16n8k16 bf16 ----
__device__ __forceinline__ void mma_bf16(float* c, uint32_t a0, uint32_t a1,
                                         uint32_t a2, uint32_t a3,
                                         uint32_t b0, uint32_t b1) {
    asm volatile(
        "mma.sync.aligned.m16n8k16.row.col.f32.bf16.bf16.f32 "
        "{%0,%1,%2,%3}, {%4,%5,%6,%7}, {%8,%9}, {%0,%1,%2,%3};"
        : "+f"(c[0]), "+f"(c[1]), "+f"(c[2]), "+f"(c[3])
        : "r"(a0), "r"(a1), "r"(a2), "r"(a3), "r"(b0), "r"(b1));
}

// B tile: bf16 [96 rows(n)][264 cols(k: 0-127 hi, 128-255 lo, 8 pad)]
// row pitch 528 B = 132 words; 132 mod 32 = 4 -> ldmatrix conflict-free.
#define BPITCH_W  132       // words per B row
#define BPITCH_B  528
#define SNH_OFF   50688     // float[128*24]
#define SG_OFF    62976     // float[96]
#define SRED_OFF  63360     // float[8][52]
#define SM_EDGE   66688
#define SM_HG     50688

// ------------ prep: pack split-bf16 W (K-stacked [Whi|Whi|Wlo]) into HMMA A-frag layout ------------
__device__ __forceinline__ void prep_one(const float* __restrict__ W, uint4* __restrict__ out,
                                         int gidx)
{
    int mblk = gidx / 768;
    int rem  = gidx - mblk * 768;
    int kk   = rem >> 5;
    int lane = rem & 31;
    int g = lane >> 2, t = lane & 3;
    unsigned regs[4];
#pragma unroll
    for (int r = 0; r < 4; r++) {
        int row = mblk * 16 + g + ((r & 1) ? 8 : 0);
        int k0  = kk * 16 + t * 2 + ((r & 2) ? 8 : 0);
        unsigned pk = 0;
#pragma unroll
        for (int e = 0; e < 2; e++) {
            int ks = k0 + e;
            int region = ks >> 7;
            int kloc = ks & 127;
            float w = W[row * 128 + kloc];
            __nv_bfloat16 h, l; split_bf(w, h, l);
            __nv_bfloat16 b = (region < 2) ? h : l;
            pk |= (unsigned)__bfloat16_as_ushort(b) << (e * 16);
        }
        regs[r] = pk;
    }
    out[gidx] = make_uint4(regs[0], regs[1], regs[2], regs[3]);
}

__global__ void __launch_bounds__(256) prep_a_k(const float* __restrict__ w1,
                                                const float* __restrict__ we,
                                                const float* __restrict__ wh,
                                                uint4* __restrict__ out)
{
    int b = blockIdx.x;
    if (b < 24)      prep_one(w1, out,          b * 256 + threadIdx.x);
    else if (b < 48) prep_one(we, out + 6144,  (b - 24) * 256 + threadIdx.x);
    else             prep_one(wh, out + 12288, (b - 48) * 256 + threadIdx.x);
}
__global__ void __launch_bounds__(256) prep_b_k(const float* __restrict__ wih,
                                                const float* __restrict__ whh,
                                                const float* __restrict__ lih,
                                                uint4* __restrict__ out)
{
    int b = blockIdx.x;
    if (b < 72)       prep_one(wih, out + 18432,  b * 256 + threadIdx.x);
    else if (b < 144) prep_one(whh, out + 36864, (b - 72) * 256 + threadIdx.x);
    else              prep_one(lih, out + 55296, (b - 144) * 256 + threadIdx.x);
}

// ------------ warp GEMM m32 x n48, A-hi dedup (two-phase), unroll-4 load window ------------
// Phase 1: A-hi (kk 0-7) x B-hi then B-lo -> one A load pair per 24 MMAs.
// Phase 2: A-lo (kk 16-23) x B-hi.  Bit-identical to the 24-step version.
__device__ __forceinline__ void gemm_m32(float c[2][6][4], const uint4* __restrict__ A4,
                                         uint32_t sbAddr, int lane, int nh)
{
    int midx = lane >> 3, row = lane & 7;
    uint32_t base0 = sbAddr +
        (uint32_t)((nh * 48 + ((midx >> 1) << 3) + row) * BPITCH_B + (midx & 1) * 16);
#pragma unroll
    for (int mb = 0; mb < 2; mb++)
#pragma unroll
        for (int nt = 0; nt < 6; nt++)
#pragma unroll
            for (int r = 0; r < 4; r++) c[mb][nt][r] = 0.f;

    // phase 1: A-hi shared by B-hi and B-lo k-chunks
#pragma unroll 4
    for (int kk2 = 0; kk2 < 8; kk2++) {
        uint4 a0 = A4[kk2 * 32 + lane];
        uint4 a1 = A4[768 + kk2 * 32 + lane];
        uint32_t r[12];
        // B-hi chunk (bytes kk2*32)
#pragma unroll
        for (int j2 = 0; j2 < 3; j2++) {
            asm volatile("ldmatrix.sync.aligned.m8n8.x4.shared.b16 {%0,%1,%2,%3}, [%4];"
                         : "=r"(r[4 * j2]), "=r"(r[4 * j2 + 1]),
                           "=r"(r[4 * j2 + 2]), "=r"(r[4 * j2 + 3])
                         : "r"(base0 + (uint32_t)(j2 * 16 * BPITCH_B + kk2 * 32)));
        }
#pragma unroll
        for (int j2 = 0; j2 < 3; j2++) {
            mma_bf16(c[0][2 * j2],     a0.x, a0.y, a0.z, a0.w, r[4 * j2],     r[4 * j2 + 1]);
            mma_bf16(c[0][2 * j2 + 1], a0.x, a0.y, a0.z, a0.w, r[4 * j2 + 2], r[4 * j2 + 3]);
            mma_bf16(c[1][2 * j2],     a1.x, a1.y, a1.z, a1.w, r[4 * j2],     r[4 * j2 + 1]);
            mma_bf16(c[1][2 * j2 + 1], a1.x, a1.y, a1.z, a1.w, r[4 * j2 + 2], r[4 * j2 + 3]);
        }
        // B-lo chunk (bytes (kk2+8)*32) with the SAME A-hi fragments
#pragma unroll
        for (int j2 = 0; j2 < 3; j2++) {
            asm volatile("ldmatrix.sync.aligned.m8n8.x4.shared.b16 {%0,%1,%2,%3}, [%4];"
                         : "=r"(r[4 * j2]), "=r"(r[4 * j2 + 1]),
                           "=r"(r[4 * j2 + 2]), "=r"(r[4 * j2 + 3])
                         : "r"(base0 + (uint32_t)(j2 * 16 * BPITCH_B + (kk2 + 8) * 32)));
        }
#pragma unroll
        for (int j2 = 0; j2 < 3; j2++) {
            mma_bf16(c[0][2 * j2],     a0.x, a0.y, a0.z, a0.w, r[4 * j2],     r[4 * j2 + 1]);
            mma_bf16(c[0][2 * j2 + 1], a0.x, a0.y, a0.z, a0.w, r[4 * j2 + 2], r[4 * j2 + 3]);
            mma_bf16(c[1][2 * j2],     a1.x, a1.y, a1.z, a1.w, r[4 * j2],     r[4 * j2 + 1]);
            mma_bf16(c[1][2 * j2 + 1], a1.x, a1.y, a1.z, a1.w, r[4 * j2 + 2], r[4 * j2 + 3]);
        }
    }
    // phase 2: A-lo x B-hi
#pragma unroll 4
    for (int kk2 = 0; kk2 < 8; kk2++) {
        uint4 a0 = A4[(16 + kk2) * 32 + lane];
        uint4 a1 = A4[768 + (16 + kk2) * 32 + lane];
        uint32_t r[12];
#pragma unroll
        for (int j2 = 0; j2 < 3; j2++) {
            asm volatile("ldmatrix.sync.aligned.m8n8.x4.shared.b16 {%0,%1,%2,%3}, [%4];"
                         : "=r"(r[4 * j2]), "=r"(r[4 * j2 + 1]),
                           "=r"(r[4 * j2 + 2]), "=r"(r[4 * j2 + 3])
                         : "r"(base0 + (uint32_t)(j2 * 16 * BPITCH_B + kk2 * 32)));
        }
#pragma unroll
        for (int j2 = 0; j2 < 3; j2++) {
            mma_bf16(c[0][2 * j2],     a0.x, a0.y, a0.z, a0.w, r[4 * j2],     r[4 * j2 + 1]);
            mma_bf16(c[0][2 * j2 + 1], a0.x, a0.y, a0.z, a0.w, r[4 * j2 + 2], r[4 * j2 + 3]);
            mma_bf16(c[1][2 * j2],     a1.x, a1.y, a1.z, a1.w, r[4 * j2],     r[4 * j2 + 1]);
            mma_bf16(c[1][2 * j2 + 1], a1.x, a1.y, a1.z, a1.w, r[4 * j2 + 2], r[4 * j2 + 3]);
        }
    }
}

// ------------ gate epilogue (m32 x n48 tiling) ------------
__device__ __forceinline__ void gate_epi32(float c[2][6][4], char* smem,
                                           const float* __restrict__ lb1,
                                           const float* __restrict__ W2,
                                           const float* __restrict__ b2p,
                                           const int* __restrict__ nnum,
                                           int c0, int f, int off)
{
    int tid = threadIdx.x;
    int w = tid >> 5, lane = tid & 31;
    int mp = w & 3;
    int g = lane >> 2, t = lane & 3;
    float* sRed = (float*)(smem + SRED_OFF);   // [8][52]

    float p0[6], p1[6];
#pragma unroll
    for (int j = 0; j < 6; j++) { p0[j] = 0.f; p1[j] = 0.f; }
#pragma unroll
    for (int mb = 0; mb < 2; mb++) {
        int r0 = mp * 32 + mb * 16 + g;
        float bb0 = lb1[r0], bb8 = lb1[r0 + 8];
        float w0 = W2[r0], w8 = W2[r0 + 8];
#pragma unroll
        for (int j = 0; j < 6; j++) {
            p0[j] += fmaxf(c[mb][j][0] + bb0, 0.f) * w0 + fmaxf(c[mb][j][2] + bb8, 0.f) * w8;
            p1[j] += fmaxf(c[mb][j][1] + bb0, 0.f) * w0 + fmaxf(c[mb][j][3] + bb8, 0.f) * w8;
        }
    }
#pragma unroll
    for (int j = 0; j < 6; j++) {
#pragma unroll
        for (int m = 4; m <= 16; m <<= 1) {
            p0[j] += __shfl_xor_sync(0xffffffffu, p0[j], m);
            p1[j] += __shfl_xor_sync(0xffffffffu, p1[j], m);
        }
    }
    if (g == 0) {
#pragma unroll
        for (int j = 0; j < 6; j++) {
            sRed[w * 52 + j * 8 + t * 2]     = p0[j];
            sRed[w * 52 + j * 8 + t * 2 + 1] = p1[j];
        }
    }
    __syncthreads();
    if (tid < 96) {
        int nh2 = tid / 48, nn = tid - nh2 * 48;
        float s = sRed[(nh2 * 4 + 0) * 52 + nn] + sRed[(nh2 * 4 + 1) * 52 + nn]
                + sRed[(nh2 * 4 + 2) * 52 + nn] + sRed[(nh2 * 4 + 3) * 52 + nn];
        int v = (off + tid) / 24, ww = (off + tid) - v * 24;
        int cnt = nnum[f];
        g_gate[c0 + tid] = (v < cnt && ww < cnt) ? sigm(s + b2p[0]) : 0.f;
    }
}

// ------------ edge0_k: layer-0 gate + epre (two GEMM passes share one B tile) ------------
__global__ void __launch_bounds__(256, 3) edge0_k(const float* __restrict__ edge,
                                                  const float* __restrict__ lb1,
                                                  const float* __restrict__ W2,
                                                  const float* __restrict__ b2p,
                                                  const float* __restrict__ msg_b,
                                                  const int* __restrict__ nnum)
{
    extern __shared__ char smem[];
    uint32_t sbAddr = smem_to_u32(smem);
    unsigned* sBw = (unsigned*)smem;
    int tid = threadIdx.x;
    int c0 = blockIdx.x * 96;
    int f = c0 / 576;
    int off = c0 - f * 576;

    // B conversion, d-pair packed: q = n-quarter, dp = d-pair
    {
        int q = tid >> 6, dp = tid & 63;
        const float* s0 = edge + (size_t)f * 73728 + (2 * dp) * 576 + off + q * 24;
        const float* s1 = s0 + 576;
        for (int i = 0; i < 24; i += 4) {
            float4 x0 = *(const float4*)(s0 + i);
            float4 x1 = *(const float4*)(s1 + i);
            float a0[4] = {x0.x, x0.y, x0.z, x0.w};
            float a1[4] = {x1.x, x1.y, x1.z, x1.w};
#pragma unroll
            for (int j = 0; j < 4; j++) {
                int n = q * 24 + i + j;
                unsigned hw, lw; split_pair(a0[j], a1[j], hw, lw);
                sBw[n * BPITCH_W + dp]      = hw;
                sBw[n * BPITCH_W + 64 + dp] = lw;
            }
        }
    }
    __syncthreads();

    int w = tid >> 5, lane = tid & 31;
    int mp = w & 3, nh = w >> 2;
    int g = lane >> 2, t = lane & 3;
    float c[2][6][4];

    // pass 1: link_W1 -> gate0
    gemm_m32(c, g_wA4 + (2 * mp) * 768, sbAddr, lane, nh);
    gate_epi32(c, smem, lb1, W2, b2p, nnum, c0, f, off);
    __syncthreads();

    // pass 2: msg_We -> epre
    gemm_m32(c, g_wA4 + 6144 + (2 * mp) * 768, sbAddr, lane, nh);
#pragma unroll
    for (int mb = 0; mb < 2; mb++) {
        int r0 = mp * 32 + mb * 16 + g;
        float mb0 = msg_b[r0], mb8 = msg_b[r0 + 8];
#pragma unroll
        for (int j = 0; j < 6; j++) {
            int col = c0 + nh * 48 + j * 8 + t * 2;
            *(float2*)(g_epre + (size_t)r0 * ECOLS + col) =
                make_float2(c[mb][j][0] + mb0, c[mb][j][1] + mb0);
            *(float2*)(g_epre + (size_t)(r0 + 8) * ECOLS + col) =
                make_float2(c[mb][j][2] + mb8, c[mb][j][3] + mb8);
        }
    }
}

// ------------ recon_k: layer p>=1 gate + m_v of layer p-1 (byproduct) ------------
__global__ void __launch_bounds__(256, 3) recon_k(const float* __restrict__ lb1,
                                                  const float* __restrict__ W2,
                                                  const float* __restrict__ b2p,
                                                  const int* __restrict__ nnum)
{
    extern __shared__ char smem[];
    uint32_t sbAddr = smem_to_u32(smem);
    unsigned* sBw = (unsigned*)smem;
    float* snh = (float*)(smem + SNH_OFF);   // [128][24]
    float* sg  = (float*)(smem + SG_OFF);    // [96]
    int tid = threadIdx.x;
    int c0 = blockIdx.x * 96;
    int f = c0 / 576;
    int off = c0 - f * 576;

    for (int i = tid; i < 3072; i += 256) {
        int d = i / 24, w = i - d * 24;
        snh[d * 24 + w] = g_nh[d * NCOLS + f * 24 + w];
    }
    if (tid < 96) sg[tid] = g_gate[c0 + tid];
    __syncthreads();

    // B conversion from reconstruction h_edge = gate * relu(nh + epre); m_v byproduct
    {
        int q = tid >> 6, dp = tid & 63;
        int d0 = 2 * dp, d1 = d0 + 1;
        const float* s0 = g_epre + (size_t)d0 * ECOLS + c0 + q * 24;
        const float* s1 = s0 + ECOLS;
        float sum0 = 0.f, sum1 = 0.f;
        for (int i = 0; i < 24; i += 4) {
            float4 x0 = *(const float4*)(s0 + i);
            float4 x1 = *(const float4*)(s1 + i);
            float a0[4] = {x0.x, x0.y, x0.z, x0.w};
            float a1[4] = {x1.x, x1.y, x1.z, x1.w};
#pragma unroll
            for (int j = 0; j < 4; j++) {
                int w = i + j;
                int n = q * 24 + w;
                float gv = sg[n];
                float v0 = gv * fmaxf(snh[d0 * 24 + w] + a0[j], 0.f);
                float v1 = gv * fmaxf(snh[d1 * 24 + w] + a1[j], 0.f);
                sum0 += v0; sum1 += v1;
                unsigned hw, lw; split_pair(v0, v1, hw, lw);
                sBw[n * BPITCH_W + dp]      = hw;
                sBw[n * BPITCH_W + 64 + dp] = lw;
            }
        }
        int v = off / 24 + q;
        g_mv[d0 * NCOLS + f * 24 + v] = sum0;
        g_mv[d1 * NCOLS + f * 24 + v] = sum1;
    }
    __syncthreads();

    int w = tid >> 5, lane = tid & 31;
    int mp = w & 3, nh = w >> 2;
    float c[2][6][4];
    gemm_m32(c, g_wA4 + (2 * mp) * 768, sbAddr, lane, nh);
    gate_epi32(c, smem, lb1, W2, b2p, nnum, c0, f, off);
}

// ------------ shared hgemm body (m32 x n48 tiling) ------------
__device__ __forceinline__ void hgemm_body(const uint4* __restrict__ Afrag, int mrowblk,
                                           const float* __restrict__ X,
                                           const float* __restrict__ bias,
                                           const float* __restrict__ bias2,
                                           float* __restrict__ Y, int cols, int c0,
                                           char* smem, uint32_t sbAddr)
{
    unsigned* sBw = (unsigned*)smem;
    int tid = threadIdx.x;
    {
        int q = tid >> 6, dp = tid & 63;
        const float* s0 = X + (size_t)(2 * dp) * cols + c0 + q * 24;
        const float* s1 = s0 + cols;
        for (int i = 0; i < 24; i += 4) {
            float4 x0 = *(const float4*)(s0 + i);
            float4 x1 = *(const float4*)(s1 + i);
            float a0[4] = {x0.x, x0.y, x0.z, x0.w};
            float a1[4] = {x1.x, x1.y, x1.z, x1.w};
#pragma unroll
            for (int j = 0; j < 4; j++) {
                int n = q * 24 + i + j;
                unsigned hw, lw; split_pair(a0[j], a1[j], hw, lw);
                sBw[n * BPITCH_W + dp]      = hw;
                sBw[n * BPITCH_W + 64 + dp] = lw;
            }
        }
    }
    __syncthreads();

    int w = tid >> 5, lane = tid & 31;
    int mp = w & 3, nh = w >> 2;
    int g = lane >> 2, t = lane & 3;
    float c[2][6][4];
    gemm_m32(c, Afrag + (mrowblk * 8 + 2 * mp) * 768, sbAddr, lane, nh);

#pragma unroll
    for (int mb = 0; mb < 2; mb++) {
        int r0 = mrowblk * 128 + mp * 32 + mb * 16 + g;
        float b0v = (bias ? bias[r0] : 0.f) + (bias2 ? bias2[r0] : 0.f);
        float b8v = (bias ? bias[r0 + 8] : 0.f) + (bias2 ? bias2[r0 + 8] : 0.f);
#pragma unroll
        for (int j = 0; j < 6; j++) {
            int col = c0 + nh * 48 + j * 8 + t * 2;
            *(float2*)(Y + (size_t)r0 * cols + col) =
                make_float2(c[mb][j][0] + b0v, c[mb][j][1] + b0v);
            *(float2*)(Y + (size_t)(r0 + 8) * cols + col) =
                make_float2(c[mb][j][2] + b8v, c[mb][j][3] + b8v);
        }
    }
}

__global__ void __launch_bounds__(256, 3) hgemm_k(const uint4* __restrict__ Afrag,
                                                  const float* __restrict__ X,
                                                  const float* __restrict__ bias,
                                                  const float* __restrict__ bias2,
                                                  float* __restrict__ Y, int cols)
{
    extern __shared__ char smem[];
    hgemm_body(Afrag, blockIdx.y, X, bias, bias2, Y, cols, blockIdx.x * 96,
               smem, smem_to_u32(smem));
}

// gi and gh in one launch: y<3 -> gi, y>=3 -> gh
__global__ void __launch_bounds__(256, 3) gigh_k(const uint4* __restrict__ wA)
{
    extern __shared__ char smem[];
    int by = blockIdx.y;
    if (by < 3)
        hgemm_body(wA + 18432, by, g_mv, nullptr, nullptr, g_gi, NCOLS,
                   blockIdx.x * 96, smem, smem_to_u32(smem));
    else
        hgemm_body(wA + 36864, by - 3, g_hnode, nullptr, nullptr, g_gh, NCOLS,
                   blockIdx.x * 96, smem, smem_to_u32(smem));
}

// ------------ node transpose ------------
__global__ void __launch_bounds__(256) tr_node_k(const float* __restrict__ in)
{
    int o4 = blockIdx.x * 256 + threadIdx.x;         // < 128*NCOLS/4
    int d = o4 / 1536; int c4 = o4 - d * 1536;
    int f = c4 / 6;    int n4 = c4 - f * 6;
    float4 v = *(const float4*)(in + f * 3072 + d * 24 + n4 * 4);
    int dst = d * NCOLS + f * 24 + n4 * 4;
    *(float4*)(g_node0 + dst) = v;
    *(float4*)(g_hnode + dst) = v;
}

// ------------ last-layer message aggregation ------------
__global__ void __launch_bounds__(256) msg3_k()
{
    __shared__ float snh[32][24];
    __shared__ float sg[576];
    int f = blockIdx.x >> 2, dg = blockIdx.x & 3;
    int tid = threadIdx.x;
    for (int i = tid; i < 768; i += 256) {
        int d = i / 24, w = i - d * 24;
        snh[d][w] = g_nh[(dg * 32 + d) * NCOLS + f * 24 + w];
    }
    for (int i = tid; i < 576; i += 256) sg[i] = g_gate[f * 576 + i];
    __syncthreads();

    int wl = tid & 31, wp = tid >> 5;
    bool ok = wl < 24;
    for (int p = wp; p < 768; p += 8) {
        int dl = p / 24, v = p - dl * 24;
        int d = dg * 32 + dl;
        float s = 0.f;
        if (ok) s = sg[v * 24 + wl] * fmaxf(snh[dl][wl] + g_epre[(size_t)d * ECOLS + f * 576 + v * 24 + wl], 0.f);
#pragma unroll
        for (int o = 16; o; o >>= 1) s += __shfl_xor_sync(0xffffffffu, s, o);
        if (wl == 0) g_mv[d * NCOLS + f * 24 + v] = s;
    }
}

// ------------ GRU elementwise ------------
__global__ void __launch_bounds__(256) gru_k(const int* __restrict__ nnum,
                                             const float* __restrict__ bih,
                                             const float* __restrict__ bhh)
{
    int idx = blockIdx.x * 256 + threadIdx.x;        // < 128*NCOLS
    int j = idx / NCOLS; int col = idx - j * NCOLS;
    float gir = g_gi[j * NCOLS + col]         + bih[j];
    float giz = g_gi[(128 + j) * NCOLS + col] + bih[128 + j];
    float gin = g_gi[(256 + j) * NCOLS + col] + bih[256 + j];
    float ghr = g_gh[j * NCOLS + col]         + bhh[j];
    float ghz = g_gh[(128 + j) * NCOLS + col] + bhh[128 + j];
    float ghn = g_gh[(256 + j) * NCOLS + col] + bhh[256 + j];
    float r = sigm(gir + ghr);
    float z = sigm(giz + ghz);
    float n2 = tanhf(gin + r * ghn);
    float h = g_hnode[idx];
    float hn = (1.f - z) * n2 + z * h;
    int f = col / 24; int n = col - f * 24;
    g_hnode[idx] = (n < nnum[f]) ? hn : g_node0[idx];
}

// ------------ persistent LSTM ------------
__device__ __forceinline__ void group_barrier(int b, unsigned want)
{
    __threadfence();
    __syncthreads();
    if (threadIdx.x == 0) {
        unsigned tk = atomicAdd(&g_cnt2[b], 1u);
        if (tk == 15u) {
            g_cnt2[b] = 0;
            __threadfence();
            atomicExch(&g_sense2[b], want);
        } else {
            unsigned v;
            do {
                asm volatile("ld.acquire.gpu.u32 %0, [%1];" : "=r"(v) : "l"(&g_sense2[b]));
            } while (v != want);
        }
    }
    __syncthreads();
}

__global__ void __launch_bounds__(192) lstm_all_k(const float* __restrict__ Whh)
{
    __shared__ __align__(16) float sWt[128][36];
    __shared__ float sH[128][25];
    __shared__ float sG[32][25];
    int tid = threadIdx.x;
    int rg = blockIdx.x & 15, b = blockIdx.x >> 4;

    for (int i = tid; i < 4096; i += 192) {
        int r = i >> 7, k = i & 127;
        int jg = (r >> 3) * 128 + rg * 8 + (r & 7);
        sWt[k][r] = Whh[jg * 128 + k];
    }
    int tr = tid & 7, tc = tid >> 3;
    int hh = tid / 24, nn = tid - hh * 24;
    int jrow = rg * 8 + hh;
    int scol = b * 24 + nn;
    float creg = 0.f;
    unsigned phase = 0;

    for (int t = 0; t < 32; t++) {
        if (t == 0) {
            for (int i = tid; i < 3200; i += 192) (&sH[0][0])[i] = 0.f;
            __syncthreads();
        } else {
            phase++;
            group_barrier(b, phase & 1u);
            const float* hb = g_h + ((t + 1) & 1) * 24576;
            for (int i = tid; i < 3072; i += 192) {
                int j = i / 24, n2 = i - j * 24;
                sH[j][n2] = __ldcg(hb + j * 192 + b * 24 + n2);
            }
            __syncthreads();
        }

        unsigned long long acc0 = 0ull, acc1 = 0ull;
#pragma unroll 8
        for (int k = 0; k < 128; k++) {
            ulonglong2 av = *(const ulonglong2*)&sWt[k][tr * 4];
            float bv = sH[k][tc];
            unsigned long long bs = pack2(bv, bv);
            ffma2(acc0, av.x, bs);
            ffma2(acc1, av.y, bs);
        }
        float2 u0 = unpack2(acc0), u1 = unpack2(acc1);
        sG[tr * 4 + 0][tc] = u0.x; sG[tr * 4 + 1][tc] = u0.y;
        sG[tr * 4 + 2][tc] = u1.x; sG[tr * 4 + 3][tc] = u1.y;
        __syncthreads();

        int colx = (b * 32 + t) * 24 + nn;
        float ig = sG[hh][nn]      + g_xg[(      jrow) * NCOLS + colx];
        float fg = sG[8 + hh][nn]  + g_xg[(128 + jrow) * NCOLS + colx];
        float gg = sG[16 + hh][nn] + g_xg[(256 + jrow) * NCOLS + colx];
        float og = sG[24 + hh][nn] + g_xg[(384 + jrow) * NCOLS + colx];
        creg = sigm(fg) * creg + sigm(ig) * tanhf(gg);
        float hnew = sigm(og) * tanhf(creg);
        __stcg(g_h + (t & 1) * 24576 + jrow * 192 + scol, hnew);
        g_hist[jrow * 6144 + t * 192 + scol] = hnew;
        __syncthreads();
    }
    phase++;
    group_barrier(b, phase & 1u);
}

// ------------ readout ------------
__global__ void __launch_bounds__(256) readout_k(const float* __restrict__ roW,
                                                 const float* __restrict__ rob,
                                                 const int* __restrict__ nnum,
                                                 float* __restrict__ out)
{
    __shared__ float sH[128][65];
    __shared__ float sRo[6][128];
    __shared__ float sRob[6];
    int tid = threadIdx.x;
    int c0 = blockIdx.x * 64;
    for (int i = tid; i < 8192; i += 256) {
        int j = i >> 6, cc = i & 63;
        sH[j][cc] = g_hist[j * 6144 + c0 + cc];
    }
    for (int i = tid; i < 768; i += 256) sRo[i >> 7][i & 127] = roW[i];
    if (tid < 6) sRob[tid] = rob[tid];
    __syncthreads();
    for (int e = tid; e < 384; e += 256) {
        int cc = e / 6, c = e - cc * 6;
        float s = 0.f;
#pragma unroll 8
        for (int j = 0; j < 128; j++) s += sRo[c][j] * sH[j][cc];
        int ct = c0 + cc;
        int t = ct / 192; int srem = ct - t * 192;
        int b = srem / 24; int n = srem - b * 24;
        int f = b * 32 + t;
        out[(f * 24 + n) * 6 + c] = (n < nnum[f]) ? (s + sRob[c]) : 0.f;
    }
}

// ------------ host launcher ------------
extern "C" void kernel_launch(void* const* d_in, const int* in_sizes, int n_in,
                              void* d_out, int out_size)
{
    const float* node     = (const float*)d_in[0];
    const float* edge     = (const float*)d_in[1];
    const float* link_W1  = (const float*)d_in[2];
    const float* link_b1  = (const float*)d_in[3];
    const float* link_W2  = (const float*)d_in[4];
    const float* link_b2  = (const float*)d_in[5];
    const float* msg_Wh   = (const float*)d_in[6];
    const float* msg_We   = (const float*)d_in[7];
    const float* msg_b    = (const float*)d_in[8];
    const float* gru_Wih  = (const float*)d_in[9];
    const float* gru_Whh  = (const float*)d_in[10];
    const float* gru_bih  = (const float*)d_in[11];
    const float* gru_bhh  = (const float*)d_in[12];
    const float* lstm_Wih = (const float*)d_in[13];
    const float* lstm_Whh = (const float*)d_in[14];
    const float* lstm_bih = (const float*)d_in[15];
    const float* lstm_bhh = (const float*)d_in[16];
    const float* ro_W     = (const float*)d_in[17];
    const float* ro_b     = (const float*)d_in[18];
    const int*   nnum     = (const int*)d_in[19];
    float* out = (float*)d_out;

    float* hnode; cudaGetSymbolAddress((void**)&hnode, g_hnode);
    float* nh;    cudaGetSymbolAddress((void**)&nh,    g_nh);
    float* xg;    cudaGetSymbolAddress((void**)&xg,    g_xg);
    uint4* wA;    cudaGetSymbolAddress((void**)&wA,    g_wA4);

    static int smem_set = 0;
    if (!smem_set) {
        cudaFuncSetAttribute(edge0_k, cudaFuncAttributeMaxDynamicSharedMemorySize, SM_EDGE);
        cudaFuncSetAttribute(recon_k, cudaFuncAttributeMaxDynamicSharedMemorySize, SM_EDGE);
        cudaFuncSetAttribute(hgemm_k, cudaFuncAttributeMaxDynamicSharedMemorySize, SM_HG);
        cudaFuncSetAttribute(gigh_k,  cudaFuncAttributeMaxDynamicSharedMemorySize, SM_HG);
        smem_set = 1;
    }

    const int NTILE = ECOLS / 96;   // 1536
    const int NCT   = NCOLS / 96;   // 64

    // launch order puts recon_k at position 6 (ncu captures launch #6)
    tr_node_k<<<(128 * NCOLS / 4) / 256, 256>>>(node);                       // 1
    prep_a_k<<<72, 256>>>(link_W1, msg_We, msg_Wh, wA);                      // 2
    prep_b_k<<<240, 256>>>(gru_Wih, gru_Whh, lstm_Wih, wA);                  // 3
    edge0_k<<<NTILE, 256, SM_EDGE>>>(edge, link_b1, link_W2, link_b2, msg_b, nnum);  // 4

    for (int p = 0; p < 3; p++) {
        hgemm_k<<<dim3(NCT, 1), 256, SM_HG>>>(wA + 12288, hnode, nullptr, nullptr, nh, NCOLS); // 5
        if (p < 2) {
            recon_k<<<NTILE, 256, SM_EDGE>>>(link_b1, link_W2, link_b2, nnum);                 // 6
        } else {
            msg3_k<<<1024, 256>>>();
        }
        gigh_k<<<dim3(NCT, 6), 256, SM_HG>>>(wA);
        gru_k<<<(128 * NCOLS) / 256, 256>>>(nnum, gru_bih, gru_bhh);
    }

    hgemm_k<<<dim3(NCT, 4), 256, SM_HG>>>(wA + 55296, hnode, lstm_bih, lstm_bhh, xg, NCOLS);
    lstm_all_k<<<128, 192>>>(lstm_Whh);
    readout_k<<<96, 256>>>(ro_W, ro_b, nnum, out);
    (void)in_sizes; (void)n_in; (void)out_size;
}

// round 13
// speedup vs baseline: 1.7728x; 1.1381x over previous
#include <cuda_runtime.h>
#include <cuda_bf16.h>
#include <math.h>
#include <stdint.h>

// ------------ problem constants ------------
#define NFRM   256                  // B*T
#define ECOLS  147456               // NFRM * 576 edge columns
#define NCOLS  6144                 // NFRM * 24 node columns

// ------------ device scratch ------------
__device__ float g_epre  [128 * ECOLS];   // msg_We @ edge + msg_b, COMPACT per frame
__device__ float g_gateA [ECOLS];         // gate double buffer (COMPACT per frame)
__device__ float g_gateB [ECOLS];
__device__ float g_node0 [128 * NCOLS];
__device__ float g_hnode [128 * NCOLS];
__device__ float g_nh    [128 * NCOLS];
__device__ float g_mv    [128 * NCOLS];
__device__ float g_gi    [384 * NCOLS];
__device__ float g_gh    [384 * NCOLS];
__device__ float g_xg    [512 * NCOLS];
__device__ float g_h     [2 * 128 * 192];
__device__ float g_hist  [128 * 6144];
__device__ unsigned g_cnt2[8];
__device__ unsigned g_sense2[8];
// HMMA A fragments: per m16 block 768 uint4 (24 kk * 32 lanes)
__device__ uint4 g_wA4[79872];

__device__ __forceinline__ float sigm(float x) { return 1.f / (1.f + expf(-x)); }

__device__ __forceinline__ void ffma2(unsigned long long& acc,
                                      unsigned long long a, unsigned long long b) {
    asm("fma.rn.f32x2 %0, %1, %2, %0;" : "+l"(acc) : "l"(a), "l"(b));
}
__device__ __forceinline__ unsigned long long pack2(float x, float y) {
    unsigned long long r;
    asm("mov.b64 %0, {%1, %2};" : "=l"(r) : "f"(x), "f"(y));
    return r;
}
__device__ __forceinline__ float2 unpack2(unsigned long long v) {
    float2 f;
    asm("mov.b64 {%0, %1}, %2;" : "=f"(f.x), "=f"(f.y) : "l"(v));
    return f;
}
__device__ __forceinline__ void split_bf(float x, __nv_bfloat16& h, __nv_bfloat16& l) {
    h = __float2bfloat16(x);
    l = __float2bfloat16(x - __bfloat162float(h));
}
__device__ __forceinline__ void split_pair(float x0, float x1, unsigned& hw, unsigned& lw) {
    __nv_bfloat16 h0, l0, h1, l1;
    split_bf(x0, h0, l0); split_bf(x1, h1, l1);
    hw = (unsigned)__bfloat16_as_ushort(h0) | ((unsigned)__bfloat16_as_ushort(h1) << 16);
    lw = (unsigned)__bfloat16_as_ushort(l0) | ((unsigned)__bfloat16_as_ushort(l1) << 16);
}
__device__ __forceinline__ uint32_t smem_to_u32(const void* p) {
    uint32_t a;
    asm("{ .reg .u64 t; cvta.to.shared.u64 t, %1; cvt.u32.u64 %0, t; }" : "=r"(a) : "l"(p));
    return a;
}

// ---- HMMA m16n8k16 bf16 ----
__device__ __forceinline__ void mma_bf16(float* c, uint32_t a0, uint32_t a1,
                                         uint32_t a2, uint32_t a3,
                                         uint32_t b0, uint32_t b1) {
    asm volatile(
        "mma.sync.aligned.m16n8k16.row.col.f32.bf16.bf16.f32 "
        "{%0,%1,%2,%3}, {%4,%5,%6,%7}, {%8,%9}, {%0,%1,%2,%3};"
        : "+f"(c[0]), "+f"(c[1]), "+f"(c[2]), "+f"(c[3])
        : "r"(a0), "r"(a1), "r"(a2), "r"(a3), "r"(b0), "r"(b1));
}

#define BPITCH_W  132       // 32-bit words per B row
#define BPITCH_B  528
#define SNH_OFF   50688     // float[128*24]
#define SG_OFF    62976     // float[96]
#define SRED_OFF  63360     // float[8][52]
#define SLUT_OFF  65024     // int[96]
#define SM_EDGE   66688
#define SM_HG     50688

// ------------ prep: pack split-bf16 W into HMMA A-frag layout ------------
__device__ __forceinline__ void prep_one(const float* __restrict__ W, uint4* __restrict__ out,
                                         int gidx)
{
    int mblk = gidx / 768;
    int rem  = gidx - mblk * 768;
    int kk   = rem >> 5;
    int lane = rem & 31;
    int g = lane >> 2, t = lane & 3;
    unsigned regs[4];
#pragma unroll
    for (int r = 0; r < 4; r++) {
        int row = mblk * 16 + g + ((r & 1) ? 8 : 0);
        int k0  = kk * 16 + t * 2 + ((r & 2) ? 8 : 0);
        unsigned pk = 0;
#pragma unroll
        for (int e = 0; e < 2; e++) {
            int ks = k0 + e;
            int region = ks >> 7;
            int kloc = ks & 127;
            float w = W[row * 128 + kloc];
            __nv_bfloat16 h, l; split_bf(w, h, l);
            __nv_bfloat16 b = (region < 2) ? h : l;
            pk |= (unsigned)__bfloat16_as_ushort(b) << (e * 16);
        }
        regs[r] = pk;
    }
    out[gidx] = make_uint4(regs[0], regs[1], regs[2], regs[3]);
}

__global__ void __launch_bounds__(256) prep_a_k(const float* __restrict__ w1,
                                                const float* __restrict__ we,
                                                const float* __restrict__ wh,
                                                uint4* __restrict__ out)
{
    int b = blockIdx.x;
    if (b < 24)      prep_one(w1, out,          b * 256 + threadIdx.x);
    else if (b < 48) prep_one(we, out + 6144,  (b - 24) * 256 + threadIdx.x);
    else             prep_one(wh, out + 12288, (b - 48) * 256 + threadIdx.x);
}
__global__ void __launch_bounds__(256) prep_b_k(const float* __restrict__ wih,
                                                const float* __restrict__ whh,
                                                const float* __restrict__ lih,
                                                uint4* __restrict__ out)
{
    int b = blockIdx.x;
    if (b < 72)       prep_one(wih, out + 18432,  b * 256 + threadIdx.x);
    else if (b < 144) prep_one(whh, out + 36864, (b - 72) * 256 + threadIdx.x);
    else              prep_one(lih, out + 55296, (b - 144) * 256 + threadIdx.x);
}

// ------------ warp GEMM m32 x n48, A-hi dedup (two-phase), unroll-4 ------------
__device__ __forceinline__ void gemm_m32(float c[2][6][4], const uint4* __restrict__ A4,
                                         uint32_t sbAddr, int lane, int nh)
{
    int midx = lane >> 3, row = lane & 7;
    uint32_t base0 = sbAddr +
        (uint32_t)((nh * 48 + ((midx >> 1) << 3) + row) * BPITCH_B + (midx & 1) * 16);
#pragma unroll
    for (int mb = 0; mb < 2; mb++)
#pragma unroll
        for (int nt = 0; nt < 6; nt++)
#pragma unroll
            for (int r = 0; r < 4; r++) c[mb][nt][r] = 0.f;

#pragma unroll 4
    for (int kk2 = 0; kk2 < 8; kk2++) {
        uint4 a0 = A4[kk2 * 32 + lane];
        uint4 a1 = A4[768 + kk2 * 32 + lane];
        uint32_t r[12];
#pragma unroll
        for (int j2 = 0; j2 < 3; j2++) {
            asm volatile("ldmatrix.sync.aligned.m8n8.x4.shared.b16 {%0,%1,%2,%3}, [%4];"
                         : "=r"(r[4 * j2]), "=r"(r[4 * j2 + 1]),
                           "=r"(r[4 * j2 + 2]), "=r"(r[4 * j2 + 3])
                         : "r"(base0 + (uint32_t)(j2 * 16 * BPITCH_B + kk2 * 32)));
        }
#pragma unroll
        for (int j2 = 0; j2 < 3; j2++) {
            mma_bf16(c[0][2 * j2],     a0.x, a0.y, a0.z, a0.w, r[4 * j2],     r[4 * j2 + 1]);
            mma_bf16(c[0][2 * j2 + 1], a0.x, a0.y, a0.z, a0.w, r[4 * j2 + 2], r[4 * j2 + 3]);
            mma_bf16(c[1][2 * j2],     a1.x, a1.y, a1.z, a1.w, r[4 * j2],     r[4 * j2 + 1]);
            mma_bf16(c[1][2 * j2 + 1], a1.x, a1.y, a1.z, a1.w, r[4 * j2 + 2], r[4 * j2 + 3]);
        }
#pragma unroll
        for (int j2 = 0; j2 < 3; j2++) {
            asm volatile("ldmatrix.sync.aligned.m8n8.x4.shared.b16 {%0,%1,%2,%3}, [%4];"
                         : "=r"(r[4 * j2]), "=r"(r[4 * j2 + 1]),
                           "=r"(r[4 * j2 + 2]), "=r"(r[4 * j2 + 3])
                         : "r"(base0 + (uint32_t)(j2 * 16 * BPITCH_B + (kk2 + 8) * 32)));
        }
#pragma unroll
        for (int j2 = 0; j2 < 3; j2++) {
            mma_bf16(c[0][2 * j2],     a0.x, a0.y, a0.z, a0.w, r[4 * j2],     r[4 * j2 + 1]);
            mma_bf16(c[0][2 * j2 + 1], a0.x, a0.y, a0.z, a0.w, r[4 * j2 + 2], r[4 * j2 + 3]);
            mma_bf16(c[1][2 * j2],     a1.x, a1.y, a1.z, a1.w, r[4 * j2],     r[4 * j2 + 1]);
            mma_bf16(c[1][2 * j2 + 1], a1.x, a1.y, a1.z, a1.w, r[4 * j2 + 2], r[4 * j2 + 3]);
        }
    }
#pragma unroll 4
    for (int kk2 = 0; kk2 < 8; kk2++) {
        uint4 a0 = A4[(16 + kk2) * 32 + lane];
        uint4 a1 = A4[768 + (16 + kk2) * 32 + lane];
        uint32_t r[12];
#pragma unroll
        for (int j2 = 0; j2 < 3; j2++) {
            asm volatile("ldmatrix.sync.aligned.m8n8.x4.shared.b16 {%0,%1,%2,%3}, [%4];"
                         : "=r"(r[4 * j2]), "=r"(r[4 * j2 + 1]),
                           "=r"(r[4 * j2 + 2]), "=r"(r[4 * j2 + 3])
                         : "r"(base0 + (uint32_t)(j2 * 16 * BPITCH_B + kk2 * 32)));
        }
#pragma unroll
        for (int j2 = 0; j2 < 3; j2++) {
            mma_bf16(c[0][2 * j2],     a0.x, a0.y, a0.z, a0.w, r[4 * j2],     r[4 * j2 + 1]);
            mma_bf16(c[0][2 * j2 + 1], a0.x, a0.y, a0.z, a0.w, r[4 * j2 + 2], r[4 * j2 + 3]);
            mma_bf16(c[1][2 * j2],     a1.x, a1.y, a1.z, a1.w, r[4 * j2],     r[4 * j2 + 1]);
            mma_bf16(c[1][2 * j2 + 1], a1.x, a1.y, a1.z, a1.w, r[4 * j2 + 2], r[4 * j2 + 3]);
        }
    }
}

// ------------ gate epilogue (compact: no mask needed) ------------
__device__ __forceinline__ void gate_epi32(float c[2][6][4], char* smem,
                                           const float* __restrict__ lb1,
                                           const float* __restrict__ W2,
                                           const float* __restrict__ b2p,
                                           float* __restrict__ gate_out, int base)
{
    int tid = threadIdx.x;
    int w = tid >> 5, lane = tid & 31;
    int mp = w & 3;
    int g = lane >> 2, t = lane & 3;
    float* sRed = (float*)(smem + SRED_OFF);   // [8][52]

    float p0[6], p1[6];
#pragma unroll
    for (int j = 0; j < 6; j++) { p0[j] = 0.f; p1[j] = 0.f; }
#pragma unroll
    for (int mb = 0; mb < 2; mb++) {
        int r0 = mp * 32 + mb * 16 + g;
        float bb0 = lb1[r0], bb8 = lb1[r0 + 8];
        float w0 = W2[r0], w8 = W2[r0 + 8];
#pragma unroll
        for (int j = 0; j < 6; j++) {
            p0[j] += fmaxf(c[mb][j][0] + bb0, 0.f) * w0 + fmaxf(c[mb][j][2] + bb8, 0.f) * w8;
            p1[j] += fmaxf(c[mb][j][1] + bb0, 0.f) * w0 + fmaxf(c[mb][j][3] + bb8, 0.f) * w8;
        }
    }
#pragma unroll
    for (int j = 0; j < 6; j++) {
#pragma unroll
        for (int m = 4; m <= 16; m <<= 1) {
            p0[j] += __shfl_xor_sync(0xffffffffu, p0[j], m);
            p1[j] += __shfl_xor_sync(0xffffffffu, p1[j], m);
        }
    }
    if (g == 0) {
#pragma unroll
        for (int j = 0; j < 6; j++) {
            sRed[w * 52 + j * 8 + t * 2]     = p0[j];
            sRed[w * 52 + j * 8 + t * 2 + 1] = p1[j];
        }
    }
    __syncthreads();
    if (tid < 96) {
        int nh2 = tid / 48, nn = tid - nh2 * 48;
        float s = sRed[(nh2 * 4 + 0) * 52 + nn] + sRed[(nh2 * 4 + 1) * 52 + nn]
                + sRed[(nh2 * 4 + 2) * 52 + nn] + sRed[(nh2 * 4 + 3) * 52 + nn];
        gate_out[base + tid] = sigm(s + b2p[0]);
    }
}

// ------------ edge0_k: layer-0 gate + epre over COMPACT columns ------------
__global__ void __launch_bounds__(256, 3) edge0_k(const float* __restrict__ edge,
                                                  const float* __restrict__ lb1,
                                                  const float* __restrict__ W2,
                                                  const float* __restrict__ b2p,
                                                  const float* __restrict__ msg_b,
                                                  const int* __restrict__ nnum,
                                                  float* __restrict__ gate_out)
{
    extern __shared__ char smem[];
    uint32_t sbAddr = smem_to_u32(smem);
    unsigned* sBw = (unsigned*)smem;
    int* sidx = (int*)(smem + SLUT_OFF);
    int tid = threadIdx.x;
    int bx = blockIdx.x;
    int f = bx / 6; int tt = bx - f * 6;
    int cnt = nnum[f]; int NV = cnt * cnt;
    int cb = tt * 96;
    if (cb >= NV) return;                     // uniform early exit
    int base = f * 576 + cb;

    if (tid < 96) {
        int c = cb + tid;
        int v = c / cnt;
        sidx[tid] = v * 24 + (c - v * cnt);
    }
    __syncthreads();

    // B conversion from original edge layout, compact columns
    {
        int q = tid >> 6, dp = tid & 63;
        const float* e0 = edge + (size_t)f * 73728 + (size_t)(2 * dp) * 576;
        const float* e1 = e0 + 576;
        int n0 = q * 24;
        for (int i = 0; i < 24; i++) {
            int nn = n0 + i;
            float x0 = 0.f, x1 = 0.f;
            if (cb + nn < NV) { int idx = sidx[nn]; x0 = e0[idx]; x1 = e1[idx]; }
            unsigned hw, lw; split_pair(x0, x1, hw, lw);
            sBw[nn * BPITCH_W + dp]      = hw;
            sBw[nn * BPITCH_W + 64 + dp] = lw;
        }
    }
    __syncthreads();

    int w = tid >> 5, lane = tid & 31;
    int mp = w & 3, nh = w >> 2;
    int g = lane >> 2, t = lane & 3;
    float c[2][6][4];

    // pass 1: link_W1 -> gate0
    gemm_m32(c, g_wA4 + (2 * mp) * 768, sbAddr, lane, nh);
    gate_epi32(c, smem, lb1, W2, b2p, gate_out, base);
    __syncthreads();

    // pass 2: msg_We -> epre
    gemm_m32(c, g_wA4 + 6144 + (2 * mp) * 768, sbAddr, lane, nh);
#pragma unroll
    for (int mb = 0; mb < 2; mb++) {
        int r0 = mp * 32 + mb * 16 + g;
        float mb0 = msg_b[r0], mb8 = msg_b[r0 + 8];
#pragma unroll
        for (int j = 0; j < 6; j++) {
            int col = base + nh * 48 + j * 8 + t * 2;
            *(float2*)(g_epre + (size_t)r0 * ECOLS + col) =
                make_float2(c[mb][j][0] + mb0, c[mb][j][1] + mb0);
            *(float2*)(g_epre + (size_t)(r0 + 8) * ECOLS + col) =
                make_float2(c[mb][j][2] + mb8, c[mb][j][3] + mb8);
        }
    }
}

// ------------ recon_k: gate_{p+1} from reconstruction (COMPACT, double-buffered gate) ------------
__global__ void __launch_bounds__(256, 3) recon_k(const float* __restrict__ lb1,
                                                  const float* __restrict__ W2,
                                                  const float* __restrict__ b2p,
                                                  const int* __restrict__ nnum,
                                                  const float* __restrict__ gate_in,
                                                  float* __restrict__ gate_out)
{
    extern __shared__ char smem[];
    uint32_t sbAddr = smem_to_u32(smem);
    unsigned* sBw = (unsigned*)smem;
    float* snh = (float*)(smem + SNH_OFF);   // [128][24]
    float* sg  = (float*)(smem + SG_OFF);    // [96]
    int* ssw = (int*)(smem + SLUT_OFF);      // [96]
    int tid = threadIdx.x;
    int bx = blockIdx.x;
    int f = bx / 6; int tt = bx - f * 6;
    int cnt = nnum[f]; int NV = cnt * cnt;
    int cb = tt * 96;
    if (cb >= NV) return;
    int base = f * 576 + cb;

    for (int i = tid; i < 3072; i += 256) {
        int d = i / 24, w = i - d * 24;
        snh[d * 24 + w] = g_nh[d * NCOLS + f * 24 + w];
    }
    if (tid < 96) {
        sg[tid] = gate_in[base + tid];
        int c = cb + tid;
        int v = c / cnt;
        ssw[tid] = c - v * cnt;
    }
    __syncthreads();

    // B conversion: h_edge = gate * relu(nh + epre) on compact columns
    {
        int q = tid >> 6, dp = tid & 63;
        int d0 = 2 * dp, d1 = d0 + 1;
        const float* s0 = g_epre + (size_t)d0 * ECOLS + base + q * 24;
        const float* s1 = s0 + ECOLS;
        int n0 = q * 24;
        for (int i = 0; i < 24; i += 4) {
            float4 x0 = *(const float4*)(s0 + i);
            float4 x1 = *(const float4*)(s1 + i);
            float a0[4] = {x0.x, x0.y, x0.z, x0.w};
            float a1[4] = {x1.x, x1.y, x1.z, x1.w};
#pragma unroll
            for (int j = 0; j < 4; j++) {
                int nn = n0 + i + j;
                float v0 = 0.f, v1 = 0.f;
                if (cb + nn < NV) {
                    int w = ssw[nn];
                    float gv = sg[nn];
                    v0 = gv * fmaxf(snh[d0 * 24 + w] + a0[j], 0.f);
                    v1 = gv * fmaxf(snh[d1 * 24 + w] + a1[j], 0.f);
                }
                unsigned hw, lw; split_pair(v0, v1, hw, lw);
                sBw[nn * BPITCH_W + dp]      = hw;
                sBw[nn * BPITCH_W + 64 + dp] = lw;
            }
        }
    }
    __syncthreads();

    int w = tid >> 5, lane = tid & 31;
    int mp = w & 3, nh = w >> 2;
    float c[2][6][4];
    gemm_m32(c, g_wA4 + (2 * mp) * 768, sbAddr, lane, nh);
    gate_epi32(c, smem, lb1, W2, b2p, gate_out, base);
}

// ------------ mv_k: m_v[d][v] = sum_{w<cnt} gate_p[c]*relu(nh+epre[c]) ------------
__global__ void __launch_bounds__(256) mv_k(const int* __restrict__ nnum,
                                            const float* __restrict__ gate_in)
{
    __shared__ float snh[32 * 24];
    __shared__ float sg[576];
    int f = blockIdx.x >> 2, dg = blockIdx.x & 3;
    int cnt = nnum[f];
    int NV = cnt * cnt;
    int tid = threadIdx.x;
    for (int i = tid; i < 768; i += 256) {
        int d = i / 24, w = i - d * 24;
        snh[i] = g_nh[(dg * 32 + d) * NCOLS + f * 24 + w];
    }
    for (int i = tid; i < NV; i += 256) sg[i] = gate_in[f * 576 + i];
    __syncthreads();

    for (int p = tid; p < 768; p += 256) {
        int dl = p / 24, v = p - dl * 24;
        int d = dg * 32 + dl;
        float s = 0.f;
        if (v < cnt) {
            const float* ep = g_epre + (size_t)d * ECOLS + f * 576 + v * cnt;
            const float* gp = sg + v * cnt;
            const float* np = snh + dl * 24;
            for (int w = 0; w < cnt; w++)
                s += gp[w] * fmaxf(np[w] + ep[w], 0.f);
        }
        g_mv[d * NCOLS + f * 24 + v] = s;
    }
}

// ------------ shared hgemm body (m32 x n48 tiling) ------------
__device__ __forceinline__ void hgemm_body(const uint4* __restrict__ Afrag, int mrowblk,
                                           const float* __restrict__ X,
                                           const float* __restrict__ bias,
                                           const float* __restrict__ bias2,
                                           float* __restrict__ Y, int cols, int c0,
                                           char* smem, uint32_t sbAddr)
{
    unsigned* sBw = (unsigned*)smem;
    int tid = threadIdx.x;
    {
        int q = tid >> 6, dp = tid & 63;
        const float* s0 = X + (size_t)(2 * dp) * cols + c0 + q * 24;
        const float* s1 = s0 + cols;
        for (int i = 0; i < 24; i += 4) {
            float4 x0 = *(const float4*)(s0 + i);
            float4 x1 = *(const float4*)(s1 + i);
            float a0[4] = {x0.x, x0.y, x0.z, x0.w};
            float a1[4] = {x1.x, x1.y, x1.z, x1.w};
#pragma unroll
            for (int j = 0; j < 4; j++) {
                int n = q * 24 + i + j;
                unsigned hw, lw; split_pair(a0[j], a1[j], hw, lw);
                sBw[n * BPITCH_W + dp]      = hw;
                sBw[n * BPITCH_W + 64 + dp] = lw;
            }
        }
    }
    __syncthreads();

    int w = tid >> 5, lane = tid & 31;
    int mp = w & 3, nh = w >> 2;
    int g = lane >> 2, t = lane & 3;
    float c[2][6][4];
    gemm_m32(c, Afrag + (mrowblk * 8 + 2 * mp) * 768, sbAddr, lane, nh);

#pragma unroll
    for (int mb = 0; mb < 2; mb++) {
        int r0 = mrowblk * 128 + mp * 32 + mb * 16 + g;
        float b0v = (bias ? bias[r0] : 0.f) + (bias2 ? bias2[r0] : 0.f);
        float b8v = (bias ? bias[r0 + 8] : 0.f) + (bias2 ? bias2[r0 + 8] : 0.f);
#pragma unroll
        for (int j = 0; j < 6; j++) {
            int col = c0 + nh * 48 + j * 8 + t * 2;
            *(float2*)(Y + (size_t)r0 * cols + col) =
                make_float2(c[mb][j][0] + b0v, c[mb][j][1] + b0v);
            *(float2*)(Y + (size_t)(r0 + 8) * cols + col) =
                make_float2(c[mb][j][2] + b8v, c[mb][j][3] + b8v);
        }
    }
}

__global__ void __launch_bounds__(256, 3) hgemm_k(const uint4* __restrict__ Afrag,
                                                  const float* __restrict__ X,
                                                  const float* __restrict__ bias,
                                                  const float* __restrict__ bias2,
                                                  float* __restrict__ Y, int cols)
{
    extern __shared__ char smem[];
    hgemm_body(Afrag, blockIdx.y, X, bias, bias2, Y, cols, blockIdx.x * 96,
               smem, smem_to_u32(smem));
}

__global__ void __launch_bounds__(256, 3) gigh_k(const uint4* __restrict__ wA)
{
    extern __shared__ char smem[];
    int by = blockIdx.y;
    if (by < 3)
        hgemm_body(wA + 18432, by, g_mv, nullptr, nullptr, g_gi, NCOLS,
                   blockIdx.x * 96, smem, smem_to_u32(smem));
    else
        hgemm_body(wA + 36864, by - 3, g_hnode, nullptr, nullptr, g_gh, NCOLS,
                   blockIdx.x * 96, smem, smem_to_u32(smem));
}

// ------------ node transpose ------------
__global__ void __launch_bounds__(256) tr_node_k(const float* __restrict__ in)
{
    int o4 = blockIdx.x * 256 + threadIdx.x;
    int d = o4 / 1536; int c4 = o4 - d * 1536;
    int f = c4 / 6;    int n4 = c4 - f * 6;
    float4 v = *(const float4*)(in + f * 3072 + d * 24 + n4 * 4);
    int dst = d * NCOLS + f * 24 + n4 * 4;
    *(float4*)(g_node0 + dst) = v;
    *(float4*)(g_hnode + dst) = v;
}

// ------------ GRU elementwise ------------
__global__ void __launch_bounds__(256) gru_k(const int* __restrict__ nnum,
                                             const float* __restrict__ bih,
                                             const float* __restrict__ bhh)
{
    int idx = blockIdx.x * 256 + threadIdx.x;
    int j = idx / NCOLS; int col = idx - j * NCOLS;
    float gir = g_gi[j * NCOLS + col]         + bih[j];
    float giz = g_gi[(128 + j) * NCOLS + col] + bih[128 + j];
    float gin = g_gi[(256 + j) * NCOLS + col] + bih[256 + j];
    float ghr = g_gh[j * NCOLS + col]         + bhh[j];
    float ghz = g_gh[(128 + j) * NCOLS + col] + bhh[128 + j];
    float ghn = g_gh[(256 + j) * NCOLS + col] + bhh[256 + j];
    float r = sigm(gir + ghr);
    float z = sigm(giz + ghz);
    float n2 = tanhf(gin + r * ghn);
    float h = g_hnode[idx];
    float hn = (1.f - z) * n2 + z * h;
    int f = col / 24; int n = col - f * 24;
    g_hnode[idx] = (n < nnum[f]) ? hn : g_node0[idx];
}

// ------------ persistent LSTM ------------
__device__ __forceinline__ void group_barrier(int b, unsigned want)
{
    __threadfence();
    __syncthreads();
    if (threadIdx.x == 0) {
        unsigned tk = atomicAdd(&g_cnt2[b], 1u);
        if (tk == 15u) {
            g_cnt2[b] = 0;
            __threadfence();
            atomicExch(&g_sense2[b], want);
        } else {
            unsigned v;
            do {
                asm volatile("ld.acquire.gpu.u32 %0, [%1];" : "=r"(v) : "l"(&g_sense2[b]));
            } while (v != want);
        }
    }
    __syncthreads();
}

__global__ void __launch_bounds__(192) lstm_all_k(const float* __restrict__ Whh)
{
    __shared__ __align__(16) float sWt[128][36];
    __shared__ float sH[128][25];
    __shared__ float sG[32][25];
    int tid = threadIdx.x;
    int rg = blockIdx.x & 15, b = blockIdx.x >> 4;

    for (int i = tid; i < 4096; i += 192) {
        int r = i >> 7, k = i & 127;
        int jg = (r >> 3) * 128 + rg * 8 + (r & 7);
        sWt[k][r] = Whh[jg * 128 + k];
    }
    int tr = tid & 7, tc = tid >> 3;
    int hh = tid / 24, nn = tid - hh * 24;
    int jrow = rg * 8 + hh;
    int scol = b * 24 + nn;
    float creg = 0.f;
    unsigned phase = 0;

    for (int t = 0; t < 32; t++) {
        if (t == 0) {
            for (int i = tid; i < 3200; i += 192) (&sH[0][0])[i] = 0.f;
            __syncthreads();
        } else {
            phase++;
            group_barrier(b, phase & 1u);
            const float* hb = g_h + ((t + 1) & 1) * 24576;
            for (int i = tid; i < 3072; i += 192) {
                int j = i / 24, n2 = i - j * 24;
                sH[j][n2] = __ldcg(hb + j * 192 + b * 24 + n2);
            }
            __syncthreads();
        }

        unsigned long long acc0 = 0ull, acc1 = 0ull;
#pragma unroll 8
        for (int k = 0; k < 128; k++) {
            ulonglong2 av = *(const ulonglong2*)&sWt[k][tr * 4];
            float bv = sH[k][tc];
            unsigned long long bs = pack2(bv, bv);
            ffma2(acc0, av.x, bs);
            ffma2(acc1, av.y, bs);
        }
        float2 u0 = unpack2(acc0), u1 = unpack2(acc1);
        sG[tr * 4 + 0][tc] = u0.x; sG[tr * 4 + 1][tc] = u0.y;
        sG[tr * 4 + 2][tc] = u1.x; sG[tr * 4 + 3][tc] = u1.y;
        __syncthreads();

        int colx = (b * 32 + t) * 24 + nn;
        float ig = sG[hh][nn]      + g_xg[(      jrow) * NCOLS + colx];
        float fg = sG[8 + hh][nn]  + g_xg[(128 + jrow) * NCOLS + colx];
        float gg = sG[16 + hh][nn] + g_xg[(256 + jrow) * NCOLS + colx];
        float og = sG[24 + hh][nn] + g_xg[(384 + jrow) * NCOLS + colx];
        creg = sigm(fg) * creg + sigm(ig) * tanhf(gg);
        float hnew = sigm(og) * tanhf(creg);
        __stcg(g_h + (t & 1) * 24576 + jrow * 192 + scol, hnew);
        g_hist[jrow * 6144 + t * 192 + scol] = hnew;
        __syncthreads();
    }
    phase++;
    group_barrier(b, phase & 1u);
}

// ------------ readout ------------
__global__ void __launch_bounds__(256) readout_k(const float* __restrict__ roW,
                                                 const float* __restrict__ rob,
                                                 const int* __restrict__ nnum,
                                                 float* __restrict__ out)
{
    __shared__ float sH[128][65];
    __shared__ float sRo[6][128];
    __shared__ float sRob[6];
    int tid = threadIdx.x;
    int c0 = blockIdx.x * 64;
    for (int i = tid; i < 8192; i += 256) {
        int j = i >> 6, cc = i & 63;
        sH[j][cc] = g_hist[j * 6144 + c0 + cc];
    }
    for (int i = tid; i < 768; i += 256) sRo[i >> 7][i & 127] = roW[i];
    if (tid < 6) sRob[tid] = rob[tid];
    __syncthreads();
    for (int e = tid; e < 384; e += 256) {
        int cc = e / 6, c = e - cc * 6;
        float s = 0.f;
#pragma unroll 8
        for (int j = 0; j < 128; j++) s += sRo[c][j] * sH[j][cc];
        int ct = c0 + cc;
        int t = ct / 192; int srem = ct - t * 192;
        int b = srem / 24; int n = srem - b * 24;
        int f = b * 32 + t;
        out[(f * 24 + n) * 6 + c] = (n < nnum[f]) ? (s + sRob[c]) : 0.f;
    }
}

// ------------ host launcher ------------
extern "C" void kernel_launch(void* const* d_in, const int* in_sizes, int n_in,
                              void* d_out, int out_size)
{
    const float* node     = (const float*)d_in[0];
    const float* edge     = (const float*)d_in[1];
    const float* link_W1  = (const float*)d_in[2];
    const float* link_b1  = (const float*)d_in[3];
    const float* link_W2  = (const float*)d_in[4];
    const float* link_b2  = (const float*)d_in[5];
    const float* msg_Wh   = (const float*)d_in[6];
    const float* msg_We   = (const float*)d_in[7];
    const float* msg_b    = (const float*)d_in[8];
    const float* gru_Wih  = (const float*)d_in[9];
    const float* gru_Whh  = (const float*)d_in[10];
    const float* gru_bih  = (const float*)d_in[11];
    const float* gru_bhh  = (const float*)d_in[12];
    const float* lstm_Wih = (const float*)d_in[13];
    const float* lstm_Whh = (const float*)d_in[14];
    const float* lstm_bih = (const float*)d_in[15];
    const float* lstm_bhh = (const float*)d_in[16];
    const float* ro_W     = (const float*)d_in[17];
    const float* ro_b     = (const float*)d_in[18];
    const int*   nnum     = (const int*)d_in[19];
    float* out = (float*)d_out;

    float* hnode; cudaGetSymbolAddress((void**)&hnode, g_hnode);
    float* nh;    cudaGetSymbolAddress((void**)&nh,    g_nh);
    float* xg;    cudaGetSymbolAddress((void**)&xg,    g_xg);
    uint4* wA;    cudaGetSymbolAddress((void**)&wA,    g_wA4);
    float* gateA; cudaGetSymbolAddress((void**)&gateA, g_gateA);
    float* gateB; cudaGetSymbolAddress((void**)&gateB, g_gateB);

    static int smem_set = 0;
    if (!smem_set) {
        cudaFuncSetAttribute(edge0_k, cudaFuncAttributeMaxDynamicSharedMemorySize, SM_EDGE);
        cudaFuncSetAttribute(recon_k, cudaFuncAttributeMaxDynamicSharedMemorySize, SM_EDGE);
        cudaFuncSetAttribute(hgemm_k, cudaFuncAttributeMaxDynamicSharedMemorySize, SM_HG);
        cudaFuncSetAttribute(gigh_k,  cudaFuncAttributeMaxDynamicSharedMemorySize, SM_HG);
        smem_set = 1;
    }

    const int NTILE = 256 * 6;      // static grid; dead tiles exit early
    const int NCT   = NCOLS / 96;   // 64

    tr_node_k<<<(128 * NCOLS / 4) / 256, 256>>>(node);                       // 1
    prep_a_k<<<72, 256>>>(link_W1, msg_We, msg_Wh, wA);                      // 2
    prep_b_k<<<240, 256>>>(gru_Wih, gru_Whh, lstm_Wih, wA);                  // 3
    edge0_k<<<NTILE, 256, SM_EDGE>>>(edge, link_b1, link_W2, link_b2, msg_b, nnum, gateA);  // 4

    float* gbuf[2] = {gateA, gateB};
    for (int p = 0; p < 3; p++) {
        float* gin  = gbuf[p & 1];
        float* gout = gbuf[(p + 1) & 1];
        hgemm_k<<<dim3(NCT, 1), 256, SM_HG>>>(wA + 12288, hnode, nullptr, nullptr, nh, NCOLS); // 5
        if (p < 2)
            recon_k<<<NTILE, 256, SM_EDGE>>>(link_b1, link_W2, link_b2, nnum, gin, gout);      // 6
        mv_k<<<1024, 256>>>(nnum, gin);
        gigh_k<<<dim3(NCT, 6), 256, SM_HG>>>(wA);
        gru_k<<<(128 * NCOLS) / 256, 256>>>(nnum, gru_bih, gru_bhh);
    }

    hgemm_k<<<dim3(NCT, 4), 256, SM_HG>>>(wA + 55296, hnode, lstm_bih, lstm_bhh, xg, NCOLS);
    lstm_all_k<<<128, 192>>>(lstm_Whh);
    readout_k<<<96, 256>>>(ro_W, ro_b, nnum, out);
    (void)in_sizes; (void)n_in; (void)out_size;
}

// round 14
// speedup vs baseline: 1.8783x; 1.0595x over previous
#include <cuda_runtime.h>
#include <cuda_bf16.h>
#include <math.h>
#include <stdint.h>

// ------------ problem constants ------------
#define NFRM   256                  // B*T
#define ECOLS  147456               // NFRM * 576 edge columns
#define NCOLS  6144                 // NFRM * 24 node columns

// ------------ device scratch ------------
__device__ float g_edge_c[128 * ECOLS];   // compacted edge [d][f*576 + c], padding zeroed
__device__ float g_epre  [128 * ECOLS];   // msg_We @ edge + msg_b, COMPACT per frame
__device__ float g_gateA [ECOLS];         // gate double buffer (COMPACT per frame)
__device__ float g_gateB [ECOLS];
__device__ float g_node0 [128 * NCOLS];
__device__ float g_hnode [128 * NCOLS];
__device__ float g_nh    [128 * NCOLS];
__device__ float g_mv    [128 * NCOLS];
__device__ float g_gi    [384 * NCOLS];
__device__ float g_gh    [384 * NCOLS];
__device__ float g_xg    [512 * NCOLS];
__device__ float g_h     [2 * 128 * 192];
__device__ float g_hist  [128 * 6144];
__device__ unsigned g_cnt2[8];
__device__ unsigned g_sense2[8];
// HMMA A fragments: per m16 block 768 uint4 (24 kk * 32 lanes)
__device__ uint4 g_wA4[79872];

__device__ __forceinline__ float sigm(float x) { return 1.f / (1.f + expf(-x)); }

__device__ __forceinline__ void ffma2(unsigned long long& acc,
                                      unsigned long long a, unsigned long long b) {
    asm("fma.rn.f32x2 %0, %1, %2, %0;" : "+l"(acc) : "l"(a), "l"(b));
}
__device__ __forceinline__ unsigned long long pack2(float x, float y) {
    unsigned long long r;
    asm("mov.b64 %0, {%1, %2};" : "=l"(r) : "f"(x), "f"(y));
    return r;
}
__device__ __forceinline__ float2 unpack2(unsigned long long v) {
    float2 f;
    asm("mov.b64 {%0, %1}, %2;" : "=f"(f.x), "=f"(f.y) : "l"(v));
    return f;
}
__device__ __forceinline__ void split_bf(float x, __nv_bfloat16& h, __nv_bfloat16& l) {
    h = __float2bfloat16(x);
    l = __float2bfloat16(x - __bfloat162float(h));
}
__device__ __forceinline__ void split_pair(float x0, float x1, unsigned& hw, unsigned& lw) {
    __nv_bfloat16 h0, l0, h1, l1;
    split_bf(x0, h0, l0); split_bf(x1, h1, l1);
    hw = (unsigned)__bfloat16_as_ushort(h0) | ((unsigned)__bfloat16_as_ushort(h1) << 16);
    lw = (unsigned)__bfloat16_as_ushort(l0) | ((unsigned)__bfloat16_as_ushort(l1) << 16);
}
__device__ __forceinline__ uint32_t smem_to_u32(const void* p) {
    uint32_t a;
    asm("{ .reg .u64 t; cvta.to.shared.u64 t, %1; cvt.u32.u64 %0, t; }" : "=r"(a) : "l"(p));
    return a;
}

// ---- HMMA m16n8k16 bf16 ----
__device__ __forceinline__ void mma_bf16(float* c, uint32_t a0, uint32_t a1,
                                         uint32_t a2, uint32_t a3,
                                         uint32_t b0, uint32_t b1) {
    asm volatile(
        "mma.sync.aligned.m16n8k16.row.col.f32.bf16.bf16.f32 "
        "{%0,%1,%2,%3}, {%4,%5,%6,%7}, {%8,%9}, {%0,%1,%2,%3};"
        : "+f"(c[0]), "+f"(c[1]), "+f"(c[2]), "+f"(c[3])
        : "r"(a0), "r"(a1), "r"(a2), "r"(a3), "r"(b0), "r"(b1));
}

#define BPITCH_W  132       // 32-bit words per B row
#define BPITCH_B  528
#define SNH_OFF   50688     // float[128*24]
#define SG_OFF    62976     // float[96]
#define SRED_OFF  63360     // float[8][52]
#define SM_EDGE   66688
#define SM_HG     50688

// ------------ compact_edge: gather dense edge into per-frame compact layout ------------
// grid 2048: f = blk>>3, dg = blk&7 (16 d rows each). Zero-pads to 96-tile boundary.
__global__ void __launch_bounds__(256) compact_edge_k(const float* __restrict__ edge,
                                                      const int* __restrict__ nnum)
{
    __shared__ int sidx[576];
    int f = blockIdx.x >> 3, dg = blockIdx.x & 7;
    int cnt = nnum[f]; int NV = cnt * cnt;
    int NVp = ((NV + 95) / 96) * 96; if (NVp > 576) NVp = 576;
    int tid = threadIdx.x;
    for (int c = tid; c < NV; c += 256) {
        int v = c / cnt;
        sidx[c] = v * 24 + (c - v * cnt);
    }
    __syncthreads();
    int tot = 16 * NVp;
    for (int i = tid; i < tot; i += 256) {
        int dl = i / NVp, c = i - dl * NVp;
        int d = dg * 16 + dl;
        float val = 0.f;
        if (c < NV) val = edge[(size_t)f * 73728 + d * 576 + sidx[c]];
        g_edge_c[(size_t)d * ECOLS + f * 576 + c] = val;
    }
}

// ------------ prep: pack split-bf16 W into HMMA A-frag layout ------------
__device__ __forceinline__ void prep_one(const float* __restrict__ W, uint4* __restrict__ out,
                                         int gidx)
{
    int mblk = gidx / 768;
    int rem  = gidx - mblk * 768;
    int kk   = rem >> 5;
    int lane = rem & 31;
    int g = lane >> 2, t = lane & 3;
    unsigned regs[4];
#pragma unroll
    for (int r = 0; r < 4; r++) {
        int row = mblk * 16 + g + ((r & 1) ? 8 : 0);
        int k0  = kk * 16 + t * 2 + ((r & 2) ? 8 : 0);
        unsigned pk = 0;
#pragma unroll
        for (int e = 0; e < 2; e++) {
            int ks = k0 + e;
            int region = ks >> 7;
            int kloc = ks & 127;
            float w = W[row * 128 + kloc];
            __nv_bfloat16 h, l; split_bf(w, h, l);
            __nv_bfloat16 b = (region < 2) ? h : l;
            pk |= (unsigned)__bfloat16_as_ushort(b) << (e * 16);
        }
        regs[r] = pk;
    }
    out[gidx] = make_uint4(regs[0], regs[1], regs[2], regs[3]);
}

__global__ void __launch_bounds__(256) prep_a_k(const float* __restrict__ w1,
                                                const float* __restrict__ we,
                                                const float* __restrict__ wh,
                                                uint4* __restrict__ out)
{
    int b = blockIdx.x;
    if (b < 24)      prep_one(w1, out,          b * 256 + threadIdx.x);
    else if (b < 48) prep_one(we, out + 6144,  (b - 24) * 256 + threadIdx.x);
    else             prep_one(wh, out + 12288, (b - 48) * 256 + threadIdx.x);
}
__global__ void __launch_bounds__(256) prep_b_k(const float* __restrict__ wih,
                                                const float* __restrict__ whh,
                                                const float* __restrict__ lih,
                                                uint4* __restrict__ out)
{
    int b = blockIdx.x;
    if (b < 72)       prep_one(wih, out + 18432,  b * 256 + threadIdx.x);
    else if (b < 144) prep_one(whh, out + 36864, (b - 72) * 256 + threadIdx.x);
    else              prep_one(lih, out + 55296, (b - 144) * 256 + threadIdx.x);
}

// ------------ warp GEMM m32 x n48, A-hi dedup (two-phase), unroll-4 ------------
__device__ __forceinline__ void gemm_m32(float c[2][6][4], const uint4* __restrict__ A4,
                                         uint32_t sbAddr, int lane, int nh)
{
    int midx = lane >> 3, row = lane & 7;
    uint32_t base0 = sbAddr +
        (uint32_t)((nh * 48 + ((midx >> 1) << 3) + row) * BPITCH_B + (midx & 1) * 16);
#pragma unroll
    for (int mb = 0; mb < 2; mb++)
#pragma unroll
        for (int nt = 0; nt < 6; nt++)
#pragma unroll
            for (int r = 0; r < 4; r++) c[mb][nt][r] = 0.f;

#pragma unroll 4
    for (int kk2 = 0; kk2 < 8; kk2++) {
        uint4 a0 = A4[kk2 * 32 + lane];
        uint4 a1 = A4[768 + kk2 * 32 + lane];
        uint32_t r[12];
#pragma unroll
        for (int j2 = 0; j2 < 3; j2++) {
            asm volatile("ldmatrix.sync.aligned.m8n8.x4.shared.b16 {%0,%1,%2,%3}, [%4];"
                         : "=r"(r[4 * j2]), "=r"(r[4 * j2 + 1]),
                           "=r"(r[4 * j2 + 2]), "=r"(r[4 * j2 + 3])
                         : "r"(base0 + (uint32_t)(j2 * 16 * BPITCH_B + kk2 * 32)));
        }
#pragma unroll
        for (int j2 = 0; j2 < 3; j2++) {
            mma_bf16(c[0][2 * j2],     a0.x, a0.y, a0.z, a0.w, r[4 * j2],     r[4 * j2 + 1]);
            mma_bf16(c[0][2 * j2 + 1], a0.x, a0.y, a0.z, a0.w, r[4 * j2 + 2], r[4 * j2 + 3]);
            mma_bf16(c[1][2 * j2],     a1.x, a1.y, a1.z, a1.w, r[4 * j2],     r[4 * j2 + 1]);
            mma_bf16(c[1][2 * j2 + 1], a1.x, a1.y, a1.z, a1.w, r[4 * j2 + 2], r[4 * j2 + 3]);
        }
#pragma unroll
        for (int j2 = 0; j2 < 3; j2++) {
            asm volatile("ldmatrix.sync.aligned.m8n8.x4.shared.b16 {%0,%1,%2,%3}, [%4];"
                         : "=r"(r[4 * j2]), "=r"(r[4 * j2 + 1]),
                           "=r"(r[4 * j2 + 2]), "=r"(r[4 * j2 + 3])
                         : "r"(base0 + (uint32_t)(j2 * 16 * BPITCH_B + (kk2 + 8) * 32)));
        }
#pragma unroll
        for (int j2 = 0; j2 < 3; j2++) {
            mma_bf16(c[0][2 * j2],     a0.x, a0.y, a0.z, a0.w, r[4 * j2],     r[4 * j2 + 1]);
            mma_bf16(c[0][2 * j2 + 1], a0.x, a0.y, a0.z, a0.w, r[4 * j2 + 2], r[4 * j2 + 3]);
            mma_bf16(c[1][2 * j2],     a1.x, a1.y, a1.z, a1.w, r[4 * j2],     r[4 * j2 + 1]);
            mma_bf16(c[1][2 * j2 + 1], a1.x, a1.y, a1.z, a1.w, r[4 * j2 + 2], r[4 * j2 + 3]);
        }
    }
#pragma unroll 4
    for (int kk2 = 0; kk2 < 8; kk2++) {
        uint4 a0 = A4[(16 + kk2) * 32 + lane];
        uint4 a1 = A4[768 + (16 + kk2) * 32 + lane];
        uint32_t r[12];
#pragma unroll
        for (int j2 = 0; j2 < 3; j2++) {
            asm volatile("ldmatrix.sync.aligned.m8n8.x4.shared.b16 {%0,%1,%2,%3}, [%4];"
                         : "=r"(r[4 * j2]), "=r"(r[4 * j2 + 1]),
                           "=r"(r[4 * j2 + 2]), "=r"(r[4 * j2 + 3])
                         : "r"(base0 + (uint32_t)(j2 * 16 * BPITCH_B + kk2 * 32)));
        }
#pragma unroll
        for (int j2 = 0; j2 < 3; j2++) {
            mma_bf16(c[0][2 * j2],     a0.x, a0.y, a0.z, a0.w, r[4 * j2],     r[4 * j2 + 1]);
            mma_bf16(c[0][2 * j2 + 1], a0.x, a0.y, a0.z, a0.w, r[4 * j2 + 2], r[4 * j2 + 3]);
            mma_bf16(c[1][2 * j2],     a1.x, a1.y, a1.z, a1.w, r[4 * j2],     r[4 * j2 + 1]);
            mma_bf16(c[1][2 * j2 + 1], a1.x, a1.y, a1.z, a1.w, r[4 * j2 + 2], r[4 * j2 + 3]);
        }
    }
}

// ------------ gate epilogue (compact: no mask needed) ------------
__device__ __forceinline__ void gate_epi32(float c[2][6][4], char* smem,
                                           const float* __restrict__ lb1,
                                           const float* __restrict__ W2,
                                           const float* __restrict__ b2p,
                                           float* __restrict__ gate_out, int base)
{
    int tid = threadIdx.x;
    int w = tid >> 5, lane = tid & 31;
    int mp = w & 3;
    int g = lane >> 2, t = lane & 3;
    float* sRed = (float*)(smem + SRED_OFF);   // [8][52]

    float p0[6], p1[6];
#pragma unroll
    for (int j = 0; j < 6; j++) { p0[j] = 0.f; p1[j] = 0.f; }
#pragma unroll
    for (int mb = 0; mb < 2; mb++) {
        int r0 = mp * 32 + mb * 16 + g;
        float bb0 = lb1[r0], bb8 = lb1[r0 + 8];
        float w0 = W2[r0], w8 = W2[r0 + 8];
#pragma unroll
        for (int j = 0; j < 6; j++) {
            p0[j] += fmaxf(c[mb][j][0] + bb0, 0.f) * w0 + fmaxf(c[mb][j][2] + bb8, 0.f) * w8;
            p1[j] += fmaxf(c[mb][j][1] + bb0, 0.f) * w0 + fmaxf(c[mb][j][3] + bb8, 0.f) * w8;
        }
    }
#pragma unroll
    for (int j = 0; j < 6; j++) {
#pragma unroll
        for (int m = 4; m <= 16; m <<= 1) {
            p0[j] += __shfl_xor_sync(0xffffffffu, p0[j], m);
            p1[j] += __shfl_xor_sync(0xffffffffu, p1[j], m);
        }
    }
    if (g == 0) {
#pragma unroll
        for (int j = 0; j < 6; j++) {
            sRed[w * 52 + j * 8 + t * 2]     = p0[j];
            sRed[w * 52 + j * 8 + t * 2 + 1] = p1[j];
        }
    }
    __syncthreads();
    if (tid < 96) {
        int nh2 = tid / 48, nn = tid - nh2 * 48;
        float s = sRed[(nh2 * 4 + 0) * 52 + nn] + sRed[(nh2 * 4 + 1) * 52 + nn]
                + sRed[(nh2 * 4 + 2) * 52 + nn] + sRed[(nh2 * 4 + 3) * 52 + nn];
        gate_out[base + tid] = sigm(s + b2p[0]);
    }
}

// ------------ edge0_k: layer-0 gate + epre over COMPACT columns ------------
__global__ void __launch_bounds__(256, 3) edge0_k(const float* __restrict__ lb1,
                                                  const float* __restrict__ W2,
                                                  const float* __restrict__ b2p,
                                                  const float* __restrict__ msg_b,
                                                  const int* __restrict__ nnum,
                                                  float* __restrict__ gate_out)
{
    extern __shared__ char smem[];
    uint32_t sbAddr = smem_to_u32(smem);
    unsigned* sBw = (unsigned*)smem;
    int tid = threadIdx.x;
    int bx = blockIdx.x;
    int f = bx / 6; int tt = bx - f * 6;
    int cnt = nnum[f]; int NV = cnt * cnt;
    int cb = tt * 96;
    if (cb >= NV) return;                     // uniform early exit
    int base = f * 576 + cb;

    // B conversion from compact edge (vectorized; padding already zeroed)
    {
        int q = tid >> 6, dp = tid & 63;
        const float* s0 = g_edge_c + (size_t)(2 * dp) * ECOLS + base + q * 24;
        const float* s1 = s0 + ECOLS;
        for (int i = 0; i < 24; i += 4) {
            float4 x0 = *(const float4*)(s0 + i);
            float4 x1 = *(const float4*)(s1 + i);
            float a0[4] = {x0.x, x0.y, x0.z, x0.w};
            float a1[4] = {x1.x, x1.y, x1.z, x1.w};
#pragma unroll
            for (int j = 0; j < 4; j++) {
                int n = q * 24 + i + j;
                unsigned hw, lw; split_pair(a0[j], a1[j], hw, lw);
                sBw[n * BPITCH_W + dp]      = hw;
                sBw[n * BPITCH_W + 64 + dp] = lw;
            }
        }
    }
    __syncthreads();

    int w = tid >> 5, lane = tid & 31;
    int mp = w & 3, nh = w >> 2;
    int g = lane >> 2, t = lane & 3;
    float c[2][6][4];

    // pass 1: link_W1 -> gate0
    gemm_m32(c, g_wA4 + (2 * mp) * 768, sbAddr, lane, nh);
    gate_epi32(c, smem, lb1, W2, b2p, gate_out, base);
    __syncthreads();

    // pass 2: msg_We -> epre
    gemm_m32(c, g_wA4 + 6144 + (2 * mp) * 768, sbAddr, lane, nh);
#pragma unroll
    for (int mb = 0; mb < 2; mb++) {
        int r0 = mp * 32 + mb * 16 + g;
        float mb0 = msg_b[r0], mb8 = msg_b[r0 + 8];
#pragma unroll
        for (int j = 0; j < 6; j++) {
            int col = base + nh * 48 + j * 8 + t * 2;
            *(float2*)(g_epre + (size_t)r0 * ECOLS + col) =
                make_float2(c[mb][j][0] + mb0, c[mb][j][1] + mb0);
            *(float2*)(g_epre + (size_t)(r0 + 8) * ECOLS + col) =
                make_float2(c[mb][j][2] + mb8, c[mb][j][3] + mb8);
        }
    }
}

// ------------ recon_k: gate_{p+1} from reconstruction (COMPACT, double-buffered gate) ------------
__global__ void __launch_bounds__(256, 3) recon_k(const float* __restrict__ lb1,
                                                  const float* __restrict__ W2,
                                                  const float* __restrict__ b2p,
                                                  const int* __restrict__ nnum,
                                                  const float* __restrict__ gate_in,
                                                  float* __restrict__ gate_out)
{
    extern __shared__ char smem[];
    uint32_t sbAddr = smem_to_u32(smem);
    unsigned* sBw = (unsigned*)smem;
    float* snh = (float*)(smem + SNH_OFF);   // [128][24]
    float* sg  = (float*)(smem + SG_OFF);    // [96]
    __shared__ int ssw[96];
    int tid = threadIdx.x;
    int bx = blockIdx.x;
    int f = bx / 6; int tt = bx - f * 6;
    int cnt = nnum[f]; int NV = cnt * cnt;
    int cb = tt * 96;
    if (cb >= NV) return;
    int base = f * 576 + cb;

    for (int i = tid; i < 3072; i += 256) {
        int d = i / 24, w = i - d * 24;
        snh[d * 24 + w] = g_nh[d * NCOLS + f * 24 + w];
    }
    if (tid < 96) {
        sg[tid] = gate_in[base + tid];
        int c = cb + tid;
        int v = c / cnt;
        ssw[tid] = c - v * cnt;
    }
    __syncthreads();

    // B conversion: h_edge = gate * relu(nh + epre) on compact columns
    {
        int q = tid >> 6, dp = tid & 63;
        int d0 = 2 * dp, d1 = d0 + 1;
        const float* s0 = g_epre + (size_t)d0 * ECOLS + base + q * 24;
        const float* s1 = s0 + ECOLS;
        int n0 = q * 24;
        for (int i = 0; i < 24; i += 4) {
            float4 x0 = *(const float4*)(s0 + i);
            float4 x1 = *(const float4*)(s1 + i);
            float a0[4] = {x0.x, x0.y, x0.z, x0.w};
            float a1[4] = {x1.x, x1.y, x1.z, x1.w};
#pragma unroll
            for (int j = 0; j < 4; j++) {
                int nn = n0 + i + j;
                float v0 = 0.f, v1 = 0.f;
                if (cb + nn < NV) {
                    int w = ssw[nn];
                    float gv = sg[nn];
                    v0 = gv * fmaxf(snh[d0 * 24 + w] + a0[j], 0.f);
                    v1 = gv * fmaxf(snh[d1 * 24 + w] + a1[j], 0.f);
                }
                unsigned hw, lw; split_pair(v0, v1, hw, lw);
                sBw[nn * BPITCH_W + dp]      = hw;
                sBw[nn * BPITCH_W + 64 + dp] = lw;
            }
        }
    }
    __syncthreads();

    int w = tid >> 5, lane = tid & 31;
    int mp = w & 3, nh = w >> 2;
    float c[2][6][4];
    gemm_m32(c, g_wA4 + (2 * mp) * 768, sbAddr, lane, nh);
    gate_epi32(c, smem, lb1, W2, b2p, gate_out, base);
}

// ------------ mv_k: m_v[d][v] = sum_{w<cnt} gate_p[c]*relu(nh+epre[c]) ------------
__global__ void __launch_bounds__(256) mv_k(const int* __restrict__ nnum,
                                            const float* __restrict__ gate_in)
{
    __shared__ float snh[32 * 24];
    __shared__ float sg[576];
    int f = blockIdx.x >> 2, dg = blockIdx.x & 3;
    int cnt = nnum[f];
    int NV = cnt * cnt;
    int tid = threadIdx.x;
    for (int i = tid; i < 768; i += 256) {
        int d = i / 24, w = i - d * 24;
        snh[i] = g_nh[(dg * 32 + d) * NCOLS + f * 24 + w];
    }
    for (int i = tid; i < NV; i += 256) sg[i] = gate_in[f * 576 + i];
    __syncthreads();

    for (int p = tid; p < 768; p += 256) {
        int dl = p / 24, v = p - dl * 24;
        int d = dg * 32 + dl;
        float s = 0.f;
        if (v < cnt) {
            const float* ep = g_epre + (size_t)d * ECOLS + f * 576 + v * cnt;
            const float* gp = sg + v * cnt;
            const float* np = snh + dl * 24;
            for (int w = 0; w < cnt; w++)
                s += gp[w] * fmaxf(np[w] + ep[w], 0.f);
        }
        g_mv[d * NCOLS + f * 24 + v] = s;
    }
}

// ------------ shared hgemm body (m32 x n48 tiling) ------------
__device__ __forceinline__ void hgemm_body(const uint4* __restrict__ Afrag, int mrowblk,
                                           const float* __restrict__ X,
                                           const float* __restrict__ bias,
                                           const float* __restrict__ bias2,
                                           float* __restrict__ Y, int cols, int c0,
                                           char* smem, uint32_t sbAddr)
{
    unsigned* sBw = (unsigned*)smem;
    int tid = threadIdx.x;
    {
        int q = tid >> 6, dp = tid & 63;
        const float* s0 = X + (size_t)(2 * dp) * cols + c0 + q * 24;
        const float* s1 = s0 + cols;
        for (int i = 0; i < 24; i += 4) {
            float4 x0 = *(const float4*)(s0 + i);
            float4 x1 = *(const float4*)(s1 + i);
            float a0[4] = {x0.x, x0.y, x0.z, x0.w};
            float a1[4] = {x1.x, x1.y, x1.z, x1.w};
#pragma unroll
            for (int j = 0; j < 4; j++) {
                int n = q * 24 + i + j;
                unsigned hw, lw; split_pair(a0[j], a1[j], hw, lw);
                sBw[n * BPITCH_W + dp]      = hw;
                sBw[n * BPITCH_W + 64 + dp] = lw;
            }
        }
    }
    __syncthreads();

    int w = tid >> 5, lane = tid & 31;
    int mp = w & 3, nh = w >> 2;
    int g = lane >> 2, t = lane & 3;
    float c[2][6][4];
    gemm_m32(c, Afrag + (mrowblk * 8 + 2 * mp) * 768, sbAddr, lane, nh);

#pragma unroll
    for (int mb = 0; mb < 2; mb++) {
        int r0 = mrowblk * 128 + mp * 32 + mb * 16 + g;
        float b0v = (bias ? bias[r0] : 0.f) + (bias2 ? bias2[r0] : 0.f);
        float b8v = (bias ? bias[r0 + 8] : 0.f) + (bias2 ? bias2[r0 + 8] : 0.f);
#pragma unroll
        for (int j = 0; j < 6; j++) {
            int col = c0 + nh * 48 + j * 8 + t * 2;
            *(float2*)(Y + (size_t)r0 * cols + col) =
                make_float2(c[mb][j][0] + b0v, c[mb][j][1] + b0v);
            *(float2*)(Y + (size_t)(r0 + 8) * cols + col) =
                make_float2(c[mb][j][2] + b8v, c[mb][j][3] + b8v);
        }
    }
}

__global__ void __launch_bounds__(256, 3) hgemm_k(const uint4* __restrict__ Afrag,
                                                  const float* __restrict__ X,
                                                  const float* __restrict__ bias,
                                                  const float* __restrict__ bias2,
                                                  float* __restrict__ Y, int cols)
{
    extern __shared__ char smem[];
    hgemm_body(Afrag, blockIdx.y, X, bias, bias2, Y, cols, blockIdx.x * 96,
               smem, smem_to_u32(smem));
}

__global__ void __launch_bounds__(256, 3) gigh_k(const uint4* __restrict__ wA)
{
    extern __shared__ char smem[];
    int by = blockIdx.y;
    if (by < 3)
        hgemm_body(wA + 18432, by, g_mv, nullptr, nullptr, g_gi, NCOLS,
                   blockIdx.x * 96, smem, smem_to_u32(smem));
    else
        hgemm_body(wA + 36864, by - 3, g_hnode, nullptr, nullptr, g_gh, NCOLS,
                   blockIdx.x * 96, smem, smem_to_u32(smem));
}

// ------------ node transpose ------------
__global__ void __launch_bounds__(256) tr_node_k(const float* __restrict__ in)
{
    int o4 = blockIdx.x * 256 + threadIdx.x;
    int d = o4 / 1536; int c4 = o4 - d * 1536;
    int f = c4 / 6;    int n4 = c4 - f * 6;
    float4 v = *(const float4*)(in + f * 3072 + d * 24 + n4 * 4);
    int dst = d * NCOLS + f * 24 + n4 * 4;
    *(float4*)(g_node0 + dst) = v;
    *(float4*)(g_hnode + dst) = v;
}

// ------------ GRU elementwise ------------
__global__ void __launch_bounds__(256) gru_k(const int* __restrict__ nnum,
                                             const float* __restrict__ bih,
                                             const float* __restrict__ bhh)
{
    int idx = blockIdx.x * 256 + threadIdx.x;
    int j = idx / NCOLS; int col = idx - j * NCOLS;
    float gir = g_gi[j * NCOLS + col]         + bih[j];
    float giz = g_gi[(128 + j) * NCOLS + col] + bih[128 + j];
    float gin = g_gi[(256 + j) * NCOLS + col] + bih[256 + j];
    float ghr = g_gh[j * NCOLS + col]         + bhh[j];
    float ghz = g_gh[(128 + j) * NCOLS + col] + bhh[128 + j];
    float ghn = g_gh[(256 + j) * NCOLS + col] + bhh[256 + j];
    float r = sigm(gir + ghr);
    float z = sigm(giz + ghz);
    float n2 = tanhf(gin + r * ghn);
    float h = g_hnode[idx];
    float hn = (1.f - z) * n2 + z * h;
    int f = col / 24; int n = col - f * 24;
    g_hnode[idx] = (n < nnum[f]) ? hn : g_node0[idx];
}

// ------------ persistent LSTM ------------
__device__ __forceinline__ void group_barrier(int b, unsigned want)
{
    __threadfence();
    __syncthreads();
    if (threadIdx.x == 0) {
        unsigned tk = atomicAdd(&g_cnt2[b], 1u);
        if (tk == 15u) {
            g_cnt2[b] = 0;
            __threadfence();
            atomicExch(&g_sense2[b], want);
        } else {
            unsigned v;
            do {
                asm volatile("ld.acquire.gpu.u32 %0, [%1];" : "=r"(v) : "l"(&g_sense2[b]));
            } while (v != want);
        }
    }
    __syncthreads();
}

__global__ void __launch_bounds__(192) lstm_all_k(const float* __restrict__ Whh)
{
    __shared__ __align__(16) float sWt[128][36];
    __shared__ float sH[128][25];
    __shared__ float sG[32][25];
    int tid = threadIdx.x;
    int rg = blockIdx.x & 15, b = blockIdx.x >> 4;

    for (int i = tid; i < 4096; i += 192) {
        int r = i >> 7, k = i & 127;
        int jg = (r >> 3) * 128 + rg * 8 + (r & 7);
        sWt[k][r] = Whh[jg * 128 + k];
    }
    int tr = tid & 7, tc = tid >> 3;
    int hh = tid / 24, nn = tid - hh * 24;
    int jrow = rg * 8 + hh;
    int scol = b * 24 + nn;
    float creg = 0.f;
    unsigned phase = 0;

    for (int t = 0; t < 32; t++) {
        if (t == 0) {
            for (int i = tid; i < 3200; i += 192) (&sH[0][0])[i] = 0.f;
            __syncthreads();
        } else {
            phase++;
            group_barrier(b, phase & 1u);
            const float* hb = g_h + ((t + 1) & 1) * 24576;
            for (int i = tid; i < 3072; i += 192) {
                int j = i / 24, n2 = i - j * 24;
                sH[j][n2] = __ldcg(hb + j * 192 + b * 24 + n2);
            }
            __syncthreads();
        }

        unsigned long long acc0 = 0ull, acc1 = 0ull;
#pragma unroll 8
        for (int k = 0; k < 128; k++) {
            ulonglong2 av = *(const ulonglong2*)&sWt[k][tr * 4];
            float bv = sH[k][tc];
            unsigned long long bs = pack2(bv, bv);
            ffma2(acc0, av.x, bs);
            ffma2(acc1, av.y, bs);
        }
        float2 u0 = unpack2(acc0), u1 = unpack2(acc1);
        sG[tr * 4 + 0][tc] = u0.x; sG[tr * 4 + 1][tc] = u0.y;
        sG[tr * 4 + 2][tc] = u1.x; sG[tr * 4 + 3][tc] = u1.y;
        __syncthreads();

        int colx = (b * 32 + t) * 24 + nn;
        float ig = sG[hh][nn]      + g_xg[(      jrow) * NCOLS + colx];
        float fg = sG[8 + hh][nn]  + g_xg[(128 + jrow) * NCOLS + colx];
        float gg = sG[16 + hh][nn] + g_xg[(256 + jrow) * NCOLS + colx];
        float og = sG[24 + hh][nn] + g_xg[(384 + jrow) * NCOLS + colx];
        creg = sigm(fg) * creg + sigm(ig) * tanhf(gg);
        float hnew = sigm(og) * tanhf(creg);
        __stcg(g_h + (t & 1) * 24576 + jrow * 192 + scol, hnew);
        g_hist[jrow * 6144 + t * 192 + scol] = hnew;
        __syncthreads();
    }
    phase++;
    group_barrier(b, phase & 1u);
}

// ------------ readout ------------
__global__ void __launch_bounds__(256) readout_k(const float* __restrict__ roW,
                                                 const float* __restrict__ rob,
                                                 const int* __restrict__ nnum,
                                                 float* __restrict__ out)
{
    __shared__ float sH[128][65];
    __shared__ float sRo[6][128];
    __shared__ float sRob[6];
    int tid = threadIdx.x;
    int c0 = blockIdx.x * 64;
    for (int i = tid; i < 8192; i += 256) {
        int j = i >> 6, cc = i & 63;
        sH[j][cc] = g_hist[j * 6144 + c0 + cc];
    }
    for (int i = tid; i < 768; i += 256) sRo[i >> 7][i & 127] = roW[i];
    if (tid < 6) sRob[tid] = rob[tid];
    __syncthreads();
    for (int e = tid; e < 384; e += 256) {
        int cc = e / 6, c = e - cc * 6;
        float s = 0.f;
#pragma unroll 8
        for (int j = 0; j < 128; j++) s += sRo[c][j] * sH[j][cc];
        int ct = c0 + cc;
        int t = ct / 192; int srem = ct - t * 192;
        int b = srem / 24; int n = srem - b * 24;
        int f = b * 32 + t;
        out[(f * 24 + n) * 6 + c] = (n < nnum[f]) ? (s + sRob[c]) : 0.f;
    }
}

// ------------ host launcher ------------
extern "C" void kernel_launch(void* const* d_in, const int* in_sizes, int n_in,
                              void* d_out, int out_size)
{
    const float* node     = (const float*)d_in[0];
    const float* edge     = (const float*)d_in[1];
    const float* link_W1  = (const float*)d_in[2];
    const float* link_b1  = (const float*)d_in[3];
    const float* link_W2  = (const float*)d_in[4];
    const float* link_b2  = (const float*)d_in[5];
    const float* msg_Wh   = (const float*)d_in[6];
    const float* msg_We   = (const float*)d_in[7];
    const float* msg_b    = (const float*)d_in[8];
    const float* gru_Wih  = (const float*)d_in[9];
    const float* gru_Whh  = (const float*)d_in[10];
    const float* gru_bih  = (const float*)d_in[11];
    const float* gru_bhh  = (const float*)d_in[12];
    const float* lstm_Wih = (const float*)d_in[13];
    const float* lstm_Whh = (const float*)d_in[14];
    const float* lstm_bih = (const float*)d_in[15];
    const float* lstm_bhh = (const float*)d_in[16];
    const float* ro_W     = (const float*)d_in[17];
    const float* ro_b     = (const float*)d_in[18];
    const int*   nnum     = (const int*)d_in[19];
    float* out = (float*)d_out;

    float* hnode; cudaGetSymbolAddress((void**)&hnode, g_hnode);
    float* nh;    cudaGetSymbolAddress((void**)&nh,    g_nh);
    float* xg;    cudaGetSymbolAddress((void**)&xg,    g_xg);
    uint4* wA;    cudaGetSymbolAddress((void**)&wA,    g_wA4);
    float* gateA; cudaGetSymbolAddress((void**)&gateA, g_gateA);
    float* gateB; cudaGetSymbolAddress((void**)&gateB, g_gateB);

    static int smem_set = 0;
    if (!smem_set) {
        cudaFuncSetAttribute(edge0_k, cudaFuncAttributeMaxDynamicSharedMemorySize, SM_EDGE);
        cudaFuncSetAttribute(recon_k, cudaFuncAttributeMaxDynamicSharedMemorySize, SM_EDGE);
        cudaFuncSetAttribute(hgemm_k, cudaFuncAttributeMaxDynamicSharedMemorySize, SM_HG);
        cudaFuncSetAttribute(gigh_k,  cudaFuncAttributeMaxDynamicSharedMemorySize, SM_HG);
        smem_set = 1;
    }

    const int NTILE = 256 * 6;      // static grid; dead tiles exit early
    const int NCT   = NCOLS / 96;   // 64

    tr_node_k<<<(128 * NCOLS / 4) / 256, 256>>>(node);                          // 1
    prep_a_k<<<72, 256>>>(link_W1, msg_We, msg_Wh, wA);                         // 2
    prep_b_k<<<240, 256>>>(gru_Wih, gru_Whh, lstm_Wih, wA);                     // 3
    compact_edge_k<<<2048, 256>>>(edge, nnum);                                  // 4
    // nh for layer 0 (depends only on node0) hoisted so edge0 lands in profile slot 6
    hgemm_k<<<dim3(NCT, 1), 256, SM_HG>>>(wA + 12288, hnode, nullptr, nullptr, nh, NCOLS); // 5
    edge0_k<<<NTILE, 256, SM_EDGE>>>(link_b1, link_W2, link_b2, msg_b, nnum, gateA);       // 6

    float* gbuf[2] = {gateA, gateB};
    for (int p = 0; p < 3; p++) {
        float* gin  = gbuf[p & 1];
        float* gout = gbuf[(p + 1) & 1];
        if (p > 0)
            hgemm_k<<<dim3(NCT, 1), 256, SM_HG>>>(wA + 12288, hnode, nullptr, nullptr, nh, NCOLS);
        if (p < 2)
            recon_k<<<NTILE, 256, SM_EDGE>>>(link_b1, link_W2, link_b2, nnum, gin, gout);
        mv_k<<<1024, 256>>>(nnum, gin);
        gigh_k<<<dim3(NCT, 6), 256, SM_HG>>>(wA);
        gru_k<<<(128 * NCOLS) / 256, 256>>>(nnum, gru_bih, gru_bhh);
    }

    hgemm_k<<<dim3(NCT, 4), 256, SM_HG>>>(wA + 55296, hnode, lstm_bih, lstm_bhh, xg, NCOLS);
    lstm_all_k<<<128, 192>>>(lstm_Whh);
    readout_k<<<96, 256>>>(ro_W, ro_b, nnum, out);
    (void)in_sizes; (void)n_in; (void)out_size;
}

// round 15
// speedup vs baseline: 1.9010x; 1.0120x over previous
#include <cuda_runtime.h>
#include <cuda_bf16.h>
#include <math.h>
#include <stdint.h>

// ------------ problem constants ------------
#define NFRM   256                  // B*T
#define ECOLS  147456               // NFRM * 576 edge columns
#define NCOLS  6144                 // NFRM * 24 node columns

// ------------ device scratch ------------
__device__ float g_edge_c[128 * ECOLS];   // compacted edge [d][f*576 + c], padding zeroed
__device__ float g_epre  [128 * ECOLS];   // msg_We @ edge + msg_b, COMPACT per frame
__device__ float g_gateA [ECOLS];
__device__ float g_gateB [ECOLS];
__device__ float g_node0 [128 * NCOLS];
__device__ float g_hnode [128 * NCOLS];   // dense hnode (LSTM path needs all columns)
__device__ float g_hnC   [128 * NCOLS];   // COMPACT hnode (node-GEMM path)
__device__ float g_nh    [128 * NCOLS];   // COMPACT
__device__ float g_mv    [128 * NCOLS];   // COMPACT
__device__ float g_gi    [384 * NCOLS];   // COMPACT
__device__ float g_gh    [384 * NCOLS];   // COMPACT
__device__ float g_xg    [512 * NCOLS];   // dense
__device__ float g_h     [2 * 128 * 192];
__device__ float g_hist  [128 * 6144];
__device__ int   g_cpre  [257];
__device__ int   g_colf  [NCOLS];
__device__ int   g_nccg  [1];
__device__ unsigned g_cnt2[8];
__device__ unsigned g_sense2[8];
__device__ uint4 g_wA4[79872];

__device__ __forceinline__ float sigm(float x) { return 1.f / (1.f + expf(-x)); }

__device__ __forceinline__ void ffma2(unsigned long long& acc,
                                      unsigned long long a, unsigned long long b) {
    asm("fma.rn.f32x2 %0, %1, %2, %0;" : "+l"(acc) : "l"(a), "l"(b));
}
__device__ __forceinline__ unsigned long long pack2(float x, float y) {
    unsigned long long r;
    asm("mov.b64 %0, {%1, %2};" : "=l"(r) : "f"(x), "f"(y));
    return r;
}
__device__ __forceinline__ float2 unpack2(unsigned long long v) {
    float2 f;
    asm("mov.b64 {%0, %1}, %2;" : "=f"(f.x), "=f"(f.y) : "l"(v));
    return f;
}
__device__ __forceinline__ void split_bf(float x, __nv_bfloat16& h, __nv_bfloat16& l) {
    h = __float2bfloat16(x);
    l = __float2bfloat16(x - __bfloat162float(h));
}
__device__ __forceinline__ void split_pair(float x0, float x1, unsigned& hw, unsigned& lw) {
    __nv_bfloat16 h0, l0, h1, l1;
    split_bf(x0, h0, l0); split_bf(x1, h1, l1);
    hw = (unsigned)__bfloat16_as_ushort(h0) | ((unsigned)__bfloat16_as_ushort(h1) << 16);
    lw = (unsigned)__bfloat16_as_ushort(l0) | ((unsigned)__bfloat16_as_ushort(l1) << 16);
}
__device__ __forceinline__ uint32_t smem_to_u32(const void* p) {
    uint32_t a;
    asm("{ .reg .u64 t; cvta.to.shared.u64 t, %1; cvt.u32.u64 %0, t; }" : "=r"(a) : "l"(p));
    return a;
}

// ---- HMMA m16n8k16 bf16 ----
__device__ __forceinline__ void mma_bf16(float* c, uint32_t a0, uint32_t a1,
                                         uint32_t a2, uint32_t a3,
                                         uint32_t b0, uint32_t b1) {
    asm volatile(
        "mma.sync.aligned.m16n8k16.row.col.f32.bf16.bf16.f32 "
        "{%0,%1,%2,%3}, {%4,%5,%6,%7}, {%8,%9}, {%0,%1,%2,%3};"
        : "+f"(c[0]), "+f"(c[1]), "+f"(c[2]), "+f"(c[3])
        : "r"(a0), "r"(a1), "r"(a2), "r"(a3), "r"(b0), "r"(b1));
}

#define BPITCH_W  132
#define BPITCH_B  528
#define SNH_OFF   50688     // float[128*24]
#define SG_OFF    62976     // float[96]
#define SRED_OFF  63360     // float[8][52]
#define SM_EDGE   66688
#define SM_HG     50688

// ------------ prefix: per-frame compact offsets + inverse column map ------------
__global__ void __launch_bounds__(256) prefix_k(const int* __restrict__ nnum)
{
    __shared__ int sc[256];
    int f = threadIdx.x;
    int c = nnum[f];
    sc[f] = c;
    __syncthreads();
    if (f == 0) {
        int acc = 0;
        for (int i = 0; i < 256; i++) { g_cpre[i] = acc; acc += sc[i]; }
        g_cpre[256] = acc;
        g_nccg[0] = acc;
    }
    __syncthreads();
    int base = g_cpre[f];
    for (int n = 0; n < c; n++) g_colf[base + n] = f * 24 + n;
}

// ------------ compact_edge ------------
__global__ void __launch_bounds__(256) compact_edge_k(const float* __restrict__ edge,
                                                      const int* __restrict__ nnum)
{
    __shared__ int sidx[576];
    int f = blockIdx.x >> 3, dg = blockIdx.x & 7;
    int cnt = nnum[f]; int NV = cnt * cnt;
    int NVp = ((NV + 95) / 96) * 96; if (NVp > 576) NVp = 576;
    int tid = threadIdx.x;
    for (int c = tid; c < NV; c += 256) {
        int v = c / cnt;
        sidx[c] = v * 24 + (c - v * cnt);
    }
    __syncthreads();
    int tot = 16 * NVp;
    for (int i = tid; i < tot; i += 256) {
        int dl = i / NVp, c = i - dl * NVp;
        int d = dg * 16 + dl;
        float val = 0.f;
        if (c < NV) val = edge[(size_t)f * 73728 + d * 576 + sidx[c]];
        g_edge_c[(size_t)d * ECOLS + f * 576 + c] = val;
    }
}

// ------------ prep ------------
__device__ __forceinline__ void prep_one(const float* __restrict__ W, uint4* __restrict__ out,
                                         int gidx)
{
    int mblk = gidx / 768;
    int rem  = gidx - mblk * 768;
    int kk   = rem >> 5;
    int lane = rem & 31;
    int g = lane >> 2, t = lane & 3;
    unsigned regs[4];
#pragma unroll
    for (int r = 0; r < 4; r++) {
        int row = mblk * 16 + g + ((r & 1) ? 8 : 0);
        int k0  = kk * 16 + t * 2 + ((r & 2) ? 8 : 0);
        unsigned pk = 0;
#pragma unroll
        for (int e = 0; e < 2; e++) {
            int ks = k0 + e;
            int region = ks >> 7;
            int kloc = ks & 127;
            float w = W[row * 128 + kloc];
            __nv_bfloat16 h, l; split_bf(w, h, l);
            __nv_bfloat16 b = (region < 2) ? h : l;
            pk |= (unsigned)__bfloat16_as_ushort(b) << (e * 16);
        }
        regs[r] = pk;
    }
    out[gidx] = make_uint4(regs[0], regs[1], regs[2], regs[3]);
}

__global__ void __launch_bounds__(256) prep_a_k(const float* __restrict__ w1,
                                                const float* __restrict__ we,
                                                const float* __restrict__ wh,
                                                uint4* __restrict__ out)
{
    int b = blockIdx.x;
    if (b < 24)      prep_one(w1, out,          b * 256 + threadIdx.x);
    else if (b < 48) prep_one(we, out + 6144,  (b - 24) * 256 + threadIdx.x);
    else             prep_one(wh, out + 12288, (b - 48) * 256 + threadIdx.x);
}
__global__ void __launch_bounds__(256) prep_b_k(const float* __restrict__ wih,
                                                const float* __restrict__ whh,
                                                const float* __restrict__ lih,
                                                uint4* __restrict__ out)
{
    int b = blockIdx.x;
    if (b < 72)       prep_one(wih, out + 18432,  b * 256 + threadIdx.x);
    else if (b < 144) prep_one(whh, out + 36864, (b - 72) * 256 + threadIdx.x);
    else              prep_one(lih, out + 55296, (b - 144) * 256 + threadIdx.x);
}

// ------------ warp GEMM m32 x n48 ------------
__device__ __forceinline__ void gemm_m32(float c[2][6][4], const uint4* __restrict__ A4,
                                         uint32_t sbAddr, int lane, int nh)
{
    int midx = lane >> 3, row = lane & 7;
    uint32_t base0 = sbAddr +
        (uint32_t)((nh * 48 + ((midx >> 1) << 3) + row) * BPITCH_B + (midx & 1) * 16);
#pragma unroll
    for (int mb = 0; mb < 2; mb++)
#pragma unroll
        for (int nt = 0; nt < 6; nt++)
#pragma unroll
            for (int r = 0; r < 4; r++) c[mb][nt][r] = 0.f;

#pragma unroll 4
    for (int kk2 = 0; kk2 < 8; kk2++) {
        uint4 a0 = A4[kk2 * 32 + lane];
        uint4 a1 = A4[768 + kk2 * 32 + lane];
        uint32_t r[12];
#pragma unroll
        for (int j2 = 0; j2 < 3; j2++) {
            asm volatile("ldmatrix.sync.aligned.m8n8.x4.shared.b16 {%0,%1,%2,%3}, [%4];"
                         : "=r"(r[4 * j2]), "=r"(r[4 * j2 + 1]),
                           "=r"(r[4 * j2 + 2]), "=r"(r[4 * j2 + 3])
                         : "r"(base0 + (uint32_t)(j2 * 16 * BPITCH_B + kk2 * 32)));
        }
#pragma unroll
        for (int j2 = 0; j2 < 3; j2++) {
            mma_bf16(c[0][2 * j2],     a0.x, a0.y, a0.z, a0.w, r[4 * j2],     r[4 * j2 + 1]);
            mma_bf16(c[0][2 * j2 + 1], a0.x, a0.y, a0.z, a0.w, r[4 * j2 + 2], r[4 * j2 + 3]);
            mma_bf16(c[1][2 * j2],     a1.x, a1.y, a1.z, a1.w, r[4 * j2],     r[4 * j2 + 1]);
            mma_bf16(c[1][2 * j2 + 1], a1.x, a1.y, a1.z, a1.w, r[4 * j2 + 2], r[4 * j2 + 3]);
        }
#pragma unroll
        for (int j2 = 0; j2 < 3; j2++) {
            asm volatile("ldmatrix.sync.aligned.m8n8.x4.shared.b16 {%0,%1,%2,%3}, [%4];"
                         : "=r"(r[4 * j2]), "=r"(r[4 * j2 + 1]),
                           "=r"(r[4 * j2 + 2]), "=r"(r[4 * j2 + 3])
                         : "r"(base0 + (uint32_t)(j2 * 16 * BPITCH_B + (kk2 + 8) * 32)));
        }
#pragma unroll
        for (int j2 = 0; j2 < 3; j2++) {
            mma_bf16(c[0][2 * j2],     a0.x, a0.y, a0.z, a0.w, r[4 * j2],     r[4 * j2 + 1]);
            mma_bf16(c[0][2 * j2 + 1], a0.x, a0.y, a0.z, a0.w, r[4 * j2 + 2], r[4 * j2 + 3]);
            mma_bf16(c[1][2 * j2],     a1.x, a1.y, a1.z, a1.w, r[4 * j2],     r[4 * j2 + 1]);
            mma_bf16(c[1][2 * j2 + 1], a1.x, a1.y, a1.z, a1.w, r[4 * j2 + 2], r[4 * j2 + 3]);
        }
    }
#pragma unroll 4
    for (int kk2 = 0; kk2 < 8; kk2++) {
        uint4 a0 = A4[(16 + kk2) * 32 + lane];
        uint4 a1 = A4[768 + (16 + kk2) * 32 + lane];
        uint32_t r[12];
#pragma unroll
        for (int j2 = 0; j2 < 3; j2++) {
            asm volatile("ldmatrix.sync.aligned.m8n8.x4.shared.b16 {%0,%1,%2,%3}, [%4];"
                         : "=r"(r[4 * j2]), "=r"(r[4 * j2 + 1]),
                           "=r"(r[4 * j2 + 2]), "=r"(r[4 * j2 + 3])
                         : "r"(base0 + (uint32_t)(j2 * 16 * BPITCH_B + kk2 * 32)));
        }
#pragma unroll
        for (int j2 = 0; j2 < 3; j2++) {
            mma_bf16(c[0][2 * j2],     a0.x, a0.y, a0.z, a0.w, r[4 * j2],     r[4 * j2 + 1]);
            mma_bf16(c[0][2 * j2 + 1], a0.x, a0.y, a0.z, a0.w, r[4 * j2 + 2], r[4 * j2 + 3]);
            mma_bf16(c[1][2 * j2],     a1.x, a1.y, a1.z, a1.w, r[4 * j2],     r[4 * j2 + 1]);
            mma_bf16(c[1][2 * j2 + 1], a1.x, a1.y, a1.z, a1.w, r[4 * j2 + 2], r[4 * j2 + 3]);
        }
    }
}

// ------------ gate epilogue ------------
__device__ __forceinline__ void gate_epi32(float c[2][6][4], char* smem,
                                           const float* __restrict__ lb1,
                                           const float* __restrict__ W2,
                                           const float* __restrict__ b2p,
                                           float* __restrict__ gate_out, int base)
{
    int tid = threadIdx.x;
    int w = tid >> 5, lane = tid & 31;
    int mp = w & 3;
    int g = lane >> 2, t = lane & 3;
    float* sRed = (float*)(smem + SRED_OFF);

    float p0[6], p1[6];
#pragma unroll
    for (int j = 0; j < 6; j++) { p0[j] = 0.f; p1[j] = 0.f; }
#pragma unroll
    for (int mb = 0; mb < 2; mb++) {
        int r0 = mp * 32 + mb * 16 + g;
        float bb0 = lb1[r0], bb8 = lb1[r0 + 8];
        float w0 = W2[r0], w8 = W2[r0 + 8];
#pragma unroll
        for (int j = 0; j < 6; j++) {
            p0[j] += fmaxf(c[mb][j][0] + bb0, 0.f) * w0 + fmaxf(c[mb][j][2] + bb8, 0.f) * w8;
            p1[j] += fmaxf(c[mb][j][1] + bb0, 0.f) * w0 + fmaxf(c[mb][j][3] + bb8, 0.f) * w8;
        }
    }
#pragma unroll
    for (int j = 0; j < 6; j++) {
#pragma unroll
        for (int m = 4; m <= 16; m <<= 1) {
            p0[j] += __shfl_xor_sync(0xffffffffu, p0[j], m);
            p1[j] += __shfl_xor_sync(0xffffffffu, p1[j], m);
        }
    }
    if (g == 0) {
#pragma unroll
        for (int j = 0; j < 6; j++) {
            sRed[w * 52 + j * 8 + t * 2]     = p0[j];
            sRed[w * 52 + j * 8 + t * 2 + 1] = p1[j];
        }
    }
    __syncthreads();
    if (tid < 96) {
        int nh2 = tid / 48, nn = tid - nh2 * 48;
        float s = sRed[(nh2 * 4 + 0) * 52 + nn] + sRed[(nh2 * 4 + 1) * 52 + nn]
                + sRed[(nh2 * 4 + 2) * 52 + nn] + sRed[(nh2 * 4 + 3) * 52 + nn];
        gate_out[base + tid] = sigm(s + b2p[0]);
    }
}

// ------------ edge0_k ------------
__global__ void __launch_bounds__(256, 3) edge0_k(const float* __restrict__ lb1,
                                                  const float* __restrict__ W2,
                                                  const float* __restrict__ b2p,
                                                  const float* __restrict__ msg_b,
                                                  const int* __restrict__ nnum,
                                                  float* __restrict__ gate_out)
{
    extern __shared__ char smem[];
    uint32_t sbAddr = smem_to_u32(smem);
    unsigned* sBw = (unsigned*)smem;
    int tid = threadIdx.x;
    int bx = blockIdx.x;
    int f = bx / 6; int tt = bx - f * 6;
    int cnt = nnum[f]; int NV = cnt * cnt;
    int cb = tt * 96;
    if (cb >= NV) return;
    int base = f * 576 + cb;

    {
        int q = tid >> 6, dp = tid & 63;
        const float* s0 = g_edge_c + (size_t)(2 * dp) * ECOLS + base + q * 24;
        const float* s1 = s0 + ECOLS;
        for (int i = 0; i < 24; i += 4) {
            float4 x0 = *(const float4*)(s0 + i);
            float4 x1 = *(const float4*)(s1 + i);
            float a0[4] = {x0.x, x0.y, x0.z, x0.w};
            float a1[4] = {x1.x, x1.y, x1.z, x1.w};
#pragma unroll
            for (int j = 0; j < 4; j++) {
                int n = q * 24 + i + j;
                unsigned hw, lw; split_pair(a0[j], a1[j], hw, lw);
                sBw[n * BPITCH_W + dp]      = hw;
                sBw[n * BPITCH_W + 64 + dp] = lw;
            }
        }
    }
    __syncthreads();

    int w = tid >> 5, lane = tid & 31;
    int mp = w & 3, nh = w >> 2;
    int g = lane >> 2, t = lane & 3;
    float c[2][6][4];

    gemm_m32(c, g_wA4 + (2 * mp) * 768, sbAddr, lane, nh);
    gate_epi32(c, smem, lb1, W2, b2p, gate_out, base);
    __syncthreads();

    gemm_m32(c, g_wA4 + 6144 + (2 * mp) * 768, sbAddr, lane, nh);
#pragma unroll
    for (int mb = 0; mb < 2; mb++) {
        int r0 = mp * 32 + mb * 16 + g;
        float mb0 = msg_b[r0], mb8 = msg_b[r0 + 8];
#pragma unroll
        for (int j = 0; j < 6; j++) {
            int col = base + nh * 48 + j * 8 + t * 2;
            *(float2*)(g_epre + (size_t)r0 * ECOLS + col) =
                make_float2(c[mb][j][0] + mb0, c[mb][j][1] + mb0);
            *(float2*)(g_epre + (size_t)(r0 + 8) * ECOLS + col) =
                make_float2(c[mb][j][2] + mb8, c[mb][j][3] + mb8);
        }
    }
}

// ------------ recon_k (nh read COMPACT via cpre) ------------
__global__ void __launch_bounds__(256, 3) recon_k(const float* __restrict__ lb1,
                                                  const float* __restrict__ W2,
                                                  const float* __restrict__ b2p,
                                                  const int* __restrict__ nnum,
                                                  const float* __restrict__ gate_in,
                                                  float* __restrict__ gate_out)
{
    extern __shared__ char smem[];
    uint32_t sbAddr = smem_to_u32(smem);
    unsigned* sBw = (unsigned*)smem;
    float* snh = (float*)(smem + SNH_OFF);
    float* sg  = (float*)(smem + SG_OFF);
    __shared__ int ssw[96];
    int tid = threadIdx.x;
    int bx = blockIdx.x;
    int f = bx / 6; int tt = bx - f * 6;
    int cnt = nnum[f]; int NV = cnt * cnt;
    int cb = tt * 96;
    if (cb >= NV) return;
    int base = f * 576 + cb;
    int cp = g_cpre[f];

    for (int i = tid; i < 3072; i += 256) {
        int d = i / 24, w = i - d * 24;
        snh[i] = (w < cnt) ? g_nh[d * NCOLS + cp + w] : 0.f;
    }
    if (tid < 96) {
        sg[tid] = gate_in[base + tid];
        int c = cb + tid;
        int v = c / cnt;
        ssw[tid] = c - v * cnt;
    }
    __syncthreads();

    {
        int q = tid >> 6, dp = tid & 63;
        int d0 = 2 * dp, d1 = d0 + 1;
        const float* s0 = g_epre + (size_t)d0 * ECOLS + base + q * 24;
        const float* s1 = s0 + ECOLS;
        int n0 = q * 24;
        for (int i = 0; i < 24; i += 4) {
            float4 x0 = *(const float4*)(s0 + i);
            float4 x1 = *(const float4*)(s1 + i);
            float a0[4] = {x0.x, x0.y, x0.z, x0.w};
            float a1[4] = {x1.x, x1.y, x1.z, x1.w};
#pragma unroll
            for (int j = 0; j < 4; j++) {
                int nn = n0 + i + j;
                float v0 = 0.f, v1 = 0.f;
                if (cb + nn < NV) {
                    int w = ssw[nn];
                    float gv = sg[nn];
                    v0 = gv * fmaxf(snh[d0 * 24 + w] + a0[j], 0.f);
                    v1 = gv * fmaxf(snh[d1 * 24 + w] + a1[j], 0.f);
                }
                unsigned hw, lw; split_pair(v0, v1, hw, lw);
                sBw[nn * BPITCH_W + dp]      = hw;
                sBw[nn * BPITCH_W + 64 + dp] = lw;
            }
        }
    }
    __syncthreads();

    int w = tid >> 5, lane = tid & 31;
    int mp = w & 3, nh = w >> 2;
    float c[2][6][4];
    gemm_m32(c, g_wA4 + (2 * mp) * 768, sbAddr, lane, nh);
    gate_epi32(c, smem, lb1, W2, b2p, gate_out, base);
}

// ------------ mv_k: writes COMPACT m_v ------------
__global__ void __launch_bounds__(256) mv_k(const int* __restrict__ nnum,
                                            const float* __restrict__ gate_in)
{
    __shared__ float snh[32 * 24];
    __shared__ float sg[576];
    int f = blockIdx.x >> 2, dg = blockIdx.x & 3;
    int cnt = nnum[f];
    int NV = cnt * cnt;
    int cp = g_cpre[f];
    int tid = threadIdx.x;
    for (int i = tid; i < 768; i += 256) {
        int d = i / 24, w = i - d * 24;
        snh[i] = (w < cnt) ? g_nh[(dg * 32 + d) * NCOLS + cp + w] : 0.f;
    }
    for (int i = tid; i < NV; i += 256) sg[i] = gate_in[f * 576 + i];
    __syncthreads();

    for (int p = tid; p < 768; p += 256) {
        int dl = p / 24, v = p - dl * 24;
        int d = dg * 32 + dl;
        if (v < cnt) {
            const float* ep = g_epre + (size_t)d * ECOLS + f * 576 + v * cnt;
            const float* gp = sg + v * cnt;
            const float* np = snh + dl * 24;
            float s = 0.f;
            for (int w = 0; w < cnt; w++)
                s += gp[w] * fmaxf(np[w] + ep[w], 0.f);
            g_mv[d * NCOLS + cp + v] = s;
        }
    }
}

// ------------ shared hgemm body (m32 x n48, optional compact early-exit) ------------
__device__ __forceinline__ void hgemm_body(const uint4* __restrict__ Afrag, int mrowblk,
                                           const float* __restrict__ X,
                                           const float* __restrict__ bias,
                                           const float* __restrict__ bias2,
                                           float* __restrict__ Y, int cols, int c0,
                                           char* smem, uint32_t sbAddr)
{
    unsigned* sBw = (unsigned*)smem;
    int tid = threadIdx.x;
    {
        int q = tid >> 6, dp = tid & 63;
        const float* s0 = X + (size_t)(2 * dp) * cols + c0 + q * 24;
        const float* s1 = s0 + cols;
        for (int i = 0; i < 24; i += 4) {
            float4 x0 = *(const float4*)(s0 + i);
            float4 x1 = *(const float4*)(s1 + i);
            float a0[4] = {x0.x, x0.y, x0.z, x0.w};
            float a1[4] = {x1.x, x1.y, x1.z, x1.w};
#pragma unroll
            for (int j = 0; j < 4; j++) {
                int n = q * 24 + i + j;
                unsigned hw, lw; split_pair(a0[j], a1[j], hw, lw);
                sBw[n * BPITCH_W + dp]      = hw;
                sBw[n * BPITCH_W + 64 + dp] = lw;
            }
        }
    }
    __syncthreads();

    int w = tid >> 5, lane = tid & 31;
    int mp = w & 3, nh = w >> 2;
    int g = lane >> 2, t = lane & 3;
    float c[2][6][4];
    gemm_m32(c, Afrag + (mrowblk * 8 + 2 * mp) * 768, sbAddr, lane, nh);

#pragma unroll
    for (int mb = 0; mb < 2; mb++) {
        int r0 = mrowblk * 128 + mp * 32 + mb * 16 + g;
        float b0v = (bias ? bias[r0] : 0.f) + (bias2 ? bias2[r0] : 0.f);
        float b8v = (bias ? bias[r0 + 8] : 0.f) + (bias2 ? bias2[r0 + 8] : 0.f);
#pragma unroll
        for (int j = 0; j < 6; j++) {
            int col = c0 + nh * 48 + j * 8 + t * 2;
            *(float2*)(Y + (size_t)r0 * cols + col) =
                make_float2(c[mb][j][0] + b0v, c[mb][j][1] + b0v);
            *(float2*)(Y + (size_t)(r0 + 8) * cols + col) =
                make_float2(c[mb][j][2] + b8v, c[mb][j][3] + b8v);
        }
    }
}

__global__ void __launch_bounds__(256, 3) hgemm_k(const uint4* __restrict__ Afrag,
                                                  const float* __restrict__ X,
                                                  const float* __restrict__ bias,
                                                  const float* __restrict__ bias2,
                                                  float* __restrict__ Y, int cols,
                                                  int use_compact)
{
    extern __shared__ char smem[];
    int c0 = blockIdx.x * 96;
    if (use_compact && c0 >= g_nccg[0]) return;
    hgemm_body(Afrag, blockIdx.y, X, bias, bias2, Y, cols, c0,
               smem, smem_to_u32(smem));
}

__global__ void __launch_bounds__(256, 3) gigh_k(const uint4* __restrict__ wA)
{
    extern __shared__ char smem[];
    int c0 = blockIdx.x * 96;
    if (c0 >= g_nccg[0]) return;
    int by = blockIdx.y;
    if (by < 3)
        hgemm_body(wA + 18432, by, g_mv, nullptr, nullptr, g_gi, NCOLS,
                   c0, smem, smem_to_u32(smem));
    else
        hgemm_body(wA + 36864, by - 3, g_hnC, nullptr, nullptr, g_gh, NCOLS,
                   c0, smem, smem_to_u32(smem));
}

// ------------ node transpose (+ compact hnC init) ------------
__global__ void __launch_bounds__(256) tr_node_k(const float* __restrict__ in)
{
    int o4 = blockIdx.x * 256 + threadIdx.x;
    int d = o4 / 1536; int c4 = o4 - d * 1536;
    int f = c4 / 6;    int n4 = c4 - f * 6;
    float4 v = *(const float4*)(in + f * 3072 + d * 24 + n4 * 4);
    int dst = d * NCOLS + f * 24 + n4 * 4;
    *(float4*)(g_node0 + dst) = v;
    *(float4*)(g_hnode + dst) = v;
    int cp = g_cpre[f];
    int cnt = g_cpre[f + 1] - cp;
    float vs[4] = {v.x, v.y, v.z, v.w};
#pragma unroll
    for (int j = 0; j < 4; j++) {
        int n = n4 * 4 + j;
        if (n < cnt) g_hnC[d * NCOLS + cp + n] = vs[j];
    }
}

// ------------ GRU elementwise (COMPACT columns; no mask) ------------
__global__ void __launch_bounds__(256) gru_k(const float* __restrict__ bih,
                                             const float* __restrict__ bhh)
{
    int idx = blockIdx.x * 256 + threadIdx.x;
    int j = idx / NCOLS; int cc = idx - j * NCOLS;
    if (cc >= g_nccg[0]) return;
    int dense = g_colf[cc];
    float gir = g_gi[j * NCOLS + cc]         + bih[j];
    float giz = g_gi[(128 + j) * NCOLS + cc] + bih[128 + j];
    float gin = g_gi[(256 + j) * NCOLS + cc] + bih[256 + j];
    float ghr = g_gh[j * NCOLS + cc]         + bhh[j];
    float ghz = g_gh[(128 + j) * NCOLS + cc] + bhh[128 + j];
    float ghn = g_gh[(256 + j) * NCOLS + cc] + bhh[256 + j];
    float r = sigm(gir + ghr);
    float z = sigm(giz + ghz);
    float n2 = tanhf(gin + r * ghn);
    float h = g_hnode[j * NCOLS + dense];
    float hn = (1.f - z) * n2 + z * h;
    g_hnode[j * NCOLS + dense] = hn;
    g_hnC[j * NCOLS + cc] = hn;
}

// ------------ persistent LSTM ------------
__device__ __forceinline__ void group_barrier(int b, unsigned want)
{
    __threadfence();
    __syncthreads();
    if (threadIdx.x == 0) {
        unsigned tk = atomicAdd(&g_cnt2[b], 1u);
        if (tk == 15u) {
            g_cnt2[b] = 0;
            __threadfence();
            atomicExch(&g_sense2[b], want);
        } else {
            unsigned v;
            do {
                asm volatile("ld.acquire.gpu.u32 %0, [%1];" : "=r"(v) : "l"(&g_sense2[b]));
            } while (v != want);
        }
    }
    __syncthreads();
}

__global__ void __launch_bounds__(192) lstm_all_k(const float* __restrict__ Whh)
{
    __shared__ __align__(16) float sWt[128][36];
    __shared__ float sH[128][25];
    __shared__ float sG[32][25];
    int tid = threadIdx.x;
    int rg = blockIdx.x & 15, b = blockIdx.x >> 4;

    for (int i = tid; i < 4096; i += 192) {
        int r = i >> 7, k = i & 127;
        int jg = (r >> 3) * 128 + rg * 8 + (r & 7);
        sWt[k][r] = Whh[jg * 128 + k];
    }
    int tr = tid & 7, tc = tid >> 3;
    int hh = tid / 24, nn = tid - hh * 24;
    int jrow = rg * 8 + hh;
    int scol = b * 24 + nn;
    float creg = 0.f;
    unsigned phase = 0;

    for (int t = 0; t < 32; t++) {
        if (t == 0) {
            for (int i = tid; i < 3200; i += 192) (&sH[0][0])[i] = 0.f;
            __syncthreads();
        } else {
            phase++;
            group_barrier(b, phase & 1u);
            const float* hb = g_h + ((t + 1) & 1) * 24576;
            for (int i = tid; i < 3072; i += 192) {
                int j = i / 24, n2 = i - j * 24;
                sH[j][n2] = __ldcg(hb + j * 192 + b * 24 + n2);
            }
            __syncthreads();
        }

        unsigned long long acc0 = 0ull, acc1 = 0ull;
#pragma unroll 8
        for (int k = 0; k < 128; k++) {
            ulonglong2 av = *(const ulonglong2*)&sWt[k][tr * 4];
            float bv = sH[k][tc];
            unsigned long long bs = pack2(bv, bv);
            ffma2(acc0, av.x, bs);
            ffma2(acc1, av.y, bs);
        }
        float2 u0 = unpack2(acc0), u1 = unpack2(acc1);
        sG[tr * 4 + 0][tc] = u0.x; sG[tr * 4 + 1][tc] = u0.y;
        sG[tr * 4 + 2][tc] = u1.x; sG[tr * 4 + 3][tc] = u1.y;
        __syncthreads();

        int colx = (b * 32 + t) * 24 + nn;
        float ig = sG[hh][nn]      + g_xg[(      jrow) * NCOLS + colx];
        float fg = sG[8 + hh][nn]  + g_xg[(128 + jrow) * NCOLS + colx];
        float gg = sG[16 + hh][nn] + g_xg[(256 + jrow) * NCOLS + colx];
        float og = sG[24 + hh][nn] + g_xg[(384 + jrow) * NCOLS + colx];
        creg = sigm(fg) * creg + sigm(ig) * tanhf(gg);
        float hnew = sigm(og) * tanhf(creg);
        __stcg(g_h + (t & 1) * 24576 + jrow * 192 + scol, hnew);
        g_hist[jrow * 6144 + t * 192 + scol] = hnew;
        __syncthreads();
    }
    phase++;
    group_barrier(b, phase & 1u);
}

// ------------ readout ------------
__global__ void __launch_bounds__(256) readout_k(const float* __restrict__ roW,
                                                 const float* __restrict__ rob,
                                                 const int* __restrict__ nnum,
                                                 float* __restrict__ out)
{
    __shared__ float sH[128][65];
    __shared__ float sRo[6][128];
    __shared__ float sRob[6];
    int tid = threadIdx.x;
    int c0 = blockIdx.x * 64;
    for (int i = tid; i < 8192; i += 256) {
        int j = i >> 6, cc = i & 63;
        sH[j][cc] = g_hist[j * 6144 + c0 + cc];
    }
    for (int i = tid; i < 768; i += 256) sRo[i >> 7][i & 127] = roW[i];
    if (tid < 6) sRob[tid] = rob[tid];
    __syncthreads();
    for (int e = tid; e < 384; e += 256) {
        int cc = e / 6, c = e - cc * 6;
        float s = 0.f;
#pragma unroll 8
        for (int j = 0; j < 128; j++) s += sRo[c][j] * sH[j][cc];
        int ct = c0 + cc;
        int t = ct / 192; int srem = ct - t * 192;
        int b = srem / 24; int n = srem - b * 24;
        int f = b * 32 + t;
        out[(f * 24 + n) * 6 + c] = (n < nnum[f]) ? (s + sRob[c]) : 0.f;
    }
}

// ------------ host launcher ------------
extern "C" void kernel_launch(void* const* d_in, const int* in_sizes, int n_in,
                              void* d_out, int out_size)
{
    const float* node     = (const float*)d_in[0];
    const float* edge     = (const float*)d_in[1];
    const float* link_W1  = (const float*)d_in[2];
    const float* link_b1  = (const float*)d_in[3];
    const float* link_W2  = (const float*)d_in[4];
    const float* link_b2  = (const float*)d_in[5];
    const float* msg_Wh   = (const float*)d_in[6];
    const float* msg_We   = (const float*)d_in[7];
    const float* msg_b    = (const float*)d_in[8];
    const float* gru_Wih  = (const float*)d_in[9];
    const float* gru_Whh  = (const float*)d_in[10];
    const float* gru_bih  = (const float*)d_in[11];
    const float* gru_bhh  = (const float*)d_in[12];
    const float* lstm_Wih = (const float*)d_in[13];
    const float* lstm_Whh = (const float*)d_in[14];
    const float* lstm_bih = (const float*)d_in[15];
    const float* lstm_bhh = (const float*)d_in[16];
    const float* ro_W     = (const float*)d_in[17];
    const float* ro_b     = (const float*)d_in[18];
    const int*   nnum     = (const int*)d_in[19];
    float* out = (float*)d_out;

    float* hnode; cudaGetSymbolAddress((void**)&hnode, g_hnode);
    float* hnC;   cudaGetSymbolAddress((void**)&hnC,   g_hnC);
    float* nh;    cudaGetSymbolAddress((void**)&nh,    g_nh);
    float* xg;    cudaGetSymbolAddress((void**)&xg,    g_xg);
    uint4* wA;    cudaGetSymbolAddress((void**)&wA,    g_wA4);
    float* gateA; cudaGetSymbolAddress((void**)&gateA, g_gateA);
    float* gateB; cudaGetSymbolAddress((void**)&gateB, g_gateB);

    static int smem_set = 0;
    if (!smem_set) {
        cudaFuncSetAttribute(edge0_k, cudaFuncAttributeMaxDynamicSharedMemorySize, SM_EDGE);
        cudaFuncSetAttribute(recon_k, cudaFuncAttributeMaxDynamicSharedMemorySize, SM_EDGE);
        cudaFuncSetAttribute(hgemm_k, cudaFuncAttributeMaxDynamicSharedMemorySize, SM_HG);
        cudaFuncSetAttribute(gigh_k,  cudaFuncAttributeMaxDynamicSharedMemorySize, SM_HG);
        smem_set = 1;
    }

    const int NTILE = 256 * 6;
    const int NCT   = NCOLS / 96;   // 64

    prefix_k<<<1, 256>>>(nnum);
    tr_node_k<<<(128 * NCOLS / 4) / 256, 256>>>(node);
    prep_a_k<<<72, 256>>>(link_W1, msg_We, msg_Wh, wA);
    prep_b_k<<<240, 256>>>(gru_Wih, gru_Whh, lstm_Wih, wA);
    compact_edge_k<<<2048, 256>>>(edge, nnum);
    // layer-0 nh (compact), then edge0 in profile slot 6
    hgemm_k<<<dim3(NCT, 1), 256, SM_HG>>>(wA + 12288, hnC, nullptr, nullptr, nh, NCOLS, 1);
    edge0_k<<<NTILE, 256, SM_EDGE>>>(link_b1, link_W2, link_b2, msg_b, nnum, gateA);

    float* gbuf[2] = {gateA, gateB};
    for (int p = 0; p < 3; p++) {
        float* gin  = gbuf[p & 1];
        float* gout = gbuf[(p + 1) & 1];
        if (p > 0)
            hgemm_k<<<dim3(NCT, 1), 256, SM_HG>>>(wA + 12288, hnC, nullptr, nullptr, nh, NCOLS, 1);
        if (p < 2)
            recon_k<<<NTILE, 256, SM_EDGE>>>(link_b1, link_W2, link_b2, nnum, gin, gout);
        mv_k<<<1024, 256>>>(nnum, gin);
        gigh_k<<<dim3(NCT, 6), 256, SM_HG>>>(wA);
        gru_k<<<(128 * NCOLS) / 256, 256>>>(gru_bih, gru_bhh);
    }

    hgemm_k<<<dim3(NCT, 4), 256, SM_HG>>>(wA + 55296, hnode, lstm_bih, lstm_bhh, xg, NCOLS, 0);
    lstm_all_k<<<128, 192>>>(lstm_Whh);
    readout_k<<<96, 256>>>(ro_W, ro_b, nnum, out);
    (void)in_sizes; (void)n_in; (void)out_size;
}

// round 16
// speedup vs baseline: 1.9168x; 1.0083x over previous
#include <cuda_runtime.h>
#include <cuda_bf16.h>
#include <math.h>
#include <stdint.h>

// ------------ problem constants ------------
#define NFRM   256                  // B*T
#define ECOLS  147456               // NFRM * 576 edge columns
#define NCOLS  6144                 // NFRM * 24 node columns

// ------------ device scratch ------------
__device__ float g_edge_c[128 * ECOLS];   // compacted edge [d][f*576 + c], padding zeroed
__device__ float g_epre  [128 * ECOLS];   // msg_We @ edge + msg_b, COMPACT per frame
__device__ float g_gateA [ECOLS];
__device__ float g_gateB [ECOLS];
__device__ float g_node0 [128 * NCOLS];
__device__ float g_hnode [128 * NCOLS];   // dense hnode (LSTM path needs all columns)
__device__ float g_hnC   [128 * NCOLS];   // COMPACT hnode (node-GEMM path)
__device__ float g_nhA   [128 * NCOLS];   // COMPACT nh double buffer
__device__ float g_nhB   [128 * NCOLS];
__device__ float g_mv    [128 * NCOLS];   // COMPACT
__device__ float g_gi    [384 * NCOLS];   // COMPACT
__device__ float g_gh    [384 * NCOLS];   // COMPACT
__device__ float g_xg    [512 * NCOLS];   // dense
__device__ float g_h     [2 * 128 * 192];
__device__ float g_hist  [128 * 6144];
__device__ int   g_cpre  [257];
__device__ int   g_colf  [NCOLS];
__device__ int   g_nccg  [1];
__device__ unsigned g_cnt2[8];
__device__ unsigned g_sense2[8];
__device__ uint4 g_wA4[79872];

__device__ __forceinline__ float sigm(float x) { return 1.f / (1.f + expf(-x)); }

__device__ __forceinline__ void ffma2(unsigned long long& acc,
                                      unsigned long long a, unsigned long long b) {
    asm("fma.rn.f32x2 %0, %1, %2, %0;" : "+l"(acc) : "l"(a), "l"(b));
}
__device__ __forceinline__ unsigned long long pack2(float x, float y) {
    unsigned long long r;
    asm("mov.b64 %0, {%1, %2};" : "=l"(r) : "f"(x), "f"(y));
    return r;
}
__device__ __forceinline__ float2 unpack2(unsigned long long v) {
    float2 f;
    asm("mov.b64 {%0, %1}, %2;" : "=f"(f.x), "=f"(f.y) : "l"(v));
    return f;
}
__device__ __forceinline__ void split_bf(float x, __nv_bfloat16& h, __nv_bfloat16& l) {
    h = __float2bfloat16(x);
    l = __float2bfloat16(x - __bfloat162float(h));
}
__device__ __forceinline__ void split_pair(float x0, float x1, unsigned& hw, unsigned& lw) {
    __nv_bfloat16 h0, l0, h1, l1;
    split_bf(x0, h0, l0); split_bf(x1, h1, l1);
    hw = (unsigned)__bfloat16_as_ushort(h0) | ((unsigned)__bfloat16_as_ushort(h1) << 16);
    lw = (unsigned)__bfloat16_as_ushort(l0) | ((unsigned)__bfloat16_as_ushort(l1) << 16);
}
__device__ __forceinline__ uint32_t smem_to_u32(const void* p) {
    uint32_t a;
    asm("{ .reg .u64 t; cvta.to.shared.u64 t, %1; cvt.u32.u64 %0, t; }" : "=r"(a) : "l"(p));
    return a;
}

// ---- HMMA m16n8k16 bf16 ----
__device__ __forceinline__ void mma_bf16(float* c, uint32_t a0, uint32_t a1,
                                         uint32_t a2, uint32_t a3,
                                         uint32_t b0, uint32_t b1) {
    asm volatile(
        "mma.sync.aligned.m16n8k16.row.col.f32.bf16.bf16.f32 "
        "{%0,%1,%2,%3}, {%4,%5,%6,%7}, {%8,%9}, {%0,%1,%2,%3};"
        : "+f"(c[0]), "+f"(c[1]), "+f"(c[2]), "+f"(c[3])
        : "r"(a0), "r"(a1), "r"(a2), "r"(a3), "r"(b0), "r"(b1));
}

#define BPITCH_W  132
#define BPITCH_B  528
#define SNH_OFF   50688     // float[128*24]
#define SG_OFF    62976     // float[96]
#define SRED_OFF  63360     // float[8][52]
#define SM_EDGE   66688
#define SM_HG     50688

// ------------ prefix ------------
__global__ void __launch_bounds__(256) prefix_k(const int* __restrict__ nnum)
{
    __shared__ int sc[256];
    int f = threadIdx.x;
    int c = nnum[f];
    sc[f] = c;
    __syncthreads();
    if (f == 0) {
        int acc = 0;
        for (int i = 0; i < 256; i++) { g_cpre[i] = acc; acc += sc[i]; }
        g_cpre[256] = acc;
        g_nccg[0] = acc;
    }
    __syncthreads();
    int base = g_cpre[f];
    for (int n = 0; n < c; n++) g_colf[base + n] = f * 24 + n;
}

// ------------ compact_edge ------------
__global__ void __launch_bounds__(256) compact_edge_k(const float* __restrict__ edge,
                                                      const int* __restrict__ nnum)
{
    __shared__ int sidx[576];
    int f = blockIdx.x >> 3, dg = blockIdx.x & 7;
    int cnt = nnum[f]; int NV = cnt * cnt;
    int NVp = ((NV + 95) / 96) * 96; if (NVp > 576) NVp = 576;
    int tid = threadIdx.x;
    for (int c = tid; c < NV; c += 256) {
        int v = c / cnt;
        sidx[c] = v * 24 + (c - v * cnt);
    }
    __syncthreads();
    int tot = 16 * NVp;
    for (int i = tid; i < tot; i += 256) {
        int dl = i / NVp, c = i - dl * NVp;
        int d = dg * 16 + dl;
        float val = 0.f;
        if (c < NV) val = edge[(size_t)f * 73728 + d * 576 + sidx[c]];
        g_edge_c[(size_t)d * ECOLS + f * 576 + c] = val;
    }
}

// ------------ prep ------------
__device__ __forceinline__ void prep_one(const float* __restrict__ W, uint4* __restrict__ out,
                                         int gidx)
{
    int mblk = gidx / 768;
    int rem  = gidx - mblk * 768;
    int kk   = rem >> 5;
    int lane = rem & 31;
    int g = lane >> 2, t = lane & 3;
    unsigned regs[4];
#pragma unroll
    for (int r = 0; r < 4; r++) {
        int row = mblk * 16 + g + ((r & 1) ? 8 : 0);
        int k0  = kk * 16 + t * 2 + ((r & 2) ? 8 : 0);
        unsigned pk = 0;
#pragma unroll
        for (int e = 0; e < 2; e++) {
            int ks = k0 + e;
            int region = ks >> 7;
            int kloc = ks & 127;
            float w = W[row * 128 + kloc];
            __nv_bfloat16 h, l; split_bf(w, h, l);
            __nv_bfloat16 b = (region < 2) ? h : l;
            pk |= (unsigned)__bfloat16_as_ushort(b) << (e * 16);
        }
        regs[r] = pk;
    }
    out[gidx] = make_uint4(regs[0], regs[1], regs[2], regs[3]);
}

__global__ void __launch_bounds__(256) prep_a_k(const float* __restrict__ w1,
                                                const float* __restrict__ we,
                                                const float* __restrict__ wh,
                                                uint4* __restrict__ out)
{
    int b = blockIdx.x;
    if (b < 24)      prep_one(w1, out,          b * 256 + threadIdx.x);
    else if (b < 48) prep_one(we, out + 6144,  (b - 24) * 256 + threadIdx.x);
    else             prep_one(wh, out + 12288, (b - 48) * 256 + threadIdx.x);
}
__global__ void __launch_bounds__(256) prep_b_k(const float* __restrict__ wih,
                                                const float* __restrict__ whh,
                                                const float* __restrict__ lih,
                                                uint4* __restrict__ out)
{
    int b = blockIdx.x;
    if (b < 72)       prep_one(wih, out + 18432,  b * 256 + threadIdx.x);
    else if (b < 144) prep_one(whh, out + 36864, (b - 72) * 256 + threadIdx.x);
    else              prep_one(lih, out + 55296, (b - 144) * 256 + threadIdx.x);
}

// ------------ warp GEMM m32 x n48 ------------
__device__ __forceinline__ void gemm_m32(float c[2][6][4], const uint4* __restrict__ A4,
                                         uint32_t sbAddr, int lane, int nh)
{
    int midx = lane >> 3, row = lane & 7;
    uint32_t base0 = sbAddr +
        (uint32_t)((nh * 48 + ((midx >> 1) << 3) + row) * BPITCH_B + (midx & 1) * 16);
#pragma unroll
    for (int mb = 0; mb < 2; mb++)
#pragma unroll
        for (int nt = 0; nt < 6; nt++)
#pragma unroll
            for (int r = 0; r < 4; r++) c[mb][nt][r] = 0.f;

#pragma unroll 4
    for (int kk2 = 0; kk2 < 8; kk2++) {
        uint4 a0 = A4[kk2 * 32 + lane];
        uint4 a1 = A4[768 + kk2 * 32 + lane];
        uint32_t r[12];
#pragma unroll
        for (int j2 = 0; j2 < 3; j2++) {
            asm volatile("ldmatrix.sync.aligned.m8n8.x4.shared.b16 {%0,%1,%2,%3}, [%4];"
                         : "=r"(r[4 * j2]), "=r"(r[4 * j2 + 1]),
                           "=r"(r[4 * j2 + 2]), "=r"(r[4 * j2 + 3])
                         : "r"(base0 + (uint32_t)(j2 * 16 * BPITCH_B + kk2 * 32)));
        }
#pragma unroll
        for (int j2 = 0; j2 < 3; j2++) {
            mma_bf16(c[0][2 * j2],     a0.x, a0.y, a0.z, a0.w, r[4 * j2],     r[4 * j2 + 1]);
            mma_bf16(c[0][2 * j2 + 1], a0.x, a0.y, a0.z, a0.w, r[4 * j2 + 2], r[4 * j2 + 3]);
            mma_bf16(c[1][2 * j2],     a1.x, a1.y, a1.z, a1.w, r[4 * j2],     r[4 * j2 + 1]);
            mma_bf16(c[1][2 * j2 + 1], a1.x, a1.y, a1.z, a1.w, r[4 * j2 + 2], r[4 * j2 + 3]);
        }
#pragma unroll
        for (int j2 = 0; j2 < 3; j2++) {
            asm volatile("ldmatrix.sync.aligned.m8n8.x4.shared.b16 {%0,%1,%2,%3}, [%4];"
                         : "=r"(r[4 * j2]), "=r"(r[4 * j2 + 1]),
                           "=r"(r[4 * j2 + 2]), "=r"(r[4 * j2 + 3])
                         : "r"(base0 + (uint32_t)(j2 * 16 * BPITCH_B + (kk2 + 8) * 32)));
        }
#pragma unroll
        for (int j2 = 0; j2 < 3; j2++) {
            mma_bf16(c[0][2 * j2],     a0.x, a0.y, a0.z, a0.w, r[4 * j2],     r[4 * j2 + 1]);
            mma_bf16(c[0][2 * j2 + 1], a0.x, a0.y, a0.z, a0.w, r[4 * j2 + 2], r[4 * j2 + 3]);
            mma_bf16(c[1][2 * j2],     a1.x, a1.y, a1.z, a1.w, r[4 * j2],     r[4 * j2 + 1]);
            mma_bf16(c[1][2 * j2 + 1], a1.x, a1.y, a1.z, a1.w, r[4 * j2 + 2], r[4 * j2 + 3]);
        }
    }
#pragma unroll 4
    for (int kk2 = 0; kk2 < 8; kk2++) {
        uint4 a0 = A4[(16 + kk2) * 32 + lane];
        uint4 a1 = A4[768 + (16 + kk2) * 32 + lane];
        uint32_t r[12];
#pragma unroll
        for (int j2 = 0; j2 < 3; j2++) {
            asm volatile("ldmatrix.sync.aligned.m8n8.x4.shared.b16 {%0,%1,%2,%3}, [%4];"
                         : "=r"(r[4 * j2]), "=r"(r[4 * j2 + 1]),
                           "=r"(r[4 * j2 + 2]), "=r"(r[4 * j2 + 3])
                         : "r"(base0 + (uint32_t)(j2 * 16 * BPITCH_B + kk2 * 32)));
        }
#pragma unroll
        for (int j2 = 0; j2 < 3; j2++) {
            mma_bf16(c[0][2 * j2],     a0.x, a0.y, a0.z, a0.w, r[4 * j2],     r[4 * j2 + 1]);
            mma_bf16(c[0][2 * j2 + 1], a0.x, a0.y, a0.z, a0.w, r[4 * j2 + 2], r[4 * j2 + 3]);
            mma_bf16(c[1][2 * j2],     a1.x, a1.y, a1.z, a1.w, r[4 * j2],     r[4 * j2 + 1]);
            mma_bf16(c[1][2 * j2 + 1], a1.x, a1.y, a1.z, a1.w, r[4 * j2 + 2], r[4 * j2 + 3]);
        }
    }
}

// ------------ gate epilogue ------------
__device__ __forceinline__ void gate_epi32(float c[2][6][4], char* smem,
                                           const float* __restrict__ lb1,
                                           const float* __restrict__ W2,
                                           const float* __restrict__ b2p,
                                           float* __restrict__ gate_out, int base)
{
    int tid = threadIdx.x;
    int w = tid >> 5, lane = tid & 31;
    int mp = w & 3;
    int g = lane >> 2, t = lane & 3;
    float* sRed = (float*)(smem + SRED_OFF);

    float p0[6], p1[6];
#pragma unroll
    for (int j = 0; j < 6; j++) { p0[j] = 0.f; p1[j] = 0.f; }
#pragma unroll
    for (int mb = 0; mb < 2; mb++) {
        int r0 = mp * 32 + mb * 16 + g;
        float bb0 = lb1[r0], bb8 = lb1[r0 + 8];
        float w0 = W2[r0], w8 = W2[r0 + 8];
#pragma unroll
        for (int j = 0; j < 6; j++) {
            p0[j] += fmaxf(c[mb][j][0] + bb0, 0.f) * w0 + fmaxf(c[mb][j][2] + bb8, 0.f) * w8;
            p1[j] += fmaxf(c[mb][j][1] + bb0, 0.f) * w0 + fmaxf(c[mb][j][3] + bb8, 0.f) * w8;
        }
    }
#pragma unroll
    for (int j = 0; j < 6; j++) {
#pragma unroll
        for (int m = 4; m <= 16; m <<= 1) {
            p0[j] += __shfl_xor_sync(0xffffffffu, p0[j], m);
            p1[j] += __shfl_xor_sync(0xffffffffu, p1[j], m);
        }
    }
    if (g == 0) {
#pragma unroll
        for (int j = 0; j < 6; j++) {
            sRed[w * 52 + j * 8 + t * 2]     = p0[j];
            sRed[w * 52 + j * 8 + t * 2 + 1] = p1[j];
        }
    }
    __syncthreads();
    if (tid < 96) {
        int nh2 = tid / 48, nn = tid - nh2 * 48;
        float s = sRed[(nh2 * 4 + 0) * 52 + nn] + sRed[(nh2 * 4 + 1) * 52 + nn]
                + sRed[(nh2 * 4 + 2) * 52 + nn] + sRed[(nh2 * 4 + 3) * 52 + nn];
        gate_out[base + tid] = sigm(s + b2p[0]);
    }
}

// ------------ edge0_k ------------
__global__ void __launch_bounds__(256, 3) edge0_k(const float* __restrict__ lb1,
                                                  const float* __restrict__ W2,
                                                  const float* __restrict__ b2p,
                                                  const float* __restrict__ msg_b,
                                                  const int* __restrict__ nnum,
                                                  float* __restrict__ gate_out)
{
    extern __shared__ char smem[];
    uint32_t sbAddr = smem_to_u32(smem);
    unsigned* sBw = (unsigned*)smem;
    int tid = threadIdx.x;
    int bx = blockIdx.x;
    int f = bx / 6; int tt = bx - f * 6;
    int cnt = nnum[f]; int NV = cnt * cnt;
    int cb = tt * 96;
    if (cb >= NV) return;
    int base = f * 576 + cb;

    {
        int q = tid >> 6, dp = tid & 63;
        const float* s0 = g_edge_c + (size_t)(2 * dp) * ECOLS + base + q * 24;
        const float* s1 = s0 + ECOLS;
        for (int i = 0; i < 24; i += 4) {
            float4 x0 = *(const float4*)(s0 + i);
            float4 x1 = *(const float4*)(s1 + i);
            float a0[4] = {x0.x, x0.y, x0.z, x0.w};
            float a1[4] = {x1.x, x1.y, x1.z, x1.w};
#pragma unroll
            for (int j = 0; j < 4; j++) {
                int n = q * 24 + i + j;
                unsigned hw, lw; split_pair(a0[j], a1[j], hw, lw);
                sBw[n * BPITCH_W + dp]      = hw;
                sBw[n * BPITCH_W + 64 + dp] = lw;
            }
        }
    }
    __syncthreads();

    int w = tid >> 5, lane = tid & 31;
    int mp = w & 3, nh = w >> 2;
    int g = lane >> 2, t = lane & 3;
    float c[2][6][4];

    gemm_m32(c, g_wA4 + (2 * mp) * 768, sbAddr, lane, nh);
    gate_epi32(c, smem, lb1, W2, b2p, gate_out, base);
    __syncthreads();

    gemm_m32(c, g_wA4 + 6144 + (2 * mp) * 768, sbAddr, lane, nh);
#pragma unroll
    for (int mb = 0; mb < 2; mb++) {
        int r0 = mp * 32 + mb * 16 + g;
        float mb0 = msg_b[r0], mb8 = msg_b[r0 + 8];
#pragma unroll
        for (int j = 0; j < 6; j++) {
            int col = base + nh * 48 + j * 8 + t * 2;
            *(float2*)(g_epre + (size_t)r0 * ECOLS + col) =
                make_float2(c[mb][j][0] + mb0, c[mb][j][1] + mb0);
            *(float2*)(g_epre + (size_t)(r0 + 8) * ECOLS + col) =
                make_float2(c[mb][j][2] + mb8, c[mb][j][3] + mb8);
        }
    }
}

// ------------ recon_k (nh buffer passed in) ------------
__global__ void __launch_bounds__(256, 3) recon_k(const float* __restrict__ lb1,
                                                  const float* __restrict__ W2,
                                                  const float* __restrict__ b2p,
                                                  const int* __restrict__ nnum,
                                                  const float* __restrict__ gate_in,
                                                  float* __restrict__ gate_out,
                                                  const float* __restrict__ nhbuf)
{
    extern __shared__ char smem[];
    uint32_t sbAddr = smem_to_u32(smem);
    unsigned* sBw = (unsigned*)smem;
    float* snh = (float*)(smem + SNH_OFF);
    float* sg  = (float*)(smem + SG_OFF);
    __shared__ int ssw[96];
    int tid = threadIdx.x;
    int bx = blockIdx.x;
    int f = bx / 6; int tt = bx - f * 6;
    int cnt = nnum[f]; int NV = cnt * cnt;
    int cb = tt * 96;
    if (cb >= NV) return;
    int base = f * 576 + cb;
    int cp = g_cpre[f];

    for (int i = tid; i < 3072; i += 256) {
        int d = i / 24, w = i - d * 24;
        snh[i] = (w < cnt) ? nhbuf[d * NCOLS + cp + w] : 0.f;
    }
    if (tid < 96) {
        sg[tid] = gate_in[base + tid];
        int c = cb + tid;
        int v = c / cnt;
        ssw[tid] = c - v * cnt;
    }
    __syncthreads();

    {
        int q = tid >> 6, dp = tid & 63;
        int d0 = 2 * dp, d1 = d0 + 1;
        const float* s0 = g_epre + (size_t)d0 * ECOLS + base + q * 24;
        const float* s1 = s0 + ECOLS;
        int n0 = q * 24;
        for (int i = 0; i < 24; i += 4) {
            float4 x0 = *(const float4*)(s0 + i);
            float4 x1 = *(const float4*)(s1 + i);
            float a0[4] = {x0.x, x0.y, x0.z, x0.w};
            float a1[4] = {x1.x, x1.y, x1.z, x1.w};
#pragma unroll
            for (int j = 0; j < 4; j++) {
                int nn = n0 + i + j;
                float v0 = 0.f, v1 = 0.f;
                if (cb + nn < NV) {
                    int w = ssw[nn];
                    float gv = sg[nn];
                    v0 = gv * fmaxf(snh[d0 * 24 + w] + a0[j], 0.f);
                    v1 = gv * fmaxf(snh[d1 * 24 + w] + a1[j], 0.f);
                }
                unsigned hw, lw; split_pair(v0, v1, hw, lw);
                sBw[nn * BPITCH_W + dp]      = hw;
                sBw[nn * BPITCH_W + 64 + dp] = lw;
            }
        }
    }
    __syncthreads();

    int w = tid >> 5, lane = tid & 31;
    int mp = w & 3, nh = w >> 2;
    float c[2][6][4];
    gemm_m32(c, g_wA4 + (2 * mp) * 768, sbAddr, lane, nh);
    gate_epi32(c, smem, lb1, W2, b2p, gate_out, base);
}

// ------------ mv_k ------------
__global__ void __launch_bounds__(256) mv_k(const int* __restrict__ nnum,
                                            const float* __restrict__ gate_in,
                                            const float* __restrict__ nhbuf)
{
    __shared__ float snh[32 * 24];
    __shared__ float sg[576];
    int f = blockIdx.x >> 2, dg = blockIdx.x & 3;
    int cnt = nnum[f];
    int NV = cnt * cnt;
    int cp = g_cpre[f];
    int tid = threadIdx.x;
    for (int i = tid; i < 768; i += 256) {
        int d = i / 24, w = i - d * 24;
        snh[i] = (w < cnt) ? nhbuf[(dg * 32 + d) * NCOLS + cp + w] : 0.f;
    }
    for (int i = tid; i < NV; i += 256) sg[i] = gate_in[f * 576 + i];
    __syncthreads();

    for (int p = tid; p < 768; p += 256) {
        int dl = p / 24, v = p - dl * 24;
        int d = dg * 32 + dl;
        if (v < cnt) {
            const float* ep = g_epre + (size_t)d * ECOLS + f * 576 + v * cnt;
            const float* gp = sg + v * cnt;
            const float* np = snh + dl * 24;
            float s = 0.f;
            for (int w = 0; w < cnt; w++)
                s += gp[w] * fmaxf(np[w] + ep[w], 0.f);
            g_mv[d * NCOLS + cp + v] = s;
        }
    }
}

// ------------ shared hgemm body ------------
__device__ __forceinline__ void hgemm_body(const uint4* __restrict__ Afrag, int mrowblk,
                                           const float* __restrict__ X,
                                           const float* __restrict__ bias,
                                           const float* __restrict__ bias2,
                                           float* __restrict__ Y, int cols, int c0,
                                           char* smem, uint32_t sbAddr)
{
    unsigned* sBw = (unsigned*)smem;
    int tid = threadIdx.x;
    {
        int q = tid >> 6, dp = tid & 63;
        const float* s0 = X + (size_t)(2 * dp) * cols + c0 + q * 24;
        const float* s1 = s0 + cols;
        for (int i = 0; i < 24; i += 4) {
            float4 x0 = *(const float4*)(s0 + i);
            float4 x1 = *(const float4*)(s1 + i);
            float a0[4] = {x0.x, x0.y, x0.z, x0.w};
            float a1[4] = {x1.x, x1.y, x1.z, x1.w};
#pragma unroll
            for (int j = 0; j < 4; j++) {
                int n = q * 24 + i + j;
                unsigned hw, lw; split_pair(a0[j], a1[j], hw, lw);
                sBw[n * BPITCH_W + dp]      = hw;
                sBw[n * BPITCH_W + 64 + dp] = lw;
            }
        }
    }
    __syncthreads();

    int w = tid >> 5, lane = tid & 31;
    int mp = w & 3, nh = w >> 2;
    int g = lane >> 2, t = lane & 3;
    float c[2][6][4];
    gemm_m32(c, Afrag + (mrowblk * 8 + 2 * mp) * 768, sbAddr, lane, nh);

#pragma unroll
    for (int mb = 0; mb < 2; mb++) {
        int r0 = mrowblk * 128 + mp * 32 + mb * 16 + g;
        float b0v = (bias ? bias[r0] : 0.f) + (bias2 ? bias2[r0] : 0.f);
        float b8v = (bias ? bias[r0 + 8] : 0.f) + (bias2 ? bias2[r0 + 8] : 0.f);
#pragma unroll
        for (int j = 0; j < 6; j++) {
            int col = c0 + nh * 48 + j * 8 + t * 2;
            *(float2*)(Y + (size_t)r0 * cols + col) =
                make_float2(c[mb][j][0] + b0v, c[mb][j][1] + b0v);
            *(float2*)(Y + (size_t)(r0 + 8) * cols + col) =
                make_float2(c[mb][j][2] + b8v, c[mb][j][3] + b8v);
        }
    }
}

__global__ void __launch_bounds__(256, 3) hgemm_k(const uint4* __restrict__ Afrag,
                                                  const float* __restrict__ X,
                                                  const float* __restrict__ bias,
                                                  const float* __restrict__ bias2,
                                                  float* __restrict__ Y, int cols,
                                                  int use_compact)
{
    extern __shared__ char smem[];
    int c0 = blockIdx.x * 96;
    if (use_compact && c0 >= g_nccg[0]) return;
    hgemm_body(Afrag, blockIdx.y, X, bias, bias2, Y, cols, c0,
               smem, smem_to_u32(smem));
}

__global__ void __launch_bounds__(256, 3) gigh_k(const uint4* __restrict__ wA)
{
    extern __shared__ char smem[];
    int c0 = blockIdx.x * 96;
    if (c0 >= g_nccg[0]) return;
    int by = blockIdx.y;
    if (by < 3)
        hgemm_body(wA + 18432, by, g_mv, nullptr, nullptr, g_gi, NCOLS,
                   c0, smem, smem_to_u32(smem));
    else
        hgemm_body(wA + 36864, by - 3, g_hnC, nullptr, nullptr, g_gh, NCOLS,
                   c0, smem, smem_to_u32(smem));
}

// ------------ node transpose ------------
__global__ void __launch_bounds__(256) tr_node_k(const float* __restrict__ in)
{
    int o4 = blockIdx.x * 256 + threadIdx.x;
    int d = o4 / 1536; int c4 = o4 - d * 1536;
    int f = c4 / 6;    int n4 = c4 - f * 6;
    float4 v = *(const float4*)(in + f * 3072 + d * 24 + n4 * 4);
    int dst = d * NCOLS + f * 24 + n4 * 4;
    *(float4*)(g_node0 + dst) = v;
    *(float4*)(g_hnode + dst) = v;
    int cp = g_cpre[f];
    int cnt = g_cpre[f + 1] - cp;
    float vs[4] = {v.x, v.y, v.z, v.w};
#pragma unroll
    for (int j = 0; j < 4; j++) {
        int n = n4 * 4 + j;
        if (n < cnt) g_hnC[d * NCOLS + cp + n] = vs[j];
    }
}

// ------------ GRU elementwise ------------
__global__ void __launch_bounds__(256) gru_k(const float* __restrict__ bih,
                                             const float* __restrict__ bhh)
{
    int idx = blockIdx.x * 256 + threadIdx.x;
    int j = idx / NCOLS; int cc = idx - j * NCOLS;
    if (cc >= g_nccg[0]) return;
    int dense = g_colf[cc];
    float gir = g_gi[j * NCOLS + cc]         + bih[j];
    float giz = g_gi[(128 + j) * NCOLS + cc] + bih[128 + j];
    float gin = g_gi[(256 + j) * NCOLS + cc] + bih[256 + j];
    float ghr = g_gh[j * NCOLS + cc]         + bhh[j];
    float ghz = g_gh[(128 + j) * NCOLS + cc] + bhh[128 + j];
    float ghn = g_gh[(256 + j) * NCOLS + cc] + bhh[256 + j];
    float r = sigm(gir + ghr);
    float z = sigm(giz + ghz);
    float n2 = tanhf(gin + r * ghn);
    float h = g_hnode[j * NCOLS + dense];
    float hn = (1.f - z) * n2 + z * h;
    g_hnode[j * NCOLS + dense] = hn;
    g_hnC[j * NCOLS + cc] = hn;
}

// ------------ persistent LSTM ------------
__device__ __forceinline__ void group_barrier(int b, unsigned want)
{
    __threadfence();
    __syncthreads();
    if (threadIdx.x == 0) {
        unsigned tk = atomicAdd(&g_cnt2[b], 1u);
        if (tk == 15u) {
            g_cnt2[b] = 0;
            __threadfence();
            atomicExch(&g_sense2[b], want);
        } else {
            unsigned v;
            do {
                asm volatile("ld.acquire.gpu.u32 %0, [%1];" : "=r"(v) : "l"(&g_sense2[b]));
            } while (v != want);
        }
    }
    __syncthreads();
}

__global__ void __launch_bounds__(192) lstm_all_k(const float* __restrict__ Whh)
{
    __shared__ __align__(16) float sWt[128][36];
    __shared__ float sH[128][25];
    __shared__ float sG[32][25];
    int tid = threadIdx.x;
    int rg = blockIdx.x & 15, b = blockIdx.x >> 4;

    for (int i = tid; i < 4096; i += 192) {
        int r = i >> 7, k = i & 127;
        int jg = (r >> 3) * 128 + rg * 8 + (r & 7);
        sWt[k][r] = Whh[jg * 128 + k];
    }
    int tr = tid & 7, tc = tid >> 3;
    int hh = tid / 24, nn = tid - hh * 24;
    int jrow = rg * 8 + hh;
    int scol = b * 24 + nn;
    float creg = 0.f;
    unsigned phase = 0;

    for (int t = 0; t < 32; t++) {
        if (t == 0) {
            for (int i = tid; i < 3200; i += 192) (&sH[0][0])[i] = 0.f;
            __syncthreads();
        } else {
            phase++;
            group_barrier(b, phase & 1u);
            const float* hb = g_h + ((t + 1) & 1) * 24576;
            for (int i = tid; i < 3072; i += 192) {
                int j = i / 24, n2 = i - j * 24;
                sH[j][n2] = __ldcg(hb + j * 192 + b * 24 + n2);
            }
            __syncthreads();
        }

        unsigned long long acc0 = 0ull, acc1 = 0ull;
#pragma unroll 8
        for (int k = 0; k < 128; k++) {
            ulonglong2 av = *(const ulonglong2*)&sWt[k][tr * 4];
            float bv = sH[k][tc];
            unsigned long long bs = pack2(bv, bv);
            ffma2(acc0, av.x, bs);
            ffma2(acc1, av.y, bs);
        }
        float2 u0 = unpack2(acc0), u1 = unpack2(acc1);
        sG[tr * 4 + 0][tc] = u0.x; sG[tr * 4 + 1][tc] = u0.y;
        sG[tr * 4 + 2][tc] = u1.x; sG[tr * 4 + 3][tc] = u1.y;
        __syncthreads();

        int colx = (b * 32 + t) * 24 + nn;
        float ig = sG[hh][nn]      + g_xg[(      jrow) * NCOLS + colx];
        float fg = sG[8 + hh][nn]  + g_xg[(128 + jrow) * NCOLS + colx];
        float gg = sG[16 + hh][nn] + g_xg[(256 + jrow) * NCOLS + colx];
        float og = sG[24 + hh][nn] + g_xg[(384 + jrow) * NCOLS + colx];
        creg = sigm(fg) * creg + sigm(ig) * tanhf(gg);
        float hnew = sigm(og) * tanhf(creg);
        __stcg(g_h + (t & 1) * 24576 + jrow * 192 + scol, hnew);
        g_hist[jrow * 6144 + t * 192 + scol] = hnew;
        __syncthreads();
    }
    phase++;
    group_barrier(b, phase & 1u);
}

// ------------ readout ------------
__global__ void __launch_bounds__(256) readout_k(const float* __restrict__ roW,
                                                 const float* __restrict__ rob,
                                                 const int* __restrict__ nnum,
                                                 float* __restrict__ out)
{
    __shared__ float sH[128][65];
    __shared__ float sRo[6][128];
    __shared__ float sRob[6];
    int tid = threadIdx.x;
    int c0 = blockIdx.x * 64;
    for (int i = tid; i < 8192; i += 256) {
        int j = i >> 6, cc = i & 63;
        sH[j][cc] = g_hist[j * 6144 + c0 + cc];
    }
    for (int i = tid; i < 768; i += 256) sRo[i >> 7][i & 127] = roW[i];
    if (tid < 6) sRob[tid] = rob[tid];
    __syncthreads();
    for (int e = tid; e < 384; e += 256) {
        int cc = e / 6, c = e - cc * 6;
        float s = 0.f;
#pragma unroll 8
        for (int j = 0; j < 128; j++) s += sRo[c][j] * sH[j][cc];
        int ct = c0 + cc;
        int t = ct / 192; int srem = ct - t * 192;
        int b = srem / 24; int n = srem - b * 24;
        int f = b * 32 + t;
        out[(f * 24 + n) * 6 + c] = (n < nnum[f]) ? (s + sRob[c]) : 0.f;
    }
}

// ------------ host launcher ------------
extern "C" void kernel_launch(void* const* d_in, const int* in_sizes, int n_in,
                              void* d_out, int out_size)
{
    const float* node     = (const float*)d_in[0];
    const float* edge     = (const float*)d_in[1];
    const float* link_W1  = (const float*)d_in[2];
    const float* link_b1  = (const float*)d_in[3];
    const float* link_W2  = (const float*)d_in[4];
    const float* link_b2  = (const float*)d_in[5];
    const float* msg_Wh   = (const float*)d_in[6];
    const float* msg_We   = (const float*)d_in[7];
    const float* msg_b    = (const float*)d_in[8];
    const float* gru_Wih  = (const float*)d_in[9];
    const float* gru_Whh  = (const float*)d_in[10];
    const float* gru_bih  = (const float*)d_in[11];
    const float* gru_bhh  = (const float*)d_in[12];
    const float* lstm_Wih = (const float*)d_in[13];
    const float* lstm_Whh = (const float*)d_in[14];
    const float* lstm_bih = (const float*)d_in[15];
    const float* lstm_bhh = (const float*)d_in[16];
    const float* ro_W     = (const float*)d_in[17];
    const float* ro_b     = (const float*)d_in[18];
    const int*   nnum     = (const int*)d_in[19];
    float* out = (float*)d_out;

    float* hnode; cudaGetSymbolAddress((void**)&hnode, g_hnode);
    float* hnC;   cudaGetSymbolAddress((void**)&hnC,   g_hnC);
    float* nhA;   cudaGetSymbolAddress((void**)&nhA,   g_nhA);
    float* nhB;   cudaGetSymbolAddress((void**)&nhB,   g_nhB);
    float* xg;    cudaGetSymbolAddress((void**)&xg,    g_xg);
    uint4* wA;    cudaGetSymbolAddress((void**)&wA,    g_wA4);
    float* gateA; cudaGetSymbolAddress((void**)&gateA, g_gateA);
    float* gateB; cudaGetSymbolAddress((void**)&gateB, g_gateB);

    static int inited = 0;
    static cudaStream_t s2;
    static cudaEvent_t eF[2], eJ[2];
    if (!inited) {
        cudaFuncSetAttribute(edge0_k, cudaFuncAttributeMaxDynamicSharedMemorySize, SM_EDGE);
        cudaFuncSetAttribute(recon_k, cudaFuncAttributeMaxDynamicSharedMemorySize, SM_EDGE);
        cudaFuncSetAttribute(hgemm_k, cudaFuncAttributeMaxDynamicSharedMemorySize, SM_HG);
        cudaFuncSetAttribute(gigh_k,  cudaFuncAttributeMaxDynamicSharedMemorySize, SM_HG);
        cudaStreamCreateWithFlags(&s2, cudaStreamNonBlocking);
        for (int i = 0; i < 2; i++) {
            cudaEventCreateWithFlags(&eF[i], cudaEventDisableTiming);
            cudaEventCreateWithFlags(&eJ[i], cudaEventDisableTiming);
        }
        inited = 1;
    }

    const int NTILE = 256 * 6;
    const int NCT   = NCOLS / 96;   // 64

    prefix_k<<<1, 256>>>(nnum);
    tr_node_k<<<(128 * NCOLS / 4) / 256, 256>>>(node);
    prep_a_k<<<72, 256>>>(link_W1, msg_We, msg_Wh, wA);
    prep_b_k<<<240, 256>>>(gru_Wih, gru_Whh, lstm_Wih, wA);
    compact_edge_k<<<2048, 256>>>(edge, nnum);
    hgemm_k<<<dim3(NCT, 1), 256, SM_HG>>>(wA + 12288, hnC, nullptr, nullptr, nhA, NCOLS, 1);
    edge0_k<<<NTILE, 256, SM_EDGE>>>(link_b1, link_W2, link_b2, msg_b, nnum, gateA);

    float* gbuf[2]  = {gateA, gateB};
    float* nhbuf[2] = {nhA, nhB};
    for (int p = 0; p < 3; p++) {
        float* gin  = gbuf[p & 1];
        float* gout = gbuf[(p + 1) & 1];
        float* nhp  = nhbuf[p & 1];
        float* nhn  = nhbuf[(p + 1) & 1];
        if (p > 0) cudaStreamWaitEvent(0, eJ[p - 1], 0);
        if (p < 2) {
            // fork: recon_p runs concurrently with the node chain
            cudaEventRecord(eF[p], 0);
            cudaStreamWaitEvent(s2, eF[p], 0);
            recon_k<<<NTILE, 256, SM_EDGE, s2>>>(link_b1, link_W2, link_b2, nnum,
                                                 gin, gout, nhp);
            cudaEventRecord(eJ[p], s2);
        }
        mv_k<<<1024, 256>>>(nnum, gin, nhp);
        gigh_k<<<dim3(NCT, 6), 256, SM_HG>>>(wA);
        gru_k<<<(128 * NCOLS) / 256, 256>>>(gru_bih, gru_bhh);
        if (p < 2)
            hgemm_k<<<dim3(NCT, 1), 256, SM_HG>>>(wA + 12288, hnC, nullptr, nullptr,
                                                  nhn, NCOLS, 1);
    }

    hgemm_k<<<dim3(NCT, 4), 256, SM_HG>>>(wA + 55296, hnode, lstm_bih, lstm_bhh, xg, NCOLS, 0);
    lstm_all_k<<<128, 192>>>(lstm_Whh);
    readout_k<<<96, 256>>>(ro_W, ro_b, nnum, out);
    (void)in_sizes; (void)n_in; (void)out_size;
}

// round 17
// speedup vs baseline: 2.0128x; 1.0501x over previous
#include <cuda_runtime.h>
#include <cuda_bf16.h>
#include <math.h>
#include <stdint.h>

// ------------ problem constants ------------
#define NFRM   256                  // B*T
#define ECOLS  147456               // NFRM * 576 edge columns
#define NCOLS  6144                 // NFRM * 24 node columns

// ------------ device scratch ------------
__device__ float g_edge_c[128 * ECOLS];   // compacted edge [d][f*576 + c], padding zeroed
__device__ float g_epre  [128 * ECOLS];   // msg_We @ edge + msg_b, COMPACT per frame
__device__ float g_gateA [ECOLS];
__device__ float g_gateB [ECOLS];
__device__ float g_hnC   [128 * NCOLS];   // COMPACT hnode
__device__ float g_nhA   [128 * NCOLS];   // COMPACT nh double buffer
__device__ float g_nhB   [128 * NCOLS];
__device__ float g_mv    [128 * NCOLS];   // COMPACT
__device__ float g_gi    [384 * NCOLS];   // COMPACT
__device__ float g_gh    [384 * NCOLS];   // COMPACT
__device__ float g_xg    [512 * NCOLS];   // dense cols; only valid cols ever read downstream
__device__ float g_h     [2 * 128 * 192];
__device__ float g_hist  [128 * 6144];
__device__ int   g_cpre  [257];
__device__ int   g_colf  [NCOLS];
__device__ int   g_nccg  [1];
__device__ unsigned g_cnt2[8];
__device__ unsigned g_sense2[8];
__device__ uint4 g_wA4[79872];

__device__ __forceinline__ float sigm(float x) { return 1.f / (1.f + expf(-x)); }

__device__ __forceinline__ void ffma2(unsigned long long& acc,
                                      unsigned long long a, unsigned long long b) {
    asm("fma.rn.f32x2 %0, %1, %2, %0;" : "+l"(acc) : "l"(a), "l"(b));
}
__device__ __forceinline__ unsigned long long pack2(float x, float y) {
    unsigned long long r;
    asm("mov.b64 %0, {%1, %2};" : "=l"(r) : "f"(x), "f"(y));
    return r;
}
__device__ __forceinline__ float2 unpack2(unsigned long long v) {
    float2 f;
    asm("mov.b64 {%0, %1}, %2;" : "=f"(f.x), "=f"(f.y) : "l"(v));
    return f;
}
__device__ __forceinline__ void split_bf(float x, __nv_bfloat16& h, __nv_bfloat16& l) {
    h = __float2bfloat16(x);
    l = __float2bfloat16(x - __bfloat162float(h));
}
__device__ __forceinline__ void split_pair(float x0, float x1, unsigned& hw, unsigned& lw) {
    __nv_bfloat16 h0, l0, h1, l1;
    split_bf(x0, h0, l0); split_bf(x1, h1, l1);
    hw = (unsigned)__bfloat16_as_ushort(h0) | ((unsigned)__bfloat16_as_ushort(h1) << 16);
    lw = (unsigned)__bfloat16_as_ushort(l0) | ((unsigned)__bfloat16_as_ushort(l1) << 16);
}
__device__ __forceinline__ uint32_t smem_to_u32(const void* p) {
    uint32_t a;
    asm("{ .reg .u64 t; cvta.to.shared.u64 t, %1; cvt.u32.u64 %0, t; }" : "=r"(a) : "l"(p));
    return a;
}

// ---- HMMA m16n8k16 bf16 ----
__device__ __forceinline__ void mma_bf16(float* c, uint32_t a0, uint32_t a1,
                                         uint32_t a2, uint32_t a3,
                                         uint32_t b0, uint32_t b1) {
    asm volatile(
        "mma.sync.aligned.m16n8k16.row.col.f32.bf16.bf16.f32 "
        "{%0,%1,%2,%3}, {%4,%5,%6,%7}, {%8,%9}, {%0,%1,%2,%3};"
        : "+f"(c[0]), "+f"(c[1]), "+f"(c[2]), "+f"(c[3])
        : "r"(a0), "r"(a1), "r"(a2), "r"(a3), "r"(b0), "r"(b1));
}

#define BPITCH_W  132
#define BPITCH_B  528
#define SNH_OFF   50688     // float[128*24]
#define SG_OFF    62976     // float[96]
#define SRED_OFF  63360     // float[8][52]
#define SM_EDGE   66688
#define SM_HG     50688

// ------------ prefix ------------
__global__ void __launch_bounds__(256) prefix_k(const int* __restrict__ nnum)
{
    __shared__ int sc[256];
    int f = threadIdx.x;
    int c = nnum[f];
    sc[f] = c;
    __syncthreads();
    if (f == 0) {
        int acc = 0;
        for (int i = 0; i < 256; i++) { g_cpre[i] = acc; acc += sc[i]; }
        g_cpre[256] = acc;
        g_nccg[0] = acc;
    }
    __syncthreads();
    int base = g_cpre[f];
    for (int n = 0; n < c; n++) g_colf[base + n] = f * 24 + n;
}

// ------------ compact_edge ------------
__global__ void __launch_bounds__(256) compact_edge_k(const float* __restrict__ edge,
                                                      const int* __restrict__ nnum)
{
    __shared__ int sidx[576];
    int f = blockIdx.x >> 3, dg = blockIdx.x & 7;
    int cnt = nnum[f]; int NV = cnt * cnt;
    int NVp = ((NV + 95) / 96) * 96; if (NVp > 576) NVp = 576;
    int tid = threadIdx.x;
    for (int c = tid; c < NV; c += 256) {
        int v = c / cnt;
        sidx[c] = v * 24 + (c - v * cnt);
    }
    __syncthreads();
    int tot = 16 * NVp;
    for (int i = tid; i < tot; i += 256) {
        int dl = i / NVp, c = i - dl * NVp;
        int d = dg * 16 + dl;
        float val = 0.f;
        if (c < NV) val = edge[(size_t)f * 73728 + d * 576 + sidx[c]];
        g_edge_c[(size_t)d * ECOLS + f * 576 + c] = val;
    }
}

// ------------ prep (all weights, one launch) ------------
__device__ __forceinline__ void prep_one(const float* __restrict__ W, uint4* __restrict__ out,
                                         int gidx)
{
    int mblk = gidx / 768;
    int rem  = gidx - mblk * 768;
    int kk   = rem >> 5;
    int lane = rem & 31;
    int g = lane >> 2, t = lane & 3;
    unsigned regs[4];
#pragma unroll
    for (int r = 0; r < 4; r++) {
        int row = mblk * 16 + g + ((r & 1) ? 8 : 0);
        int k0  = kk * 16 + t * 2 + ((r & 2) ? 8 : 0);
        unsigned pk = 0;
#pragma unroll
        for (int e = 0; e < 2; e++) {
            int ks = k0 + e;
            int region = ks >> 7;
            int kloc = ks & 127;
            float w = W[row * 128 + kloc];
            __nv_bfloat16 h, l; split_bf(w, h, l);
            __nv_bfloat16 b = (region < 2) ? h : l;
            pk |= (unsigned)__bfloat16_as_ushort(b) << (e * 16);
        }
        regs[r] = pk;
    }
    out[gidx] = make_uint4(regs[0], regs[1], regs[2], regs[3]);
}

__global__ void __launch_bounds__(256) prep_all_k(const float* __restrict__ w1,
                                                  const float* __restrict__ we,
                                                  const float* __restrict__ wh,
                                                  const float* __restrict__ wih,
                                                  const float* __restrict__ whh,
                                                  const float* __restrict__ lih,
                                                  uint4* __restrict__ out)
{
    int b = blockIdx.x;
    if (b < 24)       prep_one(w1,  out,          b * 256 + threadIdx.x);
    else if (b < 48)  prep_one(we,  out + 6144,  (b - 24) * 256 + threadIdx.x);
    else if (b < 72)  prep_one(wh,  out + 12288, (b - 48) * 256 + threadIdx.x);
    else if (b < 144) prep_one(wih, out + 18432, (b - 72) * 256 + threadIdx.x);
    else if (b < 216) prep_one(whh, out + 36864, (b - 144) * 256 + threadIdx.x);
    else              prep_one(lih, out + 55296, (b - 216) * 256 + threadIdx.x);
}

// ------------ warp GEMM m32 x n48 ------------
__device__ __forceinline__ void gemm_m32(float c[2][6][4], const uint4* __restrict__ A4,
                                         uint32_t sbAddr, int lane, int nh)
{
    int midx = lane >> 3, row = lane & 7;
    uint32_t base0 = sbAddr +
        (uint32_t)((nh * 48 + ((midx >> 1) << 3) + row) * BPITCH_B + (midx & 1) * 16);
#pragma unroll
    for (int mb = 0; mb < 2; mb++)
#pragma unroll
        for (int nt = 0; nt < 6; nt++)
#pragma unroll
            for (int r = 0; r < 4; r++) c[mb][nt][r] = 0.f;

#pragma unroll 4
    for (int kk2 = 0; kk2 < 8; kk2++) {
        uint4 a0 = A4[kk2 * 32 + lane];
        uint4 a1 = A4[768 + kk2 * 32 + lane];
        uint32_t r[12];
#pragma unroll
        for (int j2 = 0; j2 < 3; j2++) {
            asm volatile("ldmatrix.sync.aligned.m8n8.x4.shared.b16 {%0,%1,%2,%3}, [%4];"
                         : "=r"(r[4 * j2]), "=r"(r[4 * j2 + 1]),
                           "=r"(r[4 * j2 + 2]), "=r"(r[4 * j2 + 3])
                         : "r"(base0 + (uint32_t)(j2 * 16 * BPITCH_B + kk2 * 32)));
        }
#pragma unroll
        for (int j2 = 0; j2 < 3; j2++) {
            mma_bf16(c[0][2 * j2],     a0.x, a0.y, a0.z, a0.w, r[4 * j2],     r[4 * j2 + 1]);
            mma_bf16(c[0][2 * j2 + 1], a0.x, a0.y, a0.z, a0.w, r[4 * j2 + 2], r[4 * j2 + 3]);
            mma_bf16(c[1][2 * j2],     a1.x, a1.y, a1.z, a1.w, r[4 * j2],     r[4 * j2 + 1]);
            mma_bf16(c[1][2 * j2 + 1], a1.x, a1.y, a1.z, a1.w, r[4 * j2 + 2], r[4 * j2 + 3]);
        }
#pragma unroll
        for (int j2 = 0; j2 < 3; j2++) {
            asm volatile("ldmatrix.sync.aligned.m8n8.x4.shared.b16 {%0,%1,%2,%3}, [%4];"
                         : "=r"(r[4 * j2]), "=r"(r[4 * j2 + 1]),
                           "=r"(r[4 * j2 + 2]), "=r"(r[4 * j2 + 3])
                         : "r"(base0 + (uint32_t)(j2 * 16 * BPITCH_B + (kk2 + 8) * 32)));
        }
#pragma unroll
        for (int j2 = 0; j2 < 3; j2++) {
            mma_bf16(c[0][2 * j2],     a0.x, a0.y, a0.z, a0.w, r[4 * j2],     r[4 * j2 + 1]);
            mma_bf16(c[0][2 * j2 + 1], a0.x, a0.y, a0.z, a0.w, r[4 * j2 + 2], r[4 * j2 + 3]);
            mma_bf16(c[1][2 * j2],     a1.x, a1.y, a1.z, a1.w, r[4 * j2],     r[4 * j2 + 1]);
            mma_bf16(c[1][2 * j2 + 1], a1.x, a1.y, a1.z, a1.w, r[4 * j2 + 2], r[4 * j2 + 3]);
        }
    }
#pragma unroll 4
    for (int kk2 = 0; kk2 < 8; kk2++) {
        uint4 a0 = A4[(16 + kk2) * 32 + lane];
        uint4 a1 = A4[768 + (16 + kk2) * 32 + lane];
        uint32_t r[12];
#pragma unroll
        for (int j2 = 0; j2 < 3; j2++) {
            asm volatile("ldmatrix.sync.aligned.m8n8.x4.shared.b16 {%0,%1,%2,%3}, [%4];"
                         : "=r"(r[4 * j2]), "=r"(r[4 * j2 + 1]),
                           "=r"(r[4 * j2 + 2]), "=r"(r[4 * j2 + 3])
                         : "r"(base0 + (uint32_t)(j2 * 16 * BPITCH_B + kk2 * 32)));
        }
#pragma unroll
        for (int j2 = 0; j2 < 3; j2++) {
            mma_bf16(c[0][2 * j2],     a0.x, a0.y, a0.z, a0.w, r[4 * j2],     r[4 * j2 + 1]);
            mma_bf16(c[0][2 * j2 + 1], a0.x, a0.y, a0.z, a0.w, r[4 * j2 + 2], r[4 * j2 + 3]);
            mma_bf16(c[1][2 * j2],     a1.x, a1.y, a1.z, a1.w, r[4 * j2],     r[4 * j2 + 1]);
            mma_bf16(c[1][2 * j2 + 1], a1.x, a1.y, a1.z, a1.w, r[4 * j2 + 2], r[4 * j2 + 3]);
        }
    }
}

// ------------ gate epilogue ------------
__device__ __forceinline__ void gate_epi32(float c[2][6][4], char* smem,
                                           const float* __restrict__ lb1,
                                           const float* __restrict__ W2,
                                           const float* __restrict__ b2p,
                                           float* __restrict__ gate_out, int base)
{
    int tid = threadIdx.x;
    int w = tid >> 5, lane = tid & 31;
    int mp = w & 3;
    int g = lane >> 2, t = lane & 3;
    float* sRed = (float*)(smem + SRED_OFF);

    float p0[6], p1[6];
#pragma unroll
    for (int j = 0; j < 6; j++) { p0[j] = 0.f; p1[j] = 0.f; }
#pragma unroll
    for (int mb = 0; mb < 2; mb++) {
        int r0 = mp * 32 + mb * 16 + g;
        float bb0 = lb1[r0], bb8 = lb1[r0 + 8];
        float w0 = W2[r0], w8 = W2[r0 + 8];
#pragma unroll
        for (int j = 0; j < 6; j++) {
            p0[j] += fmaxf(c[mb][j][0] + bb0, 0.f) * w0 + fmaxf(c[mb][j][2] + bb8, 0.f) * w8;
            p1[j] += fmaxf(c[mb][j][1] + bb0, 0.f) * w0 + fmaxf(c[mb][j][3] + bb8, 0.f) * w8;
        }
    }
#pragma unroll
    for (int j = 0; j < 6; j++) {
#pragma unroll
        for (int m = 4; m <= 16; m <<= 1) {
            p0[j] += __shfl_xor_sync(0xffffffffu, p0[j], m);
            p1[j] += __shfl_xor_sync(0xffffffffu, p1[j], m);
        }
    }
    if (g == 0) {
#pragma unroll
        for (int j = 0; j < 6; j++) {
            sRed[w * 52 + j * 8 + t * 2]     = p0[j];
            sRed[w * 52 + j * 8 + t * 2 + 1] = p1[j];
        }
    }
    __syncthreads();
    if (tid < 96) {
        int nh2 = tid / 48, nn = tid - nh2 * 48;
        float s = sRed[(nh2 * 4 + 0) * 52 + nn] + sRed[(nh2 * 4 + 1) * 52 + nn]
                + sRed[(nh2 * 4 + 2) * 52 + nn] + sRed[(nh2 * 4 + 3) * 52 + nn];
        gate_out[base + tid] = sigm(s + b2p[0]);
    }
}

// ------------ edge0_k ------------
__global__ void __launch_bounds__(256, 3) edge0_k(const float* __restrict__ lb1,
                                                  const float* __restrict__ W2,
                                                  const float* __restrict__ b2p,
                                                  const float* __restrict__ msg_b,
                                                  const int* __restrict__ nnum,
                                                  float* __restrict__ gate_out)
{
    extern __shared__ char smem[];
    uint32_t sbAddr = smem_to_u32(smem);
    unsigned* sBw = (unsigned*)smem;
    int tid = threadIdx.x;
    int bx = blockIdx.x;
    int f = bx / 6; int tt = bx - f * 6;
    int cnt = nnum[f]; int NV = cnt * cnt;
    int cb = tt * 96;
    if (cb >= NV) return;
    int base = f * 576 + cb;

    {
        int q = tid >> 6, dp = tid & 63;
        const float* s0 = g_edge_c + (size_t)(2 * dp) * ECOLS + base + q * 24;
        const float* s1 = s0 + ECOLS;
        for (int i = 0; i < 24; i += 4) {
            float4 x0 = *(const float4*)(s0 + i);
            float4 x1 = *(const float4*)(s1 + i);
            float a0[4] = {x0.x, x0.y, x0.z, x0.w};
            float a1[4] = {x1.x, x1.y, x1.z, x1.w};
#pragma unroll
            for (int j = 0; j < 4; j++) {
                int n = q * 24 + i + j;
                unsigned hw, lw; split_pair(a0[j], a1[j], hw, lw);
                sBw[n * BPITCH_W + dp]      = hw;
                sBw[n * BPITCH_W + 64 + dp] = lw;
            }
        }
    }
    __syncthreads();

    int w = tid >> 5, lane = tid & 31;
    int mp = w & 3, nh = w >> 2;
    int g = lane >> 2, t = lane & 3;
    float c[2][6][4];

    gemm_m32(c, g_wA4 + (2 * mp) * 768, sbAddr, lane, nh);
    gate_epi32(c, smem, lb1, W2, b2p, gate_out, base);
    __syncthreads();

    gemm_m32(c, g_wA4 + 6144 + (2 * mp) * 768, sbAddr, lane, nh);
#pragma unroll
    for (int mb = 0; mb < 2; mb++) {
        int r0 = mp * 32 + mb * 16 + g;
        float mb0 = msg_b[r0], mb8 = msg_b[r0 + 8];
#pragma unroll
        for (int j = 0; j < 6; j++) {
            int col = base + nh * 48 + j * 8 + t * 2;
            *(float2*)(g_epre + (size_t)r0 * ECOLS + col) =
                make_float2(c[mb][j][0] + mb0, c[mb][j][1] + mb0);
            *(float2*)(g_epre + (size_t)(r0 + 8) * ECOLS + col) =
                make_float2(c[mb][j][2] + mb8, c[mb][j][3] + mb8);
        }
    }
}

// ------------ recon_k ------------
__global__ void __launch_bounds__(256, 3) recon_k(const float* __restrict__ lb1,
                                                  const float* __restrict__ W2,
                                                  const float* __restrict__ b2p,
                                                  const int* __restrict__ nnum,
                                                  const float* __restrict__ gate_in,
                                                  float* __restrict__ gate_out,
                                                  const float* __restrict__ nhbuf)
{
    extern __shared__ char smem[];
    uint32_t sbAddr = smem_to_u32(smem);
    unsigned* sBw = (unsigned*)smem;
    float* snh = (float*)(smem + SNH_OFF);
    float* sg  = (float*)(smem + SG_OFF);
    __shared__ int ssw[96];
    int tid = threadIdx.x;
    int bx = blockIdx.x;
    int f = bx / 6; int tt = bx - f * 6;
    int cnt = nnum[f]; int NV = cnt * cnt;
    int cb = tt * 96;
    if (cb >= NV) return;
    int base = f * 576 + cb;
    int cp = g_cpre[f];

    for (int i = tid; i < 3072; i += 256) {
        int d = i / 24, w = i - d * 24;
        snh[i] = (w < cnt) ? nhbuf[d * NCOLS + cp + w] : 0.f;
    }
    if (tid < 96) {
        sg[tid] = gate_in[base + tid];
        int c = cb + tid;
        int v = c / cnt;
        ssw[tid] = c - v * cnt;
    }
    __syncthreads();

    {
        int q = tid >> 6, dp = tid & 63;
        int d0 = 2 * dp, d1 = d0 + 1;
        const float* s0 = g_epre + (size_t)d0 * ECOLS + base + q * 24;
        const float* s1 = s0 + ECOLS;
        int n0 = q * 24;
        for (int i = 0; i < 24; i += 4) {
            float4 x0 = *(const float4*)(s0 + i);
            float4 x1 = *(const float4*)(s1 + i);
            float a0[4] = {x0.x, x0.y, x0.z, x0.w};
            float a1[4] = {x1.x, x1.y, x1.z, x1.w};
#pragma unroll
            for (int j = 0; j < 4; j++) {
                int nn = n0 + i + j;
                float v0 = 0.f, v1 = 0.f;
                if (cb + nn < NV) {
                    int w = ssw[nn];
                    float gv = sg[nn];
                    v0 = gv * fmaxf(snh[d0 * 24 + w] + a0[j], 0.f);
                    v1 = gv * fmaxf(snh[d1 * 24 + w] + a1[j], 0.f);
                }
                unsigned hw, lw; split_pair(v0, v1, hw, lw);
                sBw[nn * BPITCH_W + dp]      = hw;
                sBw[nn * BPITCH_W + 64 + dp] = lw;
            }
        }
    }
    __syncthreads();

    int w = tid >> 5, lane = tid & 31;
    int mp = w & 3, nh = w >> 2;
    float c[2][6][4];
    gemm_m32(c, g_wA4 + (2 * mp) * 768, sbAddr, lane, nh);
    gate_epi32(c, smem, lb1, W2, b2p, gate_out, base);
}

// ------------ mv_k ------------
__global__ void __launch_bounds__(256) mv_k(const int* __restrict__ nnum,
                                            const float* __restrict__ gate_in,
                                            const float* __restrict__ nhbuf)
{
    __shared__ float snh[32 * 24];
    __shared__ float sg[576];
    int f = blockIdx.x >> 2, dg = blockIdx.x & 3;
    int cnt = nnum[f];
    int NV = cnt * cnt;
    int cp = g_cpre[f];
    int tid = threadIdx.x;
    for (int i = tid; i < 768; i += 256) {
        int d = i / 24, w = i - d * 24;
        snh[i] = (w < cnt) ? nhbuf[(dg * 32 + d) * NCOLS + cp + w] : 0.f;
    }
    for (int i = tid; i < NV; i += 256) sg[i] = gate_in[f * 576 + i];
    __syncthreads();

    for (int p = tid; p < 768; p += 256) {
        int dl = p / 24, v = p - dl * 24;
        int d = dg * 32 + dl;
        if (v < cnt) {
            const float* ep = g_epre + (size_t)d * ECOLS + f * 576 + v * cnt;
            const float* gp = sg + v * cnt;
            const float* np = snh + dl * 24;
            float s = 0.f;
            for (int w = 0; w < cnt; w++)
                s += gp[w] * fmaxf(np[w] + ep[w], 0.f);
            g_mv[d * NCOLS + cp + v] = s;
        }
    }
}

// ------------ shared hgemm body ------------
__device__ __forceinline__ void hgemm_body(const uint4* __restrict__ Afrag, int mrowblk,
                                           const float* __restrict__ X,
                                           const float* __restrict__ bias,
                                           const float* __restrict__ bias2,
                                           float* __restrict__ Y, int cols, int c0,
                                           char* smem, uint32_t sbAddr)
{
    unsigned* sBw = (unsigned*)smem;
    int tid = threadIdx.x;
    {
        int q = tid >> 6, dp = tid & 63;
        const float* s0 = X + (size_t)(2 * dp) * cols + c0 + q * 24;
        const float* s1 = s0 + cols;
        for (int i = 0; i < 24; i += 4) {
            float4 x0 = *(const float4*)(s0 + i);
            float4 x1 = *(const float4*)(s1 + i);
            float a0[4] = {x0.x, x0.y, x0.z, x0.w};
            float a1[4] = {x1.x, x1.y, x1.z, x1.w};
#pragma unroll
            for (int j = 0; j < 4; j++) {
                int n = q * 24 + i + j;
                unsigned hw, lw; split_pair(a0[j], a1[j], hw, lw);
                sBw[n * BPITCH_W + dp]      = hw;
                sBw[n * BPITCH_W + 64 + dp] = lw;
            }
        }
    }
    __syncthreads();

    int w = tid >> 5, lane = tid & 31;
    int mp = w & 3, nh = w >> 2;
    int g = lane >> 2, t = lane & 3;
    float c[2][6][4];
    gemm_m32(c, Afrag + (mrowblk * 8 + 2 * mp) * 768, sbAddr, lane, nh);

#pragma unroll
    for (int mb = 0; mb < 2; mb++) {
        int r0 = mrowblk * 128 + mp * 32 + mb * 16 + g;
        float b0v = (bias ? bias[r0] : 0.f) + (bias2 ? bias2[r0] : 0.f);
        float b8v = (bias ? bias[r0 + 8] : 0.f) + (bias2 ? bias2[r0 + 8] : 0.f);
#pragma unroll
        for (int j = 0; j < 6; j++) {
            int col = c0 + nh * 48 + j * 8 + t * 2;
            *(float2*)(Y + (size_t)r0 * cols + col) =
                make_float2(c[mb][j][0] + b0v, c[mb][j][1] + b0v);
            *(float2*)(Y + (size_t)(r0 + 8) * cols + col) =
                make_float2(c[mb][j][2] + b8v, c[mb][j][3] + b8v);
        }
    }
}

__global__ void __launch_bounds__(256, 3) hgemm_k(const uint4* __restrict__ Afrag,
                                                  const float* __restrict__ X,
                                                  const float* __restrict__ bias,
                                                  const float* __restrict__ bias2,
                                                  float* __restrict__ Y, int cols,
                                                  int use_compact)
{
    extern __shared__ char smem[];
    int c0 = blockIdx.x * 96;
    if (use_compact && c0 >= g_nccg[0]) return;
    hgemm_body(Afrag, blockIdx.y, X, bias, bias2, Y, cols, c0,
               smem, smem_to_u32(smem));
}

__global__ void __launch_bounds__(256, 3) gigh_k(const uint4* __restrict__ wA)
{
    extern __shared__ char smem[];
    int c0 = blockIdx.x * 96;
    if (c0 >= g_nccg[0]) return;
    int by = blockIdx.y;
    if (by < 3)
        hgemm_body(wA + 18432, by, g_mv, nullptr, nullptr, g_gi, NCOLS,
                   c0, smem, smem_to_u32(smem));
    else
        hgemm_body(wA + 36864, by - 3, g_hnC, nullptr, nullptr, g_gh, NCOLS,
                   c0, smem, smem_to_u32(smem));
}

// ------------ xg_k: compact LSTM input projection, scatter to dense columns ------------
__global__ void __launch_bounds__(256, 3) xg_k(const uint4* __restrict__ Afrag,
                                               const float* __restrict__ bias,
                                               const float* __restrict__ bias2)
{
    extern __shared__ char smem[];
    uint32_t sbAddr = smem_to_u32(smem);
    unsigned* sBw = (unsigned*)smem;
    int c0 = blockIdx.x * 96;
    if (c0 >= g_nccg[0]) return;
    int mrowblk = blockIdx.y;
    int tid = threadIdx.x;

    {
        int q = tid >> 6, dp = tid & 63;
        const float* s0 = g_hnC + (size_t)(2 * dp) * NCOLS + c0 + q * 24;
        const float* s1 = s0 + NCOLS;
        for (int i = 0; i < 24; i += 4) {
            float4 x0 = *(const float4*)(s0 + i);
            float4 x1 = *(const float4*)(s1 + i);
            float a0[4] = {x0.x, x0.y, x0.z, x0.w};
            float a1[4] = {x1.x, x1.y, x1.z, x1.w};
#pragma unroll
            for (int j = 0; j < 4; j++) {
                int n = q * 24 + i + j;
                unsigned hw, lw; split_pair(a0[j], a1[j], hw, lw);
                sBw[n * BPITCH_W + dp]      = hw;
                sBw[n * BPITCH_W + 64 + dp] = lw;
            }
        }
    }
    __syncthreads();

    int w = tid >> 5, lane = tid & 31;
    int mp = w & 3, nh = w >> 2;
    int g = lane >> 2, t = lane & 3;
    float c[2][6][4];
    gemm_m32(c, Afrag + (mrowblk * 8 + 2 * mp) * 768, sbAddr, lane, nh);

#pragma unroll
    for (int mb = 0; mb < 2; mb++) {
        int r0 = mrowblk * 128 + mp * 32 + mb * 16 + g;
        float b0v = bias[r0] + bias2[r0];
        float b8v = bias[r0 + 8] + bias2[r0 + 8];
#pragma unroll
        for (int j = 0; j < 6; j++) {
            int col = c0 + nh * 48 + j * 8 + t * 2;
            if (col < g_nccg[0]) {
                int d0 = g_colf[col];
                int d1 = (col + 1 < g_nccg[0]) ? g_colf[col + 1] : d0;
                g_xg[(size_t)r0 * NCOLS + d0]       = c[mb][j][0] + b0v;
                g_xg[(size_t)(r0 + 8) * NCOLS + d0] = c[mb][j][2] + b8v;
                if (col + 1 < g_nccg[0]) {
                    g_xg[(size_t)r0 * NCOLS + d1]       = c[mb][j][1] + b0v;
                    g_xg[(size_t)(r0 + 8) * NCOLS + d1] = c[mb][j][3] + b8v;
                }
            }
        }
    }
}

// ------------ node transpose (compact hnC only) ------------
__global__ void __launch_bounds__(256) tr_node_k(const float* __restrict__ in)
{
    int o4 = blockIdx.x * 256 + threadIdx.x;
    int d = o4 / 1536; int c4 = o4 - d * 1536;
    int f = c4 / 6;    int n4 = c4 - f * 6;
    float4 v = *(const float4*)(in + f * 3072 + d * 24 + n4 * 4);
    int cp = g_cpre[f];
    int cnt = g_cpre[f + 1] - cp;
    float vs[4] = {v.x, v.y, v.z, v.w};
#pragma unroll
    for (int j = 0; j < 4; j++) {
        int n = n4 * 4 + j;
        if (n < cnt) g_hnC[d * NCOLS + cp + n] = vs[j];
    }
}

// ------------ GRU elementwise (compact only) ------------
__global__ void __launch_bounds__(256) gru_k(const float* __restrict__ bih,
                                             const float* __restrict__ bhh)
{
    int idx = blockIdx.x * 256 + threadIdx.x;
    int j = idx / NCOLS; int cc = idx - j * NCOLS;
    if (cc >= g_nccg[0]) return;
    float gir = g_gi[j * NCOLS + cc]         + bih[j];
    float giz = g_gi[(128 + j) * NCOLS + cc] + bih[128 + j];
    float gin = g_gi[(256 + j) * NCOLS + cc] + bih[256 + j];
    float ghr = g_gh[j * NCOLS + cc]         + bhh[j];
    float ghz = g_gh[(128 + j) * NCOLS + cc] + bhh[128 + j];
    float ghn = g_gh[(256 + j) * NCOLS + cc] + bhh[256 + j];
    float r = sigm(gir + ghr);
    float z = sigm(giz + ghz);
    float n2 = tanhf(gin + r * ghn);
    float h = g_hnC[j * NCOLS + cc];
    g_hnC[j * NCOLS + cc] = (1.f - z) * n2 + z * h;
}

// ------------ persistent LSTM ------------
__device__ __forceinline__ void group_barrier(int b, unsigned want)
{
    __threadfence();
    __syncthreads();
    if (threadIdx.x == 0) {
        unsigned tk = atomicAdd(&g_cnt2[b], 1u);
        if (tk == 15u) {
            g_cnt2[b] = 0;
            __threadfence();
            atomicExch(&g_sense2[b], want);
        } else {
            unsigned v;
            do {
                asm volatile("ld.acquire.gpu.u32 %0, [%1];" : "=r"(v) : "l"(&g_sense2[b]));
            } while (v != want);
        }
    }
    __syncthreads();
}

__global__ void __launch_bounds__(192) lstm_all_k(const float* __restrict__ Whh)
{
    __shared__ __align__(16) float sWt[128][36];
    __shared__ float sH[128][25];
    __shared__ float sG[32][25];
    int tid = threadIdx.x;
    int rg = blockIdx.x & 15, b = blockIdx.x >> 4;

    for (int i = tid; i < 4096; i += 192) {
        int r = i >> 7, k = i & 127;
        int jg = (r >> 3) * 128 + rg * 8 + (r & 7);
        sWt[k][r] = Whh[jg * 128 + k];
    }
    int tr = tid & 7, tc = tid >> 3;
    int hh = tid / 24, nn = tid - hh * 24;
    int jrow = rg * 8 + hh;
    int scol = b * 24 + nn;
    float creg = 0.f;
    unsigned phase = 0;

    for (int t = 0; t < 32; t++) {
        if (t == 0) {
            for (int i = tid; i < 3200; i += 192) (&sH[0][0])[i] = 0.f;
            __syncthreads();
        } else {
            phase++;
            group_barrier(b, phase & 1u);
            const float* hb = g_h + ((t + 1) & 1) * 24576;
            for (int i = tid; i < 3072; i += 192) {
                int j = i / 24, n2 = i - j * 24;
                sH[j][n2] = __ldcg(hb + j * 192 + b * 24 + n2);
            }
            __syncthreads();
        }

        unsigned long long acc0 = 0ull, acc1 = 0ull;
#pragma unroll 8
        for (int k = 0; k < 128; k++) {
            ulonglong2 av = *(const ulonglong2*)&sWt[k][tr * 4];
            float bv = sH[k][tc];
            unsigned long long bs = pack2(bv, bv);
            ffma2(acc0, av.x, bs);
            ffma2(acc1, av.y, bs);
        }
        float2 u0 = unpack2(acc0), u1 = unpack2(acc1);
        sG[tr * 4 + 0][tc] = u0.x; sG[tr * 4 + 1][tc] = u0.y;
        sG[tr * 4 + 2][tc] = u1.x; sG[tr * 4 + 3][tc] = u1.y;
        __syncthreads();

        int colx = (b * 32 + t) * 24 + nn;
        float ig = sG[hh][nn]      + g_xg[(      jrow) * NCOLS + colx];
        float fg = sG[8 + hh][nn]  + g_xg[(128 + jrow) * NCOLS + colx];
        float gg = sG[16 + hh][nn] + g_xg[(256 + jrow) * NCOLS + colx];
        float og = sG[24 + hh][nn] + g_xg[(384 + jrow) * NCOLS + colx];
        creg = sigm(fg) * creg + sigm(ig) * tanhf(gg);
        float hnew = sigm(og) * tanhf(creg);
        __stcg(g_h + (t & 1) * 24576 + jrow * 192 + scol, hnew);
        g_hist[jrow * 6144 + t * 192 + scol] = hnew;
        __syncthreads();
    }
    phase++;
    group_barrier(b, phase & 1u);
}

// ------------ readout ------------
__global__ void __launch_bounds__(256) readout_k(const float* __restrict__ roW,
                                                 const float* __restrict__ rob,
                                                 const int* __restrict__ nnum,
                                                 float* __restrict__ out)
{
    __shared__ float sH[128][65];
    __shared__ float sRo[6][128];
    __shared__ float sRob[6];
    int tid = threadIdx.x;
    int c0 = blockIdx.x * 64;
    for (int i = tid; i < 8192; i += 256) {
        int j = i >> 6, cc = i & 63;
        sH[j][cc] = g_hist[j * 6144 + c0 + cc];
    }
    for (int i = tid; i < 768; i += 256) sRo[i >> 7][i & 127] = roW[i];
    if (tid < 6) sRob[tid] = rob[tid];
    __syncthreads();
    for (int e = tid; e < 384; e += 256) {
        int cc = e / 6, c = e - cc * 6;
        float s = 0.f;
#pragma unroll 8
        for (int j = 0; j < 128; j++) s += sRo[c][j] * sH[j][cc];
        int ct = c0 + cc;
        int t = ct / 192; int srem = ct - t * 192;
        int b = srem / 24; int n = srem - b * 24;
        int f = b * 32 + t;
        out[(f * 24 + n) * 6 + c] = (n < nnum[f]) ? (s + sRob[c]) : 0.f;
    }
}

// ------------ host launcher ------------
extern "C" void kernel_launch(void* const* d_in, const int* in_sizes, int n_in,
                              void* d_out, int out_size)
{
    const float* node     = (const float*)d_in[0];
    const float* edge     = (const float*)d_in[1];
    const float* link_W1  = (const float*)d_in[2];
    const float* link_b1  = (const float*)d_in[3];
    const float* link_W2  = (const float*)d_in[4];
    const float* link_b2  = (const float*)d_in[5];
    const float* msg_Wh   = (const float*)d_in[6];
    const float* msg_We   = (const float*)d_in[7];
    const float* msg_b    = (const float*)d_in[8];
    const float* gru_Wih  = (const float*)d_in[9];
    const float* gru_Whh  = (const float*)d_in[10];
    const float* gru_bih  = (const float*)d_in[11];
    const float* gru_bhh  = (const float*)d_in[12];
    const float* lstm_Wih = (const float*)d_in[13];
    const float* lstm_Whh = (const float*)d_in[14];
    const float* lstm_bih = (const float*)d_in[15];
    const float* lstm_bhh = (const float*)d_in[16];
    const float* ro_W     = (const float*)d_in[17];
    const float* ro_b     = (const float*)d_in[18];
    const int*   nnum     = (const int*)d_in[19];
    float* out = (float*)d_out;

    float* hnC;   cudaGetSymbolAddress((void**)&hnC,   g_hnC);
    float* nhA;   cudaGetSymbolAddress((void**)&nhA,   g_nhA);
    float* nhB;   cudaGetSymbolAddress((void**)&nhB,   g_nhB);
    uint4* wA;    cudaGetSymbolAddress((void**)&wA,    g_wA4);
    float* gateA; cudaGetSymbolAddress((void**)&gateA, g_gateA);
    float* gateB; cudaGetSymbolAddress((void**)&gateB, g_gateB);

    static int inited = 0;
    static cudaStream_t s2;
    static cudaEvent_t eF[3], eJ[3];
    if (!inited) {
        cudaFuncSetAttribute(edge0_k, cudaFuncAttributeMaxDynamicSharedMemorySize, SM_EDGE);
        cudaFuncSetAttribute(recon_k, cudaFuncAttributeMaxDynamicSharedMemorySize, SM_EDGE);
        cudaFuncSetAttribute(hgemm_k, cudaFuncAttributeMaxDynamicSharedMemorySize, SM_HG);
        cudaFuncSetAttribute(gigh_k,  cudaFuncAttributeMaxDynamicSharedMemorySize, SM_HG);
        cudaFuncSetAttribute(xg_k,    cudaFuncAttributeMaxDynamicSharedMemorySize, SM_HG);
        cudaStreamCreateWithFlags(&s2, cudaStreamNonBlocking);
        for (int i = 0; i < 3; i++) {
            cudaEventCreateWithFlags(&eF[i], cudaEventDisableTiming);
            cudaEventCreateWithFlags(&eJ[i], cudaEventDisableTiming);
        }
        inited = 1;
    }

    const int NTILE = 256 * 6;
    const int NCT   = NCOLS / 96;   // 64

    // preamble: compact_edge on s2 overlaps prefix/tr_node/prep/nh0 on main
    cudaEventRecord(eF[2], 0);
    cudaStreamWaitEvent(s2, eF[2], 0);
    compact_edge_k<<<2048, 256, 0, s2>>>(edge, nnum);
    cudaEventRecord(eJ[2], s2);

    prefix_k<<<1, 256>>>(nnum);
    tr_node_k<<<(128 * NCOLS / 4) / 256, 256>>>(node);
    prep_all_k<<<312, 256>>>(link_W1, msg_We, msg_Wh, gru_Wih, gru_Whh, lstm_Wih, wA);
    hgemm_k<<<dim3(NCT, 1), 256, SM_HG>>>(wA + 12288, hnC, nullptr, nullptr, nhA, NCOLS, 1);
    cudaStreamWaitEvent(0, eJ[2], 0);
    edge0_k<<<NTILE, 256, SM_EDGE>>>(link_b1, link_W2, link_b2, msg_b, nnum, gateA);

    float* gbuf[2]  = {gateA, gateB};
    float* nhbuf[2] = {nhA, nhB};
    for (int p = 0; p < 3; p++) {
        float* gin  = gbuf[p & 1];
        float* gout = gbuf[(p + 1) & 1];
        float* nhp  = nhbuf[p & 1];
        float* nhn  = nhbuf[(p + 1) & 1];
        if (p > 0) cudaStreamWaitEvent(0, eJ[p - 1], 0);
        if (p < 2) {
            cudaEventRecord(eF[p], 0);
            cudaStreamWaitEvent(s2, eF[p], 0);
            recon_k<<<NTILE, 256, SM_EDGE, s2>>>(link_b1, link_W2, link_b2, nnum,
                                                 gin, gout, nhp);
            cudaEventRecord(eJ[p], s2);
        }
        mv_k<<<1024, 256>>>(nnum, gin, nhp);
        gigh_k<<<dim3(NCT, 6), 256, SM_HG>>>(wA);
        gru_k<<<(128 * NCOLS) / 256, 256>>>(gru_bih, gru_bhh);
        if (p < 2)
            hgemm_k<<<dim3(NCT, 1), 256, SM_HG>>>(wA + 12288, hnC, nullptr, nullptr,
                                                  nhn, NCOLS, 1);
    }

    xg_k<<<dim3(NCT, 4), 256, SM_HG>>>(wA + 55296, lstm_bih, lstm_bhh);
    lstm_all_k<<<128, 192>>>(lstm_Whh);
    readout_k<<<96, 256>>>(ro_W, ro_b, nnum, out);
    (void)in_sizes; (void)n_in; (void)out_size;
}